// round 2
// baseline (speedup 1.0000x reference)
#include <cuda_runtime.h>
#include <math.h>

#define DIM   1024
#define NH    16
#define HD    64
#define B_    2
#define S_    2048
#define MROWS (B_ * S_)   // 4096

// Scratch (allocation-free rule: __device__ globals)
__device__ float g_Q[B_ * NH * S_ * HD];   // [B,H,S,hd]
__device__ float g_K[B_ * NH * S_ * HD];
__device__ float g_V[B_ * NH * S_ * HD];
__device__ float g_C[MROWS * DIM];         // attention context, [B*S, H*hd]

// ---------------------------------------------------------------------------
// SGEMM: C[M,N] = A[M,K] @ W[K,N] + bias
// mode 0: C row-major [M,N]
// mode 1: scatter to [B,H,S,hd] layout (for Q/K/V)
// BM=BN=128, BK=8, 256 threads, 8x8 micro-tile.
// ---------------------------------------------------------------------------
__global__ __launch_bounds__(256) void sgemm_kernel(
    const float* __restrict__ A, const float* __restrict__ W,
    const float* __restrict__ bias, float* __restrict__ C,
    int M, int N, int K, int mode)
{
    __shared__ float As[8][128];
    __shared__ float Bs[8][128];

    const int tid = threadIdx.x;
    const int bm = blockIdx.y * 128;
    const int bn = blockIdx.x * 128;
    const int tx = tid & 15;
    const int ty = tid >> 4;

    float acc[8][8];
#pragma unroll
    for (int i = 0; i < 8; i++)
#pragma unroll
        for (int j = 0; j < 8; j++) acc[i][j] = 0.0f;

    // A tile: 128 rows x 8 cols -> 256 float4
    const int arow = tid >> 1;
    const int acol = (tid & 1) << 2;
    // B tile: 8 rows x 128 cols -> 256 float4
    const int brow = tid >> 5;
    const int bcol = (tid & 31) << 2;

    const float* Ap = A + (size_t)(bm + arow) * K + acol;
    const float* Bp = W + (size_t)brow * N + bn + bcol;

    for (int k0 = 0; k0 < K; k0 += 8) {
        float4 av = *(const float4*)(Ap + k0);
        float4 bv = *(const float4*)(Bp + (size_t)k0 * N);
        __syncthreads();
        As[acol + 0][arow] = av.x;
        As[acol + 1][arow] = av.y;
        As[acol + 2][arow] = av.z;
        As[acol + 3][arow] = av.w;
        *(float4*)&Bs[brow][bcol] = bv;
        __syncthreads();

#pragma unroll
        for (int kk = 0; kk < 8; kk++) {
            float ra[8], rb[8];
            *(float4*)&ra[0] = *(const float4*)&As[kk][ty * 8];
            *(float4*)&ra[4] = *(const float4*)&As[kk][ty * 8 + 4];
            *(float4*)&rb[0] = *(const float4*)&Bs[kk][tx * 8];
            *(float4*)&rb[4] = *(const float4*)&Bs[kk][tx * 8 + 4];
#pragma unroll
            for (int i = 0; i < 8; i++)
#pragma unroll
                for (int j = 0; j < 8; j++)
                    acc[i][j] += ra[i] * rb[j];
        }
    }

    if (mode == 0) {
#pragma unroll
        for (int i = 0; i < 8; i++) {
            const int m = bm + ty * 8 + i;
            const int n0 = bn + tx * 8;
            float4 v0, v1;
            v0.x = acc[i][0] + bias[n0 + 0];
            v0.y = acc[i][1] + bias[n0 + 1];
            v0.z = acc[i][2] + bias[n0 + 2];
            v0.w = acc[i][3] + bias[n0 + 3];
            v1.x = acc[i][4] + bias[n0 + 4];
            v1.y = acc[i][5] + bias[n0 + 5];
            v1.z = acc[i][6] + bias[n0 + 6];
            v1.w = acc[i][7] + bias[n0 + 7];
            *(float4*)&C[(size_t)m * N + n0]     = v0;
            *(float4*)&C[(size_t)m * N + n0 + 4] = v1;
        }
    } else {
        // scatter to [B, H, S, hd]
#pragma unroll
        for (int i = 0; i < 8; i++) {
            const int m = bm + ty * 8 + i;
            const int b = m >> 11;        // / S_
            const int s = m & (S_ - 1);
#pragma unroll
            for (int j = 0; j < 8; j++) {
                const int n = bn + tx * 8 + j;
                const int h = n >> 6;
                const int d = n & 63;
                C[(((size_t)(b * NH + h)) * S_ + s) * HD + d] = acc[i][j] + bias[n];
            }
        }
    }
}

// ---------------------------------------------------------------------------
// RoPE (in-place on Q and K, [B,H,S,hd] layout).
// One warp per (b,h,s) row of 64 elements.
// out[i]    = x[2i]*cos - x[2i+1]*sin     (i < 32)
// out[i+32] = x[2i]*sin + x[2i+1]*cos
// ---------------------------------------------------------------------------
__global__ void rope_kernel(float* __restrict__ Q, float* __restrict__ K,
                            const float* __restrict__ theta)
{
    const int gid  = blockIdx.x * blockDim.x + threadIdx.x;
    const int warp = gid >> 5;
    const int lane = gid & 31;
    const int s = warp & (S_ - 1);

    const float th = theta[lane];
    float sn, cs;
    sincosf((float)s * th, &sn, &cs);

    float* q = Q + (size_t)warp * HD;
    float x1 = q[2 * lane], x2 = q[2 * lane + 1];
    __syncwarp();
    q[lane]      = x1 * cs - x2 * sn;
    q[lane + 32] = x1 * sn + x2 * cs;

    float* k = K + (size_t)warp * HD;
    float y1 = k[2 * lane], y2 = k[2 * lane + 1];
    __syncwarp();
    k[lane]      = y1 * cs - y2 * sn;
    k[lane + 32] = y1 * sn + y2 * cs;
}

// ---------------------------------------------------------------------------
// Causal flash attention.
// Grid: (S/128 q-tiles, B*H). 256 threads. BQ=128, BK=64.
// Thread (tx,ty) owns score rows ty*8..ty*8+7, cols tx*4..tx*4+3.
// ctx written as [B*S, H*hd] for the output projection GEMM.
// ---------------------------------------------------------------------------
#define FLASH_SMEM_FLOATS (128*64 + 64*65 + 64*64 + 128*65)

__global__ __launch_bounds__(256, 1) void flash_kernel(
    const float* __restrict__ Q, const float* __restrict__ K,
    const float* __restrict__ V, float* __restrict__ ctx)
{
    extern __shared__ float sm[];
    float* Qs = sm;                    // [128][64]
    float* Ks = Qs + 128 * 64;         // [64][65] padded
    float* Vs = Ks + 64 * 65;          // [64][64]
    float* Ps = Vs + 64 * 64;          // [128][65] padded

    const int qb = blockIdx.x;
    const int bh = blockIdx.y;
    const int tid = threadIdx.x;
    const int tx = tid & 15;
    const int ty = tid >> 4;

    const float* Qg = Q + ((size_t)bh * S_ + qb * 128) * HD;
    const float* Kg = K + (size_t)bh * S_ * HD;
    const float* Vg = V + (size_t)bh * S_ * HD;

    // load Q tile (8192 floats)
    for (int i = tid; i < 2048; i += 256)
        ((float4*)Qs)[i] = ((const float4*)Qg)[i];

    float m_i[8], l_i[8], o[8][4];
#pragma unroll
    for (int i = 0; i < 8; i++) {
        m_i[i] = -3.0e38f;
        l_i[i] = 0.0f;
#pragma unroll
        for (int j = 0; j < 4; j++) o[i][j] = 0.0f;
    }

    const int jmax = 2 * qb + 1;
    for (int j = 0; j <= jmax; j++) {
        __syncthreads();   // prior PV reads of Ks/Vs/Ps done
        // load K (padded) and V tiles: 1024 float4 each
        const float4* kg = (const float4*)(Kg + (size_t)j * 64 * HD);
        const float4* vg = (const float4*)(Vg + (size_t)j * 64 * HD);
        for (int i = tid; i < 1024; i += 256) {
            const int row = i >> 4, c4 = (i & 15) << 2;
            float4 kv = kg[i];
            Ks[row * 65 + c4 + 0] = kv.x;
            Ks[row * 65 + c4 + 1] = kv.y;
            Ks[row * 65 + c4 + 2] = kv.z;
            Ks[row * 65 + c4 + 3] = kv.w;
            ((float4*)Vs)[i] = vg[i];
        }
        __syncthreads();

        // scores = Q K^T
        float sacc[8][4];
#pragma unroll
        for (int i = 0; i < 8; i++)
#pragma unroll
            for (int jj = 0; jj < 4; jj++) sacc[i][jj] = 0.0f;

#pragma unroll 4
        for (int d = 0; d < 64; d++) {
            float kvv[4];
#pragma unroll
            for (int jj = 0; jj < 4; jj++) kvv[jj] = Ks[(tx * 4 + jj) * 65 + d];
#pragma unroll
            for (int ii = 0; ii < 8; ii++) {
                const float qv = Qs[(ty * 8 + ii) * 64 + d];
#pragma unroll
                for (int jj = 0; jj < 4; jj++) sacc[ii][jj] += qv * kvv[jj];
            }
        }

        const bool diag = (j >= 2 * qb);
#pragma unroll
        for (int ii = 0; ii < 8; ii++) {
            const int qglob = qb * 128 + ty * 8 + ii;
            float rmax = -3.0e38f;
#pragma unroll
            for (int jj = 0; jj < 4; jj++) {
                float sv = sacc[ii][jj] * 0.125f;  // 1/sqrt(64)
                if (diag && (j * 64 + tx * 4 + jj > qglob)) sv = -3.0e38f;
                sacc[ii][jj] = sv;
                rmax = fmaxf(rmax, sv);
            }
#pragma unroll
            for (int off = 1; off < 16; off <<= 1)
                rmax = fmaxf(rmax, __shfl_xor_sync(0xffffffffu, rmax, off));

            const float mn = fmaxf(m_i[ii], rmax);
            const float al = __expf(m_i[ii] - mn);
            float rsum = 0.0f;
#pragma unroll
            for (int jj = 0; jj < 4; jj++) {
                const float p = __expf(sacc[ii][jj] - mn);
                Ps[(ty * 8 + ii) * 65 + tx * 4 + jj] = p;
                rsum += p;
            }
#pragma unroll
            for (int off = 1; off < 16; off <<= 1)
                rsum += __shfl_xor_sync(0xffffffffu, rsum, off);

            l_i[ii] = l_i[ii] * al + rsum;
            m_i[ii] = mn;
#pragma unroll
            for (int jj = 0; jj < 4; jj++) o[ii][jj] *= al;
        }
        __syncthreads();   // Ps visible to all

        // O += P @ V
#pragma unroll 2
        for (int k = 0; k < 64; k++) {
            float vv[4];
#pragma unroll
            for (int jj = 0; jj < 4; jj++) vv[jj] = Vs[k * 64 + tx * 4 + jj];
#pragma unroll
            for (int ii = 0; ii < 8; ii++) {
                const float p = Ps[(ty * 8 + ii) * 65 + k];
#pragma unroll
                for (int jj = 0; jj < 4; jj++) o[ii][jj] += p * vv[jj];
            }
        }
    }

    // write ctx [B*S, H*hd]
    const int b = bh >> 4, h = bh & 15;
#pragma unroll
    for (int ii = 0; ii < 8; ii++) {
        const int row = qb * 128 + ty * 8 + ii;
        const float inv = 1.0f / l_i[ii];
        float4 ov = make_float4(o[ii][0] * inv, o[ii][1] * inv,
                                o[ii][2] * inv, o[ii][3] * inv);
        *(float4*)&ctx[((size_t)(b * S_ + row)) * DIM + h * 64 + tx * 4] = ov;
    }
}

// ---------------------------------------------------------------------------
extern "C" void kernel_launch(void* const* d_in, const int* in_sizes, int n_in,
                              void* d_out, int out_size)
{
    const float* x     = (const float*)d_in[0];
    // d_in[1] = positions (== arange(S), unused: RoPE uses s directly)
    const float* theta = (const float*)d_in[2];
    const float* Wq    = (const float*)d_in[3];
    const float* bq    = (const float*)d_in[4];
    const float* Wk    = (const float*)d_in[5];
    const float* bk    = (const float*)d_in[6];
    const float* Wv    = (const float*)d_in[7];
    const float* bv    = (const float*)d_in[8];
    const float* Wo    = (const float*)d_in[9];
    const float* bo    = (const float*)d_in[10];
    float* out = (float*)d_out;

    float *Qb, *Kb, *Vb, *Cb;
    cudaGetSymbolAddress((void**)&Qb, g_Q);
    cudaGetSymbolAddress((void**)&Kb, g_K);
    cudaGetSymbolAddress((void**)&Vb, g_V);
    cudaGetSymbolAddress((void**)&Cb, g_C);

    const dim3 gemmGrid(DIM / 128, MROWS / 128);

    sgemm_kernel<<<gemmGrid, 256>>>(x, Wq, bq, Qb, MROWS, DIM, DIM, 1);
    sgemm_kernel<<<gemmGrid, 256>>>(x, Wk, bk, Kb, MROWS, DIM, DIM, 1);
    sgemm_kernel<<<gemmGrid, 256>>>(x, Wv, bv, Vb, MROWS, DIM, DIM, 1);

    rope_kernel<<<(B_ * NH * S_ * 32) / 256, 256>>>(Qb, Kb, theta);

    const int flashSmem = FLASH_SMEM_FLOATS * (int)sizeof(float);  // ~99 KB
    cudaFuncSetAttribute(flash_kernel,
                         cudaFuncAttributeMaxDynamicSharedMemorySize, flashSmem);
    flash_kernel<<<dim3(S_ / 128, B_ * NH), 256, flashSmem>>>(Qb, Kb, Vb, Cb);

    sgemm_kernel<<<gemmGrid, 256>>>(Cb, Wo, bo, out, MROWS, DIM, DIM, 0);
}

// round 4
// speedup vs baseline: 1.5291x; 1.5291x over previous
#include <cuda_runtime.h>
#include <math.h>
#include <stdint.h>

#define DIM   1024
#define NH    16
#define HD    64
#define B_    2
#define S_    2048
#define MROWS (B_ * S_)   // 4096

// Scratch (allocation-free rule: __device__ globals)
__device__ float g_Q[B_ * NH * S_ * HD];   // [B,H,S,hd]
__device__ float g_K[B_ * NH * S_ * HD];
__device__ float g_V[B_ * NH * S_ * HD];
__device__ float g_C[MROWS * DIM];         // attention context, [B*S, H*hd]

// ---------------------------------------------------------------------------
// TF32 helpers
// ---------------------------------------------------------------------------
__device__ __forceinline__ uint32_t f2tf(float f) {
    uint32_t r;
    asm("cvt.rna.tf32.f32 %0, %1;" : "=r"(r) : "f"(f));
    return r;
}

__device__ __forceinline__ void mma_tf32(float* d, const uint32_t* a, const uint32_t* b) {
    asm volatile(
        "mma.sync.aligned.m16n8k8.row.col.f32.tf32.tf32.f32 "
        "{%0,%1,%2,%3}, {%4,%5,%6,%7}, {%8,%9}, {%0,%1,%2,%3};"
        : "+f"(d[0]), "+f"(d[1]), "+f"(d[2]), "+f"(d[3])
        : "r"(a[0]), "r"(a[1]), "r"(a[2]), "r"(a[3]),
          "r"(b[0]), "r"(b[1]));
}

// ---------------------------------------------------------------------------
// TF32 tensor-core GEMM: C[M,N] = A[M,K] @ W[K,N] + bias
// mode 0: C row-major [M,N];  mode 1: scatter to [B,H,S,hd]
// Block 128x128x16, 8 warps (2x4), warp tile 64x32, m16n8k8 MMA.
// Double-buffered smem + register prefetch. LDA=20/LDB=136 pads are
// bank-conflict-free for the fragment LDS patterns (verified mod 32).
// ---------------------------------------------------------------------------
#define LDA 20
#define LDB 136

__global__ __launch_bounds__(256) void tf32_gemm_kernel(
    const float* __restrict__ A, const float* __restrict__ W,
    const float* __restrict__ bias, float* __restrict__ C,
    int M, int N, int K, int mode)
{
    __shared__ uint32_t As[2][128 * LDA];   // [row][k] tf32
    __shared__ uint32_t Bs[2][16 * LDB];    // [k][n]   tf32

    const int tid  = threadIdx.x;
    const int lane = tid & 31;
    const int warp = tid >> 5;
    const int bm = blockIdx.y * 128;
    const int bn = blockIdx.x * 128;
    const int wm = (warp & 1) << 6;    // 0 / 64
    const int wn = (warp >> 1) << 5;   // 0 / 32 / 64 / 96

    // Global-load assignments (two float4 per array per thread)
    const int ar0 = tid >> 2;                 // rows 0..63
    const int ar1 = (tid + 256) >> 2;         // rows 64..127
    const int akc = (tid & 3) << 2;           // k offset 0/4/8/12
    const int bk0 = tid >> 5;                 // k rows 0..7
    const int bk1 = (tid + 256) >> 5;         // k rows 8..15
    const int bnc = (tid & 31) << 2;          // n offset 0..124

    const float* Ap0 = A + (size_t)(bm + ar0) * K + akc;
    const float* Ap1 = A + (size_t)(bm + ar1) * K + akc;
    const float* Bp0 = W + (size_t)bk0 * N + bn + bnc;
    const float* Bp1 = W + (size_t)bk1 * N + bn + bnc;

    float acc[16][4];
#pragma unroll
    for (int i = 0; i < 16; i++)
#pragma unroll
        for (int j = 0; j < 4; j++) acc[i][j] = 0.0f;

    // ---- prologue: load tile 0 and stage into buffer 0
    float4 a0 = *(const float4*)Ap0;
    float4 a1 = *(const float4*)Ap1;
    float4 b0 = *(const float4*)Bp0;
    float4 b1 = *(const float4*)Bp1;
    {
        uint4 v;
        v.x = f2tf(a0.x); v.y = f2tf(a0.y); v.z = f2tf(a0.z); v.w = f2tf(a0.w);
        *(uint4*)&As[0][ar0 * LDA + akc] = v;
        v.x = f2tf(a1.x); v.y = f2tf(a1.y); v.z = f2tf(a1.z); v.w = f2tf(a1.w);
        *(uint4*)&As[0][ar1 * LDA + akc] = v;
        v.x = f2tf(b0.x); v.y = f2tf(b0.y); v.z = f2tf(b0.z); v.w = f2tf(b0.w);
        *(uint4*)&Bs[0][bk0 * LDB + bnc] = v;
        v.x = f2tf(b1.x); v.y = f2tf(b1.y); v.z = f2tf(b1.z); v.w = f2tf(b1.w);
        *(uint4*)&Bs[0][bk1 * LDB + bnc] = v;
    }
    __syncthreads();

    const int NT = K / 16;
#pragma unroll 1
    for (int kt = 0; kt < NT; kt++) {
        const int cur = kt & 1;
        const bool more = (kt + 1) < NT;
        if (more) {
            a0 = *(const float4*)(Ap0 + (kt + 1) * 16);
            a1 = *(const float4*)(Ap1 + (kt + 1) * 16);
            b0 = *(const float4*)(Bp0 + (size_t)(kt + 1) * 16 * N);
            b1 = *(const float4*)(Bp1 + (size_t)(kt + 1) * 16 * N);
        }

#pragma unroll
        for (int ks = 0; ks < 2; ks++) {
            uint32_t af[4][4], bf[4][2];
#pragma unroll
            for (int mi = 0; mi < 4; mi++) {
                const int r = wm + mi * 16 + (lane >> 2);
                const int c = ks * 8 + (lane & 3);
                af[mi][0] = As[cur][r * LDA + c];
                af[mi][1] = As[cur][(r + 8) * LDA + c];
                af[mi][2] = As[cur][r * LDA + c + 4];
                af[mi][3] = As[cur][(r + 8) * LDA + c + 4];
            }
#pragma unroll
            for (int ni = 0; ni < 4; ni++) {
                const int n = wn + ni * 8 + (lane >> 2);
                const int k = ks * 8 + (lane & 3);
                bf[ni][0] = Bs[cur][k * LDB + n];
                bf[ni][1] = Bs[cur][(k + 4) * LDB + n];
            }
#pragma unroll
            for (int mi = 0; mi < 4; mi++)
#pragma unroll
                for (int ni = 0; ni < 4; ni++)
                    mma_tf32(acc[mi * 4 + ni], af[mi], bf[ni]);
        }

        if (more) {
            const int nx = (kt + 1) & 1;
            uint4 v;
            v.x = f2tf(a0.x); v.y = f2tf(a0.y); v.z = f2tf(a0.z); v.w = f2tf(a0.w);
            *(uint4*)&As[nx][ar0 * LDA + akc] = v;
            v.x = f2tf(a1.x); v.y = f2tf(a1.y); v.z = f2tf(a1.z); v.w = f2tf(a1.w);
            *(uint4*)&As[nx][ar1 * LDA + akc] = v;
            v.x = f2tf(b0.x); v.y = f2tf(b0.y); v.z = f2tf(b0.z); v.w = f2tf(b0.w);
            *(uint4*)&Bs[nx][bk0 * LDB + bnc] = v;
            v.x = f2tf(b1.x); v.y = f2tf(b1.y); v.z = f2tf(b1.z); v.w = f2tf(b1.w);
            *(uint4*)&Bs[nx][bk1 * LDB + bnc] = v;
        }
        __syncthreads();
    }

    // ---- epilogue
#pragma unroll
    for (int mi = 0; mi < 4; mi++) {
        const int r0 = bm + wm + mi * 16 + (lane >> 2);
        const int r1 = r0 + 8;
#pragma unroll
        for (int ni = 0; ni < 4; ni++) {
            const int c0 = bn + wn + ni * 8 + ((lane & 3) << 1);
            const float* a = acc[mi * 4 + ni];
            const float bi0 = bias[c0], bi1 = bias[c0 + 1];
            if (mode == 0) {
                *(float2*)&C[(size_t)r0 * N + c0] = make_float2(a[0] + bi0, a[1] + bi1);
                *(float2*)&C[(size_t)r1 * N + c0] = make_float2(a[2] + bi0, a[3] + bi1);
            } else {
                const int h = c0 >> 6, d = c0 & 63;
                const int b0r = r0 >> 11, s0 = r0 & (S_ - 1);
                const int b1r = r1 >> 11, s1 = r1 & (S_ - 1);
                *(float2*)&C[(((size_t)(b0r * NH + h)) * S_ + s0) * HD + d] =
                    make_float2(a[0] + bi0, a[1] + bi1);
                *(float2*)&C[(((size_t)(b1r * NH + h)) * S_ + s1) * HD + d] =
                    make_float2(a[2] + bi0, a[3] + bi1);
            }
        }
    }
}

// ---------------------------------------------------------------------------
// RoPE (in-place on Q and K, [B,H,S,hd] layout). One warp per (b,h,s) row.
// ---------------------------------------------------------------------------
__global__ void rope_kernel(float* __restrict__ Q, float* __restrict__ K,
                            const float* __restrict__ theta)
{
    const int gid  = blockIdx.x * blockDim.x + threadIdx.x;
    const int warp = gid >> 5;
    const int lane = gid & 31;
    const int s = warp & (S_ - 1);

    const float th = theta[lane];
    float sn, cs;
    sincosf((float)s * th, &sn, &cs);

    float* q = Q + (size_t)warp * HD;
    float x1 = q[2 * lane], x2 = q[2 * lane + 1];
    __syncwarp();
    q[lane]      = x1 * cs - x2 * sn;
    q[lane + 32] = x1 * sn + x2 * cs;

    float* k = K + (size_t)warp * HD;
    float y1 = k[2 * lane], y2 = k[2 * lane + 1];
    __syncwarp();
    k[lane]      = y1 * cs - y2 * sn;
    k[lane + 32] = y1 * sn + y2 * cs;
}

// ---------------------------------------------------------------------------
// Causal flash attention (fp32). Grid: (S/128, B*H). 256 threads.
// BQ=128, BK=64. ctx written as [B*S, H*hd].
// ---------------------------------------------------------------------------
#define FLASH_SMEM_FLOATS (128*64 + 64*65 + 64*64 + 128*65)

__global__ __launch_bounds__(256, 1) void flash_kernel(
    const float* __restrict__ Q, const float* __restrict__ K,
    const float* __restrict__ V, float* __restrict__ ctx)
{
    extern __shared__ float sm[];
    float* Qs = sm;                    // [128][64]
    float* Ks = Qs + 128 * 64;         // [64][65] padded
    float* Vs = Ks + 64 * 65;          // [64][64]
    float* Ps = Vs + 64 * 64;          // [128][65] padded

    const int qb = blockIdx.x;
    const int bh = blockIdx.y;
    const int tid = threadIdx.x;
    const int tx = tid & 15;
    const int ty = tid >> 4;

    const float* Qg = Q + ((size_t)bh * S_ + qb * 128) * HD;
    const float* Kg = K + (size_t)bh * S_ * HD;
    const float* Vg = V + (size_t)bh * S_ * HD;

    for (int i = tid; i < 2048; i += 256)
        ((float4*)Qs)[i] = ((const float4*)Qg)[i];

    float m_i[8], l_i[8], o[8][4];
#pragma unroll
    for (int i = 0; i < 8; i++) {
        m_i[i] = -3.0e38f;
        l_i[i] = 0.0f;
#pragma unroll
        for (int j = 0; j < 4; j++) o[i][j] = 0.0f;
    }

    const int jmax = 2 * qb + 1;
    for (int j = 0; j <= jmax; j++) {
        __syncthreads();
        const float4* kg = (const float4*)(Kg + (size_t)j * 64 * HD);
        const float4* vg = (const float4*)(Vg + (size_t)j * 64 * HD);
        for (int i = tid; i < 1024; i += 256) {
            const int row = i >> 4, c4 = (i & 15) << 2;
            float4 kv = kg[i];
            Ks[row * 65 + c4 + 0] = kv.x;
            Ks[row * 65 + c4 + 1] = kv.y;
            Ks[row * 65 + c4 + 2] = kv.z;
            Ks[row * 65 + c4 + 3] = kv.w;
            ((float4*)Vs)[i] = vg[i];
        }
        __syncthreads();

        float sacc[8][4];
#pragma unroll
        for (int i = 0; i < 8; i++)
#pragma unroll
            for (int jj = 0; jj < 4; jj++) sacc[i][jj] = 0.0f;

#pragma unroll 4
        for (int d = 0; d < 64; d++) {
            float kvv[4];
#pragma unroll
            for (int jj = 0; jj < 4; jj++) kvv[jj] = Ks[(tx * 4 + jj) * 65 + d];
#pragma unroll
            for (int ii = 0; ii < 8; ii++) {
                const float qv = Qs[(ty * 8 + ii) * 64 + d];
#pragma unroll
                for (int jj = 0; jj < 4; jj++) sacc[ii][jj] += qv * kvv[jj];
            }
        }

        const bool diag = (j >= 2 * qb);
#pragma unroll
        for (int ii = 0; ii < 8; ii++) {
            const int qglob = qb * 128 + ty * 8 + ii;
            float rmax = -3.0e38f;
#pragma unroll
            for (int jj = 0; jj < 4; jj++) {
                float sv = sacc[ii][jj] * 0.125f;
                if (diag && (j * 64 + tx * 4 + jj > qglob)) sv = -3.0e38f;
                sacc[ii][jj] = sv;
                rmax = fmaxf(rmax, sv);
            }
#pragma unroll
            for (int off = 1; off < 16; off <<= 1)
                rmax = fmaxf(rmax, __shfl_xor_sync(0xffffffffu, rmax, off));

            const float mn = fmaxf(m_i[ii], rmax);
            const float al = __expf(m_i[ii] - mn);
            float rsum = 0.0f;
#pragma unroll
            for (int jj = 0; jj < 4; jj++) {
                const float p = __expf(sacc[ii][jj] - mn);
                Ps[(ty * 8 + ii) * 65 + tx * 4 + jj] = p;
                rsum += p;
            }
#pragma unroll
            for (int off = 1; off < 16; off <<= 1)
                rsum += __shfl_xor_sync(0xffffffffu, rsum, off);

            l_i[ii] = l_i[ii] * al + rsum;
            m_i[ii] = mn;
#pragma unroll
            for (int jj = 0; jj < 4; jj++) o[ii][jj] *= al;
        }
        __syncthreads();

#pragma unroll 2
        for (int k = 0; k < 64; k++) {
            float vv[4];
#pragma unroll
            for (int jj = 0; jj < 4; jj++) vv[jj] = Vs[k * 64 + tx * 4 + jj];
#pragma unroll
            for (int ii = 0; ii < 8; ii++) {
                const float p = Ps[(ty * 8 + ii) * 65 + k];
#pragma unroll
                for (int jj = 0; jj < 4; jj++) o[ii][jj] += p * vv[jj];
            }
        }
    }

    const int b = bh >> 4, h = bh & 15;
#pragma unroll
    for (int ii = 0; ii < 8; ii++) {
        const int row = qb * 128 + ty * 8 + ii;
        const float inv = 1.0f / l_i[ii];
        float4 ov = make_float4(o[ii][0] * inv, o[ii][1] * inv,
                                o[ii][2] * inv, o[ii][3] * inv);
        *(float4*)&ctx[((size_t)(b * S_ + row)) * DIM + h * 64 + tx * 4] = ov;
    }
}

// ---------------------------------------------------------------------------
extern "C" void kernel_launch(void* const* d_in, const int* in_sizes, int n_in,
                              void* d_out, int out_size)
{
    const float* x     = (const float*)d_in[0];
    const float* theta = (const float*)d_in[2];
    const float* Wq    = (const float*)d_in[3];
    const float* bq    = (const float*)d_in[4];
    const float* Wk    = (const float*)d_in[5];
    const float* bk    = (const float*)d_in[6];
    const float* Wv    = (const float*)d_in[7];
    const float* bv    = (const float*)d_in[8];
    const float* Wo    = (const float*)d_in[9];
    const float* bo    = (const float*)d_in[10];
    float* out = (float*)d_out;

    float *Qb, *Kb, *Vb, *Cb;
    cudaGetSymbolAddress((void**)&Qb, g_Q);
    cudaGetSymbolAddress((void**)&Kb, g_K);
    cudaGetSymbolAddress((void**)&Vb, g_V);
    cudaGetSymbolAddress((void**)&Cb, g_C);

    const dim3 gemmGrid(DIM / 128, MROWS / 128);

    tf32_gemm_kernel<<<gemmGrid, 256>>>(x, Wq, bq, Qb, MROWS, DIM, DIM, 1);
    tf32_gemm_kernel<<<gemmGrid, 256>>>(x, Wk, bk, Kb, MROWS, DIM, DIM, 1);
    tf32_gemm_kernel<<<gemmGrid, 256>>>(x, Wv, bv, Vb, MROWS, DIM, DIM, 1);

    rope_kernel<<<(B_ * NH * S_ * 32) / 256, 256>>>(Qb, Kb, theta);

    const int flashSmem = FLASH_SMEM_FLOATS * (int)sizeof(float);  // ~99 KB
    cudaFuncSetAttribute(flash_kernel,
                         cudaFuncAttributeMaxDynamicSharedMemorySize, flashSmem);
    flash_kernel<<<dim3(S_ / 128, B_ * NH), 256, flashSmem>>>(Qb, Kb, Vb, Cb);

    tf32_gemm_kernel<<<gemmGrid, 256>>>(Cb, Wo, bo, out, MROWS, DIM, DIM, 0);
}

// round 5
// speedup vs baseline: 1.5319x; 1.0018x over previous
#include <cuda_runtime.h>
#include <math.h>
#include <stdint.h>

#define DIM   1024
#define NH    16
#define HD    64
#define B_    2
#define S_    2048
#define MROWS (B_ * S_)   // 4096

// Scratch (allocation-free rule: __device__ globals)
__device__ float g_Q[B_ * NH * S_ * HD];   // [B,H,S,hd]
__device__ float g_K[B_ * NH * S_ * HD];
__device__ float g_V[B_ * NH * S_ * HD];
__device__ float g_C[MROWS * DIM];         // attention context, [B*S, H*hd]

// ---------------------------------------------------------------------------
// TF32 helpers
// ---------------------------------------------------------------------------
__device__ __forceinline__ uint32_t f2tf(float f) {
    uint32_t r;
    asm("cvt.rna.tf32.f32 %0, %1;" : "=r"(r) : "f"(f));
    return r;
}

__device__ __forceinline__ void mma_tf32(float* d, const uint32_t* a, const uint32_t* b) {
    asm volatile(
        "mma.sync.aligned.m16n8k8.row.col.f32.tf32.tf32.f32 "
        "{%0,%1,%2,%3}, {%4,%5,%6,%7}, {%8,%9}, {%0,%1,%2,%3};"
        : "+f"(d[0]), "+f"(d[1]), "+f"(d[2]), "+f"(d[3])
        : "r"(a[0]), "r"(a[1]), "r"(a[2]), "r"(a[3]),
          "r"(b[0]), "r"(b[1]));
}

// ---------------------------------------------------------------------------
// TF32 tensor-core GEMM: C[M,N] = A[M,K] @ W[K,N] + bias
// mode 0: C row-major [M,N];  mode 1: scatter to [B,H,S,hd]
// Block 128x128x16, 8 warps (2x4), warp tile 64x32, m16n8k8 MMA.
// Double-buffered smem + register prefetch. LDA=20/LDB=136 pads are
// bank-conflict-free for the fragment LDS patterns (verified mod 32).
// ---------------------------------------------------------------------------
#define LDA 20
#define LDB 136

__global__ __launch_bounds__(256) void tf32_gemm_kernel(
    const float* __restrict__ A, const float* __restrict__ W,
    const float* __restrict__ bias, float* __restrict__ C,
    int M, int N, int K, int mode)
{
    __shared__ uint32_t As[2][128 * LDA];   // [row][k] tf32
    __shared__ uint32_t Bs[2][16 * LDB];    // [k][n]   tf32

    const int tid  = threadIdx.x;
    const int lane = tid & 31;
    const int warp = tid >> 5;
    const int bm = blockIdx.y * 128;
    const int bn = blockIdx.x * 128;
    const int wm = (warp & 1) << 6;    // 0 / 64
    const int wn = (warp >> 1) << 5;   // 0 / 32 / 64 / 96

    // Global-load assignments (two float4 per array per thread)
    const int ar0 = tid >> 2;                 // rows 0..63
    const int ar1 = (tid + 256) >> 2;         // rows 64..127
    const int akc = (tid & 3) << 2;           // k offset 0/4/8/12
    const int bk0 = tid >> 5;                 // k rows 0..7
    const int bk1 = (tid + 256) >> 5;         // k rows 8..15
    const int bnc = (tid & 31) << 2;          // n offset 0..124

    const float* Ap0 = A + (size_t)(bm + ar0) * K + akc;
    const float* Ap1 = A + (size_t)(bm + ar1) * K + akc;
    const float* Bp0 = W + (size_t)bk0 * N + bn + bnc;
    const float* Bp1 = W + (size_t)bk1 * N + bn + bnc;

    float acc[16][4];
#pragma unroll
    for (int i = 0; i < 16; i++)
#pragma unroll
        for (int j = 0; j < 4; j++) acc[i][j] = 0.0f;

    // ---- prologue: load tile 0 and stage into buffer 0
    float4 a0 = *(const float4*)Ap0;
    float4 a1 = *(const float4*)Ap1;
    float4 b0 = *(const float4*)Bp0;
    float4 b1 = *(const float4*)Bp1;
    {
        uint4 v;
        v.x = f2tf(a0.x); v.y = f2tf(a0.y); v.z = f2tf(a0.z); v.w = f2tf(a0.w);
        *(uint4*)&As[0][ar0 * LDA + akc] = v;
        v.x = f2tf(a1.x); v.y = f2tf(a1.y); v.z = f2tf(a1.z); v.w = f2tf(a1.w);
        *(uint4*)&As[0][ar1 * LDA + akc] = v;
        v.x = f2tf(b0.x); v.y = f2tf(b0.y); v.z = f2tf(b0.z); v.w = f2tf(b0.w);
        *(uint4*)&Bs[0][bk0 * LDB + bnc] = v;
        v.x = f2tf(b1.x); v.y = f2tf(b1.y); v.z = f2tf(b1.z); v.w = f2tf(b1.w);
        *(uint4*)&Bs[0][bk1 * LDB + bnc] = v;
    }
    __syncthreads();

    const int NT = K / 16;
#pragma unroll 1
    for (int kt = 0; kt < NT; kt++) {
        const int cur = kt & 1;
        const bool more = (kt + 1) < NT;
        if (more) {
            a0 = *(const float4*)(Ap0 + (kt + 1) * 16);
            a1 = *(const float4*)(Ap1 + (kt + 1) * 16);
            b0 = *(const float4*)(Bp0 + (size_t)(kt + 1) * 16 * N);
            b1 = *(const float4*)(Bp1 + (size_t)(kt + 1) * 16 * N);
        }

#pragma unroll
        for (int ks = 0; ks < 2; ks++) {
            uint32_t af[4][4], bf[4][2];
#pragma unroll
            for (int mi = 0; mi < 4; mi++) {
                const int r = wm + mi * 16 + (lane >> 2);
                const int c = ks * 8 + (lane & 3);
                af[mi][0] = As[cur][r * LDA + c];
                af[mi][1] = As[cur][(r + 8) * LDA + c];
                af[mi][2] = As[cur][r * LDA + c + 4];
                af[mi][3] = As[cur][(r + 8) * LDA + c + 4];
            }
#pragma unroll
            for (int ni = 0; ni < 4; ni++) {
                const int n = wn + ni * 8 + (lane >> 2);
                const int k = ks * 8 + (lane & 3);
                bf[ni][0] = Bs[cur][k * LDB + n];
                bf[ni][1] = Bs[cur][(k + 4) * LDB + n];
            }
#pragma unroll
            for (int mi = 0; mi < 4; mi++)
#pragma unroll
                for (int ni = 0; ni < 4; ni++)
                    mma_tf32(acc[mi * 4 + ni], af[mi], bf[ni]);
        }

        if (more) {
            const int nx = (kt + 1) & 1;
            uint4 v;
            v.x = f2tf(a0.x); v.y = f2tf(a0.y); v.z = f2tf(a0.z); v.w = f2tf(a0.w);
            *(uint4*)&As[nx][ar0 * LDA + akc] = v;
            v.x = f2tf(a1.x); v.y = f2tf(a1.y); v.z = f2tf(a1.z); v.w = f2tf(a1.w);
            *(uint4*)&As[nx][ar1 * LDA + akc] = v;
            v.x = f2tf(b0.x); v.y = f2tf(b0.y); v.z = f2tf(b0.z); v.w = f2tf(b0.w);
            *(uint4*)&Bs[nx][bk0 * LDB + bnc] = v;
            v.x = f2tf(b1.x); v.y = f2tf(b1.y); v.z = f2tf(b1.z); v.w = f2tf(b1.w);
            *(uint4*)&Bs[nx][bk1 * LDB + bnc] = v;
        }
        __syncthreads();
    }

    // ---- epilogue
#pragma unroll
    for (int mi = 0; mi < 4; mi++) {
        const int r0 = bm + wm + mi * 16 + (lane >> 2);
        const int r1 = r0 + 8;
#pragma unroll
        for (int ni = 0; ni < 4; ni++) {
            const int c0 = bn + wn + ni * 8 + ((lane & 3) << 1);
            const float* a = acc[mi * 4 + ni];
            const float bi0 = bias[c0], bi1 = bias[c0 + 1];
            if (mode == 0) {
                *(float2*)&C[(size_t)r0 * N + c0] = make_float2(a[0] + bi0, a[1] + bi1);
                *(float2*)&C[(size_t)r1 * N + c0] = make_float2(a[2] + bi0, a[3] + bi1);
            } else {
                const int h = c0 >> 6, d = c0 & 63;
                const int b0r = r0 >> 11, s0 = r0 & (S_ - 1);
                const int b1r = r1 >> 11, s1 = r1 & (S_ - 1);
                *(float2*)&C[(((size_t)(b0r * NH + h)) * S_ + s0) * HD + d] =
                    make_float2(a[0] + bi0, a[1] + bi1);
                *(float2*)&C[(((size_t)(b1r * NH + h)) * S_ + s1) * HD + d] =
                    make_float2(a[2] + bi0, a[3] + bi1);
            }
        }
    }
}

// ---------------------------------------------------------------------------
// RoPE (in-place on Q and K, [B,H,S,hd] layout). One warp per (b,h,s) row.
// ---------------------------------------------------------------------------
__global__ void rope_kernel(float* __restrict__ Q, float* __restrict__ K,
                            const float* __restrict__ theta)
{
    const int gid  = blockIdx.x * blockDim.x + threadIdx.x;
    const int warp = gid >> 5;
    const int lane = gid & 31;
    const int s = warp & (S_ - 1);

    const float th = theta[lane];
    float sn, cs;
    sincosf((float)s * th, &sn, &cs);

    float* q = Q + (size_t)warp * HD;
    float x1 = q[2 * lane], x2 = q[2 * lane + 1];
    __syncwarp();
    q[lane]      = x1 * cs - x2 * sn;
    q[lane + 32] = x1 * sn + x2 * cs;

    float* k = K + (size_t)warp * HD;
    float y1 = k[2 * lane], y2 = k[2 * lane + 1];
    __syncwarp();
    k[lane]      = y1 * cs - y2 * sn;
    k[lane + 32] = y1 * sn + y2 * cs;
}

// ---------------------------------------------------------------------------
// Causal flash attention (fp32). Grid: (S/128, B*H). 256 threads.
// BQ=128, BK=64. ctx written as [B*S, H*hd].
// ---------------------------------------------------------------------------
#define FLASH_SMEM_FLOATS (128*64 + 64*65 + 64*64 + 128*65)

__global__ __launch_bounds__(256, 1) void flash_kernel(
    const float* __restrict__ Q, const float* __restrict__ K,
    const float* __restrict__ V, float* __restrict__ ctx)
{
    extern __shared__ float sm[];
    float* Qs = sm;                    // [128][64]
    float* Ks = Qs + 128 * 64;         // [64][65] padded
    float* Vs = Ks + 64 * 65;          // [64][64]
    float* Ps = Vs + 64 * 64;          // [128][65] padded

    const int qb = blockIdx.x;
    const int bh = blockIdx.y;
    const int tid = threadIdx.x;
    const int tx = tid & 15;
    const int ty = tid >> 4;

    const float* Qg = Q + ((size_t)bh * S_ + qb * 128) * HD;
    const float* Kg = K + (size_t)bh * S_ * HD;
    const float* Vg = V + (size_t)bh * S_ * HD;

    for (int i = tid; i < 2048; i += 256)
        ((float4*)Qs)[i] = ((const float4*)Qg)[i];

    float m_i[8], l_i[8], o[8][4];
#pragma unroll
    for (int i = 0; i < 8; i++) {
        m_i[i] = -3.0e38f;
        l_i[i] = 0.0f;
#pragma unroll
        for (int j = 0; j < 4; j++) o[i][j] = 0.0f;
    }

    const int jmax = 2 * qb + 1;
    for (int j = 0; j <= jmax; j++) {
        __syncthreads();
        const float4* kg = (const float4*)(Kg + (size_t)j * 64 * HD);
        const float4* vg = (const float4*)(Vg + (size_t)j * 64 * HD);
        for (int i = tid; i < 1024; i += 256) {
            const int row = i >> 4, c4 = (i & 15) << 2;
            float4 kv = kg[i];
            Ks[row * 65 + c4 + 0] = kv.x;
            Ks[row * 65 + c4 + 1] = kv.y;
            Ks[row * 65 + c4 + 2] = kv.z;
            Ks[row * 65 + c4 + 3] = kv.w;
            ((float4*)Vs)[i] = vg[i];
        }
        __syncthreads();

        float sacc[8][4];
#pragma unroll
        for (int i = 0; i < 8; i++)
#pragma unroll
            for (int jj = 0; jj < 4; jj++) sacc[i][jj] = 0.0f;

#pragma unroll 4
        for (int d = 0; d < 64; d++) {
            float kvv[4];
#pragma unroll
            for (int jj = 0; jj < 4; jj++) kvv[jj] = Ks[(tx * 4 + jj) * 65 + d];
#pragma unroll
            for (int ii = 0; ii < 8; ii++) {
                const float qv = Qs[(ty * 8 + ii) * 64 + d];
#pragma unroll
                for (int jj = 0; jj < 4; jj++) sacc[ii][jj] += qv * kvv[jj];
            }
        }

        const bool diag = (j >= 2 * qb);
#pragma unroll
        for (int ii = 0; ii < 8; ii++) {
            const int qglob = qb * 128 + ty * 8 + ii;
            float rmax = -3.0e38f;
#pragma unroll
            for (int jj = 0; jj < 4; jj++) {
                float sv = sacc[ii][jj] * 0.125f;
                if (diag && (j * 64 + tx * 4 + jj > qglob)) sv = -3.0e38f;
                sacc[ii][jj] = sv;
                rmax = fmaxf(rmax, sv);
            }
#pragma unroll
            for (int off = 1; off < 16; off <<= 1)
                rmax = fmaxf(rmax, __shfl_xor_sync(0xffffffffu, rmax, off));

            const float mn = fmaxf(m_i[ii], rmax);
            const float al = __expf(m_i[ii] - mn);
            float rsum = 0.0f;
#pragma unroll
            for (int jj = 0; jj < 4; jj++) {
                const float p = __expf(sacc[ii][jj] - mn);
                Ps[(ty * 8 + ii) * 65 + tx * 4 + jj] = p;
                rsum += p;
            }
#pragma unroll
            for (int off = 1; off < 16; off <<= 1)
                rsum += __shfl_xor_sync(0xffffffffu, rsum, off);

            l_i[ii] = l_i[ii] * al + rsum;
            m_i[ii] = mn;
#pragma unroll
            for (int jj = 0; jj < 4; jj++) o[ii][jj] *= al;
        }
        __syncthreads();

#pragma unroll 2
        for (int k = 0; k < 64; k++) {
            float vv[4];
#pragma unroll
            for (int jj = 0; jj < 4; jj++) vv[jj] = Vs[k * 64 + tx * 4 + jj];
#pragma unroll
            for (int ii = 0; ii < 8; ii++) {
                const float p = Ps[(ty * 8 + ii) * 65 + k];
#pragma unroll
                for (int jj = 0; jj < 4; jj++) o[ii][jj] += p * vv[jj];
            }
        }
    }

    const int b = bh >> 4, h = bh & 15;
#pragma unroll
    for (int ii = 0; ii < 8; ii++) {
        const int row = qb * 128 + ty * 8 + ii;
        const float inv = 1.0f / l_i[ii];
        float4 ov = make_float4(o[ii][0] * inv, o[ii][1] * inv,
                                o[ii][2] * inv, o[ii][3] * inv);
        *(float4*)&ctx[((size_t)(b * S_ + row)) * DIM + h * 64 + tx * 4] = ov;
    }
}

// ---------------------------------------------------------------------------
extern "C" void kernel_launch(void* const* d_in, const int* in_sizes, int n_in,
                              void* d_out, int out_size)
{
    const float* x     = (const float*)d_in[0];
    const float* theta = (const float*)d_in[2];
    const float* Wq    = (const float*)d_in[3];
    const float* bq    = (const float*)d_in[4];
    const float* Wk    = (const float*)d_in[5];
    const float* bk    = (const float*)d_in[6];
    const float* Wv    = (const float*)d_in[7];
    const float* bv    = (const float*)d_in[8];
    const float* Wo    = (const float*)d_in[9];
    const float* bo    = (const float*)d_in[10];
    float* out = (float*)d_out;

    float *Qb, *Kb, *Vb, *Cb;
    cudaGetSymbolAddress((void**)&Qb, g_Q);
    cudaGetSymbolAddress((void**)&Kb, g_K);
    cudaGetSymbolAddress((void**)&Vb, g_V);
    cudaGetSymbolAddress((void**)&Cb, g_C);

    const dim3 gemmGrid(DIM / 128, MROWS / 128);

    tf32_gemm_kernel<<<gemmGrid, 256>>>(x, Wq, bq, Qb, MROWS, DIM, DIM, 1);
    tf32_gemm_kernel<<<gemmGrid, 256>>>(x, Wk, bk, Kb, MROWS, DIM, DIM, 1);
    tf32_gemm_kernel<<<gemmGrid, 256>>>(x, Wv, bv, Vb, MROWS, DIM, DIM, 1);

    rope_kernel<<<(B_ * NH * S_ * 32) / 256, 256>>>(Qb, Kb, theta);

    const int flashSmem = FLASH_SMEM_FLOATS * (int)sizeof(float);  // ~99 KB
    cudaFuncSetAttribute(flash_kernel,
                         cudaFuncAttributeMaxDynamicSharedMemorySize, flashSmem);
    flash_kernel<<<dim3(S_ / 128, B_ * NH), 256, flashSmem>>>(Qb, Kb, Vb, Cb);

    tf32_gemm_kernel<<<gemmGrid, 256>>>(Cb, Wo, bo, out, MROWS, DIM, DIM, 0);
}

// round 6
// speedup vs baseline: 2.5796x; 1.6839x over previous
#include <cuda_runtime.h>
#include <math.h>
#include <stdint.h>

#define DIM   1024
#define NH    16
#define HD    64
#define B_    2
#define S_    2048
#define MROWS (B_ * S_)   // 4096

// Scratch (allocation-free rule: __device__ globals)
__device__ float g_Q[B_ * NH * S_ * HD];   // [B,H,S,hd]
__device__ float g_K[B_ * NH * S_ * HD];
__device__ float g_V[B_ * NH * S_ * HD];
__device__ float g_C[MROWS * DIM];         // attention context, [B*S, H*hd]

// ---------------------------------------------------------------------------
// TF32 helpers
// ---------------------------------------------------------------------------
__device__ __forceinline__ uint32_t f2tf(float f) {
    uint32_t r;
    asm("cvt.rna.tf32.f32 %0, %1;" : "=r"(r) : "f"(f));
    return r;
}

__device__ __forceinline__ void mma_tf32(float* d, const uint32_t* a, const uint32_t* b) {
    asm volatile(
        "mma.sync.aligned.m16n8k8.row.col.f32.tf32.tf32.f32 "
        "{%0,%1,%2,%3}, {%4,%5,%6,%7}, {%8,%9}, {%0,%1,%2,%3};"
        : "+f"(d[0]), "+f"(d[1]), "+f"(d[2]), "+f"(d[3])
        : "r"(a[0]), "r"(a[1]), "r"(a[2]), "r"(a[3]),
          "r"(b[0]), "r"(b[1]));
}

// ---------------------------------------------------------------------------
// TF32 tensor-core GEMM: C[M,N] = A[M,K] @ W[K,N] + bias
// mode 0: C row-major [M,N];  mode 1: scatter to [B,H,S,hd]
// Block 128x128x16, 8 warps (2x4), warp tile 64x32, m16n8k8 MMA.
// ---------------------------------------------------------------------------
#define LDA 20
#define LDB 136

__global__ __launch_bounds__(256) void tf32_gemm_kernel(
    const float* __restrict__ A, const float* __restrict__ W,
    const float* __restrict__ bias, float* __restrict__ C,
    int M, int N, int K, int mode)
{
    __shared__ uint32_t As[2][128 * LDA];   // [row][k] tf32
    __shared__ uint32_t Bs[2][16 * LDB];    // [k][n]   tf32

    const int tid  = threadIdx.x;
    const int lane = tid & 31;
    const int warp = tid >> 5;
    const int bm = blockIdx.y * 128;
    const int bn = blockIdx.x * 128;
    const int wm = (warp & 1) << 6;
    const int wn = (warp >> 1) << 5;

    const int ar0 = tid >> 2;
    const int ar1 = (tid + 256) >> 2;
    const int akc = (tid & 3) << 2;
    const int bk0 = tid >> 5;
    const int bk1 = (tid + 256) >> 5;
    const int bnc = (tid & 31) << 2;

    const float* Ap0 = A + (size_t)(bm + ar0) * K + akc;
    const float* Ap1 = A + (size_t)(bm + ar1) * K + akc;
    const float* Bp0 = W + (size_t)bk0 * N + bn + bnc;
    const float* Bp1 = W + (size_t)bk1 * N + bn + bnc;

    float acc[16][4];
#pragma unroll
    for (int i = 0; i < 16; i++)
#pragma unroll
        for (int j = 0; j < 4; j++) acc[i][j] = 0.0f;

    float4 a0 = *(const float4*)Ap0;
    float4 a1 = *(const float4*)Ap1;
    float4 b0 = *(const float4*)Bp0;
    float4 b1 = *(const float4*)Bp1;
    {
        uint4 v;
        v.x = f2tf(a0.x); v.y = f2tf(a0.y); v.z = f2tf(a0.z); v.w = f2tf(a0.w);
        *(uint4*)&As[0][ar0 * LDA + akc] = v;
        v.x = f2tf(a1.x); v.y = f2tf(a1.y); v.z = f2tf(a1.z); v.w = f2tf(a1.w);
        *(uint4*)&As[0][ar1 * LDA + akc] = v;
        v.x = f2tf(b0.x); v.y = f2tf(b0.y); v.z = f2tf(b0.z); v.w = f2tf(b0.w);
        *(uint4*)&Bs[0][bk0 * LDB + bnc] = v;
        v.x = f2tf(b1.x); v.y = f2tf(b1.y); v.z = f2tf(b1.z); v.w = f2tf(b1.w);
        *(uint4*)&Bs[0][bk1 * LDB + bnc] = v;
    }
    __syncthreads();

    const int NT = K / 16;
#pragma unroll 1
    for (int kt = 0; kt < NT; kt++) {
        const int cur = kt & 1;
        const bool more = (kt + 1) < NT;
        if (more) {
            a0 = *(const float4*)(Ap0 + (kt + 1) * 16);
            a1 = *(const float4*)(Ap1 + (kt + 1) * 16);
            b0 = *(const float4*)(Bp0 + (size_t)(kt + 1) * 16 * N);
            b1 = *(const float4*)(Bp1 + (size_t)(kt + 1) * 16 * N);
        }

#pragma unroll
        for (int ks = 0; ks < 2; ks++) {
            uint32_t af[4][4], bf[4][2];
#pragma unroll
            for (int mi = 0; mi < 4; mi++) {
                const int r = wm + mi * 16 + (lane >> 2);
                const int c = ks * 8 + (lane & 3);
                af[mi][0] = As[cur][r * LDA + c];
                af[mi][1] = As[cur][(r + 8) * LDA + c];
                af[mi][2] = As[cur][r * LDA + c + 4];
                af[mi][3] = As[cur][(r + 8) * LDA + c + 4];
            }
#pragma unroll
            for (int ni = 0; ni < 4; ni++) {
                const int n = wn + ni * 8 + (lane >> 2);
                const int k = ks * 8 + (lane & 3);
                bf[ni][0] = Bs[cur][k * LDB + n];
                bf[ni][1] = Bs[cur][(k + 4) * LDB + n];
            }
#pragma unroll
            for (int mi = 0; mi < 4; mi++)
#pragma unroll
                for (int ni = 0; ni < 4; ni++)
                    mma_tf32(acc[mi * 4 + ni], af[mi], bf[ni]);
        }

        if (more) {
            const int nx = (kt + 1) & 1;
            uint4 v;
            v.x = f2tf(a0.x); v.y = f2tf(a0.y); v.z = f2tf(a0.z); v.w = f2tf(a0.w);
            *(uint4*)&As[nx][ar0 * LDA + akc] = v;
            v.x = f2tf(a1.x); v.y = f2tf(a1.y); v.z = f2tf(a1.z); v.w = f2tf(a1.w);
            *(uint4*)&As[nx][ar1 * LDA + akc] = v;
            v.x = f2tf(b0.x); v.y = f2tf(b0.y); v.z = f2tf(b0.z); v.w = f2tf(b0.w);
            *(uint4*)&Bs[nx][bk0 * LDB + bnc] = v;
            v.x = f2tf(b1.x); v.y = f2tf(b1.y); v.z = f2tf(b1.z); v.w = f2tf(b1.w);
            *(uint4*)&Bs[nx][bk1 * LDB + bnc] = v;
        }
        __syncthreads();
    }

#pragma unroll
    for (int mi = 0; mi < 4; mi++) {
        const int r0 = bm + wm + mi * 16 + (lane >> 2);
        const int r1 = r0 + 8;
#pragma unroll
        for (int ni = 0; ni < 4; ni++) {
            const int c0 = bn + wn + ni * 8 + ((lane & 3) << 1);
            const float* a = acc[mi * 4 + ni];
            const float bi0 = bias[c0], bi1 = bias[c0 + 1];
            if (mode == 0) {
                *(float2*)&C[(size_t)r0 * N + c0] = make_float2(a[0] + bi0, a[1] + bi1);
                *(float2*)&C[(size_t)r1 * N + c0] = make_float2(a[2] + bi0, a[3] + bi1);
            } else {
                const int h = c0 >> 6, d = c0 & 63;
                const int b0r = r0 >> 11, s0 = r0 & (S_ - 1);
                const int b1r = r1 >> 11, s1 = r1 & (S_ - 1);
                *(float2*)&C[(((size_t)(b0r * NH + h)) * S_ + s0) * HD + d] =
                    make_float2(a[0] + bi0, a[1] + bi1);
                *(float2*)&C[(((size_t)(b1r * NH + h)) * S_ + s1) * HD + d] =
                    make_float2(a[2] + bi0, a[3] + bi1);
            }
        }
    }
}

// ---------------------------------------------------------------------------
// RoPE (in-place on Q and K, [B,H,S,hd] layout). One warp per (b,h,s) row.
// ---------------------------------------------------------------------------
__global__ void rope_kernel(float* __restrict__ Q, float* __restrict__ K,
                            const float* __restrict__ theta)
{
    const int gid  = blockIdx.x * blockDim.x + threadIdx.x;
    const int warp = gid >> 5;
    const int lane = gid & 31;
    const int s = warp & (S_ - 1);

    const float th = theta[lane];
    float sn, cs;
    sincosf((float)s * th, &sn, &cs);

    float* q = Q + (size_t)warp * HD;
    float x1 = q[2 * lane], x2 = q[2 * lane + 1];
    __syncwarp();
    q[lane]      = x1 * cs - x2 * sn;
    q[lane + 32] = x1 * sn + x2 * cs;

    float* k = K + (size_t)warp * HD;
    float y1 = k[2 * lane], y2 = k[2 * lane + 1];
    __syncwarp();
    k[lane]      = y1 * cs - y2 * sn;
    k[lane + 32] = y1 * sn + y2 * cs;
}

// ---------------------------------------------------------------------------
// TF32 tensor-core causal flash attention.
// Grid (S/128, B*H), 256 threads = 8 warps; warp w owns q-rows [16w,16w+16).
// BQ=128, BK=64. All matmuls on m16n8k8 tf32 MMA; softmax on fragments with
// quad shfl reductions. P staged through smem per-warp (syncwarp only).
// Pads: LD=68 for Qs/Ks/Ps (bank 4g+c conflict-free), LD=72 for Vs (8k+n).
// ---------------------------------------------------------------------------
#define QLD 68
#define KLD 68
#define VLD 72
#define PLD 68
#define FLASH_SMEM_WORDS (128*QLD + 64*KLD + 64*VLD + 128*PLD)

__global__ __launch_bounds__(256, 1) void flash_tf32_kernel(
    const float* __restrict__ Q, const float* __restrict__ K,
    const float* __restrict__ V, float* __restrict__ ctx)
{
    extern __shared__ uint32_t sm[];
    uint32_t* Qs = sm;                  // [128][QLD] tf32 (pre-scaled by 1/8)
    uint32_t* Ks = Qs + 128 * QLD;      // [64][KLD]  tf32
    uint32_t* Vs = Ks + 64 * KLD;       // [64][VLD]  tf32
    uint32_t* Ps = Vs + 64 * VLD;       // [128][PLD] tf32

    const int qb   = blockIdx.x;
    const int bh   = blockIdx.y;
    const int tid  = threadIdx.x;
    const int lane = tid & 31;
    const int warp = tid >> 5;
    const int g = lane >> 2;       // group-of-4 id = row within 8
    const int c = lane & 3;        // lane within quad
    const int wrow = warp * 16;    // warp's q-row base within tile

    const float* Qg = Q + ((size_t)bh * S_ + qb * 128) * HD;
    const float* Kg = K + (size_t)bh * S_ * HD;
    const float* Vg = V + (size_t)bh * S_ * HD;

    // load Q tile: fold softmax scale, convert to tf32
    for (int i = tid; i < 2048; i += 256) {       // 2048 float4
        const int r = i >> 4, c4 = (i & 15) << 2;
        float4 v = ((const float4*)Qg)[i];
        Qs[r * QLD + c4 + 0] = f2tf(v.x * 0.125f);
        Qs[r * QLD + c4 + 1] = f2tf(v.y * 0.125f);
        Qs[r * QLD + c4 + 2] = f2tf(v.z * 0.125f);
        Qs[r * QLD + c4 + 3] = f2tf(v.w * 0.125f);
    }

    float oacc[8][4];
#pragma unroll
    for (int nt = 0; nt < 8; nt++)
#pragma unroll
        for (int k = 0; k < 4; k++) oacc[nt][k] = 0.0f;
    float m0 = -3.0e38f, m1 = -3.0e38f, l0 = 0.0f, l1 = 0.0f;

    const int jmax = 2 * qb + 1;
    for (int j = 0; j <= jmax; j++) {
        __syncthreads();   // prior iter's Ks/Vs reads (and Qs init) complete
        const float4* kg = (const float4*)(Kg + (size_t)j * 64 * HD);
        const float4* vg = (const float4*)(Vg + (size_t)j * 64 * HD);
        for (int i = tid; i < 1024; i += 256) {
            const int r = i >> 4, c4 = (i & 15) << 2;
            float4 kv = kg[i];
            Ks[r * KLD + c4 + 0] = f2tf(kv.x);
            Ks[r * KLD + c4 + 1] = f2tf(kv.y);
            Ks[r * KLD + c4 + 2] = f2tf(kv.z);
            Ks[r * KLD + c4 + 3] = f2tf(kv.w);
            float4 vv = vg[i];
            Vs[r * VLD + c4 + 0] = f2tf(vv.x);
            Vs[r * VLD + c4 + 1] = f2tf(vv.y);
            Vs[r * VLD + c4 + 2] = f2tf(vv.z);
            Vs[r * VLD + c4 + 3] = f2tf(vv.w);
        }
        __syncthreads();

        // ---- S = Qs @ Ks^T  (warp rows [wrow, wrow+16), all 64 keys)
        float sacc[8][4];
#pragma unroll
        for (int nt = 0; nt < 8; nt++)
#pragma unroll
            for (int k = 0; k < 4; k++) sacc[nt][k] = 0.0f;

#pragma unroll
        for (int ks = 0; ks < 8; ks++) {
            uint32_t af[4];
            af[0] = Qs[(wrow + g)     * QLD + ks * 8 + c];
            af[1] = Qs[(wrow + g + 8) * QLD + ks * 8 + c];
            af[2] = Qs[(wrow + g)     * QLD + ks * 8 + c + 4];
            af[3] = Qs[(wrow + g + 8) * QLD + ks * 8 + c + 4];
#pragma unroll
            for (int nt = 0; nt < 8; nt++) {
                uint32_t bf[2];
                bf[0] = Ks[(nt * 8 + g) * KLD + ks * 8 + c];
                bf[1] = Ks[(nt * 8 + g) * KLD + ks * 8 + c + 4];
                mma_tf32(sacc[nt], af, bf);
            }
        }

        // ---- causal mask (diagonal tiles only)
        if (j >= 2 * qb) {
            const int r0 = qb * 128 + wrow + g;
            const int r1 = r0 + 8;
#pragma unroll
            for (int nt = 0; nt < 8; nt++) {
                const int col = j * 64 + nt * 8 + 2 * c;
                if (col     > r0) sacc[nt][0] = -3.0e38f;
                if (col + 1 > r0) sacc[nt][1] = -3.0e38f;
                if (col     > r1) sacc[nt][2] = -3.0e38f;
                if (col + 1 > r1) sacc[nt][3] = -3.0e38f;
            }
        }

        // ---- online softmax on fragments
        float rmax0 = -3.0e38f, rmax1 = -3.0e38f;
#pragma unroll
        for (int nt = 0; nt < 8; nt++) {
            rmax0 = fmaxf(rmax0, fmaxf(sacc[nt][0], sacc[nt][1]));
            rmax1 = fmaxf(rmax1, fmaxf(sacc[nt][2], sacc[nt][3]));
        }
#pragma unroll
        for (int off = 1; off < 4; off <<= 1) {
            rmax0 = fmaxf(rmax0, __shfl_xor_sync(0xffffffffu, rmax0, off));
            rmax1 = fmaxf(rmax1, __shfl_xor_sync(0xffffffffu, rmax1, off));
        }

        const float mn0 = fmaxf(m0, rmax0);
        const float mn1 = fmaxf(m1, rmax1);
        const float al0 = __expf(m0 - mn0);
        const float al1 = __expf(m1 - mn1);

        float rsum0 = 0.0f, rsum1 = 0.0f;
        __syncwarp();   // prior PV reads of Ps complete before overwrite
#pragma unroll
        for (int nt = 0; nt < 8; nt++) {
            const float p0 = __expf(sacc[nt][0] - mn0);
            const float p1 = __expf(sacc[nt][1] - mn0);
            const float p2 = __expf(sacc[nt][2] - mn1);
            const float p3 = __expf(sacc[nt][3] - mn1);
            rsum0 += p0 + p1;
            rsum1 += p2 + p3;
            *(uint2*)&Ps[(wrow + g)     * PLD + nt * 8 + 2 * c] =
                make_uint2(f2tf(p0), f2tf(p1));
            *(uint2*)&Ps[(wrow + g + 8) * PLD + nt * 8 + 2 * c] =
                make_uint2(f2tf(p2), f2tf(p3));
        }
#pragma unroll
        for (int off = 1; off < 4; off <<= 1) {
            rsum0 += __shfl_xor_sync(0xffffffffu, rsum0, off);
            rsum1 += __shfl_xor_sync(0xffffffffu, rsum1, off);
        }
        l0 = l0 * al0 + rsum0;
        l1 = l1 * al1 + rsum1;
        m0 = mn0;
        m1 = mn1;
#pragma unroll
        for (int nt = 0; nt < 8; nt++) {
            oacc[nt][0] *= al0;
            oacc[nt][1] *= al0;
            oacc[nt][2] *= al1;
            oacc[nt][3] *= al1;
        }
        __syncwarp();   // Ps writes visible to whole warp

        // ---- O += P @ V  (K-dim = 64 keys)
#pragma unroll
        for (int ks = 0; ks < 8; ks++) {
            uint32_t af[4];
            af[0] = Ps[(wrow + g)     * PLD + ks * 8 + c];
            af[1] = Ps[(wrow + g + 8) * PLD + ks * 8 + c];
            af[2] = Ps[(wrow + g)     * PLD + ks * 8 + c + 4];
            af[3] = Ps[(wrow + g + 8) * PLD + ks * 8 + c + 4];
#pragma unroll
            for (int nt = 0; nt < 8; nt++) {
                uint32_t bf[2];
                bf[0] = Vs[(ks * 8 + c)     * VLD + nt * 8 + g];
                bf[1] = Vs[(ks * 8 + c + 4) * VLD + nt * 8 + g];
                mma_tf32(oacc[nt], af, bf);
            }
        }
    }

    // ---- write ctx [B*S, H*hd]
    const int b = bh >> 4, h = bh & 15;
    const int r0 = qb * 128 + wrow + g;
    const int r1 = r0 + 8;
    const float inv0 = 1.0f / l0;
    const float inv1 = 1.0f / l1;
#pragma unroll
    for (int nt = 0; nt < 8; nt++) {
        const int col = h * 64 + nt * 8 + 2 * c;
        *(float2*)&ctx[(size_t)(b * S_ + r0) * DIM + col] =
            make_float2(oacc[nt][0] * inv0, oacc[nt][1] * inv0);
        *(float2*)&ctx[(size_t)(b * S_ + r1) * DIM + col] =
            make_float2(oacc[nt][2] * inv1, oacc[nt][3] * inv1);
    }
}

// ---------------------------------------------------------------------------
extern "C" void kernel_launch(void* const* d_in, const int* in_sizes, int n_in,
                              void* d_out, int out_size)
{
    const float* x     = (const float*)d_in[0];
    const float* theta = (const float*)d_in[2];
    const float* Wq    = (const float*)d_in[3];
    const float* bq    = (const float*)d_in[4];
    const float* Wk    = (const float*)d_in[5];
    const float* bk    = (const float*)d_in[6];
    const float* Wv    = (const float*)d_in[7];
    const float* bv    = (const float*)d_in[8];
    const float* Wo    = (const float*)d_in[9];
    const float* bo    = (const float*)d_in[10];
    float* out = (float*)d_out;

    float *Qb, *Kb, *Vb, *Cb;
    cudaGetSymbolAddress((void**)&Qb, g_Q);
    cudaGetSymbolAddress((void**)&Kb, g_K);
    cudaGetSymbolAddress((void**)&Vb, g_V);
    cudaGetSymbolAddress((void**)&Cb, g_C);

    const dim3 gemmGrid(DIM / 128, MROWS / 128);

    tf32_gemm_kernel<<<gemmGrid, 256>>>(x, Wq, bq, Qb, MROWS, DIM, DIM, 1);
    tf32_gemm_kernel<<<gemmGrid, 256>>>(x, Wk, bk, Kb, MROWS, DIM, DIM, 1);
    tf32_gemm_kernel<<<gemmGrid, 256>>>(x, Wv, bv, Vb, MROWS, DIM, DIM, 1);

    rope_kernel<<<(B_ * NH * S_ * 32) / 256, 256>>>(Qb, Kb, theta);

    const int flashSmem = FLASH_SMEM_WORDS * (int)sizeof(uint32_t);  // ~103 KB
    cudaFuncSetAttribute(flash_tf32_kernel,
                         cudaFuncAttributeMaxDynamicSharedMemorySize, flashSmem);
    flash_tf32_kernel<<<dim3(S_ / 128, B_ * NH), 256, flashSmem>>>(Qb, Kb, Vb, Cb);

    tf32_gemm_kernel<<<gemmGrid, 256>>>(Cb, Wo, bo, out, MROWS, DIM, DIM, 0);
}

// round 7
// speedup vs baseline: 2.9251x; 1.1339x over previous
#include <cuda_runtime.h>
#include <math.h>
#include <stdint.h>

#define DIM   1024
#define NH    16
#define HD    64
#define B_    2
#define S_    2048
#define MROWS (B_ * S_)   // 4096

// Scratch (allocation-free rule: __device__ globals)
__device__ float g_Q[B_ * NH * S_ * HD];   // [B,H,S,hd]
__device__ float g_K[B_ * NH * S_ * HD];
__device__ float g_V[B_ * NH * S_ * HD];
__device__ float g_C[MROWS * DIM];         // attention context, [B*S, H*hd]

// ---------------------------------------------------------------------------
// TF32 / async helpers
// ---------------------------------------------------------------------------
__device__ __forceinline__ uint32_t f2tf(float f) {
    uint32_t r;
    asm("cvt.rna.tf32.f32 %0, %1;" : "=r"(r) : "f"(f));
    return r;
}
__device__ __forceinline__ float tfr(float f) { return __uint_as_float(f2tf(f)); }

__device__ __forceinline__ void mma_tf32(float* d, const uint32_t* a, const uint32_t* b) {
    asm volatile(
        "mma.sync.aligned.m16n8k8.row.col.f32.tf32.tf32.f32 "
        "{%0,%1,%2,%3}, {%4,%5,%6,%7}, {%8,%9}, {%0,%1,%2,%3};"
        : "+f"(d[0]), "+f"(d[1]), "+f"(d[2]), "+f"(d[3])
        : "r"(a[0]), "r"(a[1]), "r"(a[2]), "r"(a[3]),
          "r"(b[0]), "r"(b[1]));
}

__device__ __forceinline__ void cp_async16(uint32_t smem_byte_addr, const void* gptr) {
    asm volatile("cp.async.cg.shared.global [%0], [%1], 16;"
                 :: "r"(smem_byte_addr), "l"(gptr));
}
__device__ __forceinline__ void cp_commit() {
    asm volatile("cp.async.commit_group;");
}

// ---------------------------------------------------------------------------
// TF32 tensor-core GEMM: C[M,N] = A[M,K] @ W[K,N] + bias
// mode 0: C row-major [M,N]
// mode 1: scatter to [B,H,S,hd], values rounded to tf32-RNA (so downstream
//         flash can cp.async them and feed the MMA losslessly)
// ---------------------------------------------------------------------------
#define LDA 20
#define LDB 136

__global__ __launch_bounds__(256) void tf32_gemm_kernel(
    const float* __restrict__ A, const float* __restrict__ W,
    const float* __restrict__ bias, float* __restrict__ C,
    int M, int N, int K, int mode)
{
    __shared__ uint32_t As[2][128 * LDA];   // [row][k] tf32
    __shared__ uint32_t Bs[2][16 * LDB];    // [k][n]   tf32

    const int tid  = threadIdx.x;
    const int lane = tid & 31;
    const int warp = tid >> 5;
    const int bm = blockIdx.y * 128;
    const int bn = blockIdx.x * 128;
    const int wm = (warp & 1) << 6;
    const int wn = (warp >> 1) << 5;

    const int ar0 = tid >> 2;
    const int ar1 = (tid + 256) >> 2;
    const int akc = (tid & 3) << 2;
    const int bk0 = tid >> 5;
    const int bk1 = (tid + 256) >> 5;
    const int bnc = (tid & 31) << 2;

    const float* Ap0 = A + (size_t)(bm + ar0) * K + akc;
    const float* Ap1 = A + (size_t)(bm + ar1) * K + akc;
    const float* Bp0 = W + (size_t)bk0 * N + bn + bnc;
    const float* Bp1 = W + (size_t)bk1 * N + bn + bnc;

    float acc[16][4];
#pragma unroll
    for (int i = 0; i < 16; i++)
#pragma unroll
        for (int j = 0; j < 4; j++) acc[i][j] = 0.0f;

    float4 a0 = *(const float4*)Ap0;
    float4 a1 = *(const float4*)Ap1;
    float4 b0 = *(const float4*)Bp0;
    float4 b1 = *(const float4*)Bp1;
    {
        uint4 v;
        v.x = f2tf(a0.x); v.y = f2tf(a0.y); v.z = f2tf(a0.z); v.w = f2tf(a0.w);
        *(uint4*)&As[0][ar0 * LDA + akc] = v;
        v.x = f2tf(a1.x); v.y = f2tf(a1.y); v.z = f2tf(a1.z); v.w = f2tf(a1.w);
        *(uint4*)&As[0][ar1 * LDA + akc] = v;
        v.x = f2tf(b0.x); v.y = f2tf(b0.y); v.z = f2tf(b0.z); v.w = f2tf(b0.w);
        *(uint4*)&Bs[0][bk0 * LDB + bnc] = v;
        v.x = f2tf(b1.x); v.y = f2tf(b1.y); v.z = f2tf(b1.z); v.w = f2tf(b1.w);
        *(uint4*)&Bs[0][bk1 * LDB + bnc] = v;
    }
    __syncthreads();

    const int NT = K / 16;
#pragma unroll 1
    for (int kt = 0; kt < NT; kt++) {
        const int cur = kt & 1;
        const bool more = (kt + 1) < NT;
        if (more) {
            a0 = *(const float4*)(Ap0 + (kt + 1) * 16);
            a1 = *(const float4*)(Ap1 + (kt + 1) * 16);
            b0 = *(const float4*)(Bp0 + (size_t)(kt + 1) * 16 * N);
            b1 = *(const float4*)(Bp1 + (size_t)(kt + 1) * 16 * N);
        }

#pragma unroll
        for (int ks = 0; ks < 2; ks++) {
            uint32_t af[4][4], bf[4][2];
#pragma unroll
            for (int mi = 0; mi < 4; mi++) {
                const int r = wm + mi * 16 + (lane >> 2);
                const int c = ks * 8 + (lane & 3);
                af[mi][0] = As[cur][r * LDA + c];
                af[mi][1] = As[cur][(r + 8) * LDA + c];
                af[mi][2] = As[cur][r * LDA + c + 4];
                af[mi][3] = As[cur][(r + 8) * LDA + c + 4];
            }
#pragma unroll
            for (int ni = 0; ni < 4; ni++) {
                const int n = wn + ni * 8 + (lane >> 2);
                const int k = ks * 8 + (lane & 3);
                bf[ni][0] = Bs[cur][k * LDB + n];
                bf[ni][1] = Bs[cur][(k + 4) * LDB + n];
            }
#pragma unroll
            for (int mi = 0; mi < 4; mi++)
#pragma unroll
                for (int ni = 0; ni < 4; ni++)
                    mma_tf32(acc[mi * 4 + ni], af[mi], bf[ni]);
        }

        if (more) {
            const int nx = (kt + 1) & 1;
            uint4 v;
            v.x = f2tf(a0.x); v.y = f2tf(a0.y); v.z = f2tf(a0.z); v.w = f2tf(a0.w);
            *(uint4*)&As[nx][ar0 * LDA + akc] = v;
            v.x = f2tf(a1.x); v.y = f2tf(a1.y); v.z = f2tf(a1.z); v.w = f2tf(a1.w);
            *(uint4*)&As[nx][ar1 * LDA + akc] = v;
            v.x = f2tf(b0.x); v.y = f2tf(b0.y); v.z = f2tf(b0.z); v.w = f2tf(b0.w);
            *(uint4*)&Bs[nx][bk0 * LDB + bnc] = v;
            v.x = f2tf(b1.x); v.y = f2tf(b1.y); v.z = f2tf(b1.z); v.w = f2tf(b1.w);
            *(uint4*)&Bs[nx][bk1 * LDB + bnc] = v;
        }
        __syncthreads();
    }

#pragma unroll
    for (int mi = 0; mi < 4; mi++) {
        const int r0 = bm + wm + mi * 16 + (lane >> 2);
        const int r1 = r0 + 8;
#pragma unroll
        for (int ni = 0; ni < 4; ni++) {
            const int c0 = bn + wn + ni * 8 + ((lane & 3) << 1);
            const float* a = acc[mi * 4 + ni];
            const float bi0 = bias[c0], bi1 = bias[c0 + 1];
            if (mode == 0) {
                *(float2*)&C[(size_t)r0 * N + c0] = make_float2(a[0] + bi0, a[1] + bi1);
                *(float2*)&C[(size_t)r1 * N + c0] = make_float2(a[2] + bi0, a[3] + bi1);
            } else {
                const int h = c0 >> 6, d = c0 & 63;
                const int b0r = r0 >> 11, s0 = r0 & (S_ - 1);
                const int b1r = r1 >> 11, s1 = r1 & (S_ - 1);
                *(float2*)&C[(((size_t)(b0r * NH + h)) * S_ + s0) * HD + d] =
                    make_float2(tfr(a[0] + bi0), tfr(a[1] + bi1));
                *(float2*)&C[(((size_t)(b1r * NH + h)) * S_ + s1) * HD + d] =
                    make_float2(tfr(a[2] + bi0), tfr(a[3] + bi1));
            }
        }
    }
}

// ---------------------------------------------------------------------------
// RoPE (in-place on Q and K). Outputs rounded to tf32-RNA so flash can
// consume the raw bits losslessly through the tf32 MMA.
// ---------------------------------------------------------------------------
__global__ void rope_kernel(float* __restrict__ Q, float* __restrict__ K,
                            const float* __restrict__ theta)
{
    const int gid  = blockIdx.x * blockDim.x + threadIdx.x;
    const int warp = gid >> 5;
    const int lane = gid & 31;
    const int s = warp & (S_ - 1);

    const float th = theta[lane];
    float sn, cs;
    sincosf((float)s * th, &sn, &cs);

    float* q = Q + (size_t)warp * HD;
    float x1 = q[2 * lane], x2 = q[2 * lane + 1];
    __syncwarp();
    q[lane]      = tfr(x1 * cs - x2 * sn);
    q[lane + 32] = tfr(x1 * sn + x2 * cs);

    float* k = K + (size_t)warp * HD;
    float y1 = k[2 * lane], y2 = k[2 * lane + 1];
    __syncwarp();
    k[lane]      = tfr(y1 * cs - y2 * sn);
    k[lane + 32] = tfr(y1 * sn + y2 * cs);
}

// ---------------------------------------------------------------------------
// TF32 tensor-core causal flash attention, cp.async double-buffered K/V.
// Grid (S/128, B*H), 256 threads = 8 warps; warp w owns q-rows [16w,16w+16).
// K/V arrive in GMEM already tf32-RNA-rounded, so raw cp.async bytes feed
// the tf32 MMA losslessly (HW truncation is a no-op on pre-rounded values).
// ---------------------------------------------------------------------------
#define QLD 68
#define KLD 68
#define VLD 72
#define PLD 68
#define KBUF (64 * KLD)
#define VBUF (64 * VLD)
#define FLASH_SMEM_WORDS (128*QLD + 2*KBUF + 2*VBUF + 128*PLD)

__global__ __launch_bounds__(256, 1) void flash_tf32_kernel(
    const float* __restrict__ Q, const float* __restrict__ K,
    const float* __restrict__ V, float* __restrict__ ctx)
{
    extern __shared__ uint32_t sm[];
    uint32_t* Qs = sm;                   // [128][QLD] tf32 (pre-scaled by 1/8)
    uint32_t* Ks = Qs + 128 * QLD;       // [2][64][KLD]
    uint32_t* Vs = Ks + 2 * KBUF;        // [2][64][VLD]
    uint32_t* Ps = Vs + 2 * VBUF;        // [128][PLD] tf32

    const int qb   = blockIdx.x;
    const int bh   = blockIdx.y;
    const int tid  = threadIdx.x;
    const int lane = tid & 31;
    const int warp = tid >> 5;
    const int g = lane >> 2;
    const int c = lane & 3;
    const int wrow = warp * 16;

    const float* Qg = Q + ((size_t)bh * S_ + qb * 128) * HD;
    const float* Kg = K + (size_t)bh * S_ * HD;
    const float* Vg = V + (size_t)bh * S_ * HD;

    const uint32_t ks_smem = (uint32_t)__cvta_generic_to_shared(Ks);
    const uint32_t vs_smem = (uint32_t)__cvta_generic_to_shared(Vs);

    // per-thread cp.async assignment: 4 rows of 16B chunks for K and V each
    const int lr = tid >> 4;            // 0..15  (row block)
    const int lc = (tid & 15) << 2;     // 0..60  (float col)

    // issue async copy of tile t into buffer b
    auto issue_tile = [&](int t, int b) {
        const float* kg = Kg + (size_t)t * 64 * HD;
        const float* vg = Vg + (size_t)t * 64 * HD;
#pragma unroll
        for (int rr = 0; rr < 4; rr++) {
            const int r = lr + rr * 16;
            cp_async16(ks_smem + (b * KBUF + r * KLD + lc) * 4, kg + r * HD + lc);
            cp_async16(vs_smem + (b * VBUF + r * VLD + lc) * 4, vg + r * HD + lc);
        }
        cp_commit();
    };

    issue_tile(0, 0);

    // load Q tile: fold softmax scale (x0.125 exact in tf32), convert
    for (int i = tid; i < 2048; i += 256) {
        const int r = i >> 4, c4 = (i & 15) << 2;
        float4 v = ((const float4*)Qg)[i];
        Qs[r * QLD + c4 + 0] = f2tf(v.x * 0.125f);
        Qs[r * QLD + c4 + 1] = f2tf(v.y * 0.125f);
        Qs[r * QLD + c4 + 2] = f2tf(v.z * 0.125f);
        Qs[r * QLD + c4 + 3] = f2tf(v.w * 0.125f);
    }

    float oacc[8][4];
#pragma unroll
    for (int nt = 0; nt < 8; nt++)
#pragma unroll
        for (int k = 0; k < 4; k++) oacc[nt][k] = 0.0f;
    float m0 = -3.0e38f, m1 = -3.0e38f, l0 = 0.0f, l1 = 0.0f;

    const int jmax = 2 * qb + 1;
    int buf = 0;
    for (int j = 0; j <= jmax; j++) {
        if (j < jmax) {
            issue_tile(j + 1, buf ^ 1);
            asm volatile("cp.async.wait_group 1;");
        } else {
            asm volatile("cp.async.wait_group 0;");
        }
        __syncthreads();   // tile j visible to all; also covers Qs init (j=0)

        const uint32_t* Kb = Ks + buf * KBUF;
        const uint32_t* Vb = Vs + buf * VBUF;

        // ---- S = Qs @ K^T
        float sacc[8][4];
#pragma unroll
        for (int nt = 0; nt < 8; nt++)
#pragma unroll
            for (int k = 0; k < 4; k++) sacc[nt][k] = 0.0f;

#pragma unroll
        for (int ks = 0; ks < 8; ks++) {
            uint32_t af[4];
            af[0] = Qs[(wrow + g)     * QLD + ks * 8 + c];
            af[1] = Qs[(wrow + g + 8) * QLD + ks * 8 + c];
            af[2] = Qs[(wrow + g)     * QLD + ks * 8 + c + 4];
            af[3] = Qs[(wrow + g + 8) * QLD + ks * 8 + c + 4];
#pragma unroll
            for (int nt = 0; nt < 8; nt++) {
                uint32_t bf[2];
                bf[0] = Kb[(nt * 8 + g) * KLD + ks * 8 + c];
                bf[1] = Kb[(nt * 8 + g) * KLD + ks * 8 + c + 4];
                mma_tf32(sacc[nt], af, bf);
            }
        }

        // ---- causal mask (diagonal tiles only)
        if (j >= 2 * qb) {
            const int r0 = qb * 128 + wrow + g;
            const int r1 = r0 + 8;
#pragma unroll
            for (int nt = 0; nt < 8; nt++) {
                const int col = j * 64 + nt * 8 + 2 * c;
                if (col     > r0) sacc[nt][0] = -3.0e38f;
                if (col + 1 > r0) sacc[nt][1] = -3.0e38f;
                if (col     > r1) sacc[nt][2] = -3.0e38f;
                if (col + 1 > r1) sacc[nt][3] = -3.0e38f;
            }
        }

        // ---- online softmax on fragments
        float rmax0 = -3.0e38f, rmax1 = -3.0e38f;
#pragma unroll
        for (int nt = 0; nt < 8; nt++) {
            rmax0 = fmaxf(rmax0, fmaxf(sacc[nt][0], sacc[nt][1]));
            rmax1 = fmaxf(rmax1, fmaxf(sacc[nt][2], sacc[nt][3]));
        }
#pragma unroll
        for (int off = 1; off < 4; off <<= 1) {
            rmax0 = fmaxf(rmax0, __shfl_xor_sync(0xffffffffu, rmax0, off));
            rmax1 = fmaxf(rmax1, __shfl_xor_sync(0xffffffffu, rmax1, off));
        }

        const float mn0 = fmaxf(m0, rmax0);
        const float mn1 = fmaxf(m1, rmax1);
        const float al0 = __expf(m0 - mn0);
        const float al1 = __expf(m1 - mn1);

        float rsum0 = 0.0f, rsum1 = 0.0f;
        __syncwarp();   // prior PV reads of Ps complete before overwrite
#pragma unroll
        for (int nt = 0; nt < 8; nt++) {
            const float p0 = __expf(sacc[nt][0] - mn0);
            const float p1 = __expf(sacc[nt][1] - mn0);
            const float p2 = __expf(sacc[nt][2] - mn1);
            const float p3 = __expf(sacc[nt][3] - mn1);
            rsum0 += p0 + p1;
            rsum1 += p2 + p3;
            *(uint2*)&Ps[(wrow + g)     * PLD + nt * 8 + 2 * c] =
                make_uint2(f2tf(p0), f2tf(p1));
            *(uint2*)&Ps[(wrow + g + 8) * PLD + nt * 8 + 2 * c] =
                make_uint2(f2tf(p2), f2tf(p3));
        }
#pragma unroll
        for (int off = 1; off < 4; off <<= 1) {
            rsum0 += __shfl_xor_sync(0xffffffffu, rsum0, off);
            rsum1 += __shfl_xor_sync(0xffffffffu, rsum1, off);
        }
        l0 = l0 * al0 + rsum0;
        l1 = l1 * al1 + rsum1;
        m0 = mn0;
        m1 = mn1;
#pragma unroll
        for (int nt = 0; nt < 8; nt++) {
            oacc[nt][0] *= al0;
            oacc[nt][1] *= al0;
            oacc[nt][2] *= al1;
            oacc[nt][3] *= al1;
        }
        __syncwarp();   // Ps writes visible to whole warp

        // ---- O += P @ V
#pragma unroll
        for (int ks = 0; ks < 8; ks++) {
            uint32_t af[4];
            af[0] = Ps[(wrow + g)     * PLD + ks * 8 + c];
            af[1] = Ps[(wrow + g + 8) * PLD + ks * 8 + c];
            af[2] = Ps[(wrow + g)     * PLD + ks * 8 + c + 4];
            af[3] = Ps[(wrow + g + 8) * PLD + ks * 8 + c + 4];
#pragma unroll
            for (int nt = 0; nt < 8; nt++) {
                uint32_t bf[2];
                bf[0] = Vb[(ks * 8 + c)     * VLD + nt * 8 + g];
                bf[1] = Vb[(ks * 8 + c + 4) * VLD + nt * 8 + g];
                mma_tf32(oacc[nt], af, bf);
            }
        }

        __syncthreads();   // all warps done with buf before it is re-issued
        buf ^= 1;
    }

    // ---- write ctx [B*S, H*hd]
    const int b = bh >> 4, h = bh & 15;
    const int r0 = qb * 128 + wrow + g;
    const int r1 = r0 + 8;
    const float inv0 = 1.0f / l0;
    const float inv1 = 1.0f / l1;
#pragma unroll
    for (int nt = 0; nt < 8; nt++) {
        const int col = h * 64 + nt * 8 + 2 * c;
        *(float2*)&ctx[(size_t)(b * S_ + r0) * DIM + col] =
            make_float2(oacc[nt][0] * inv0, oacc[nt][1] * inv0);
        *(float2*)&ctx[(size_t)(b * S_ + r1) * DIM + col] =
            make_float2(oacc[nt][2] * inv1, oacc[nt][3] * inv1);
    }
}

// ---------------------------------------------------------------------------
extern "C" void kernel_launch(void* const* d_in, const int* in_sizes, int n_in,
                              void* d_out, int out_size)
{
    const float* x     = (const float*)d_in[0];
    const float* theta = (const float*)d_in[2];
    const float* Wq    = (const float*)d_in[3];
    const float* bq    = (const float*)d_in[4];
    const float* Wk    = (const float*)d_in[5];
    const float* bk    = (const float*)d_in[6];
    const float* Wv    = (const float*)d_in[7];
    const float* bv    = (const float*)d_in[8];
    const float* Wo    = (const float*)d_in[9];
    const float* bo    = (const float*)d_in[10];
    float* out = (float*)d_out;

    float *Qb, *Kb, *Vb, *Cb;
    cudaGetSymbolAddress((void**)&Qb, g_Q);
    cudaGetSymbolAddress((void**)&Kb, g_K);
    cudaGetSymbolAddress((void**)&Vb, g_V);
    cudaGetSymbolAddress((void**)&Cb, g_C);

    const dim3 gemmGrid(DIM / 128, MROWS / 128);

    tf32_gemm_kernel<<<gemmGrid, 256>>>(x, Wq, bq, Qb, MROWS, DIM, DIM, 1);
    tf32_gemm_kernel<<<gemmGrid, 256>>>(x, Wk, bk, Kb, MROWS, DIM, DIM, 1);
    tf32_gemm_kernel<<<gemmGrid, 256>>>(x, Wv, bv, Vb, MROWS, DIM, DIM, 1);

    rope_kernel<<<(B_ * NH * S_ * 32) / 256, 256>>>(Qb, Kb, theta);

    const int flashSmem = FLASH_SMEM_WORDS * (int)sizeof(uint32_t);  // ~138 KB
    cudaFuncSetAttribute(flash_tf32_kernel,
                         cudaFuncAttributeMaxDynamicSharedMemorySize, flashSmem);
    flash_tf32_kernel<<<dim3(S_ / 128, B_ * NH), 256, flashSmem>>>(Qb, Kb, Vb, Cb);

    tf32_gemm_kernel<<<gemmGrid, 256>>>(Cb, Wo, bo, out, MROWS, DIM, DIM, 0);
}

// round 8
// speedup vs baseline: 2.9303x; 1.0018x over previous
#include <cuda_runtime.h>
#include <math.h>
#include <stdint.h>

#define DIM   1024
#define NH    16
#define HD    64
#define B_    2
#define S_    2048
#define MROWS (B_ * S_)   // 4096

// Scratch (allocation-free rule: __device__ globals)
__device__ float g_Q[B_ * NH * S_ * HD];   // [B,H,S,hd]
__device__ float g_K[B_ * NH * S_ * HD];
__device__ float g_V[B_ * NH * S_ * HD];
__device__ float g_C[MROWS * DIM];         // attention context, [B*S, H*hd]

// ---------------------------------------------------------------------------
// TF32 / async helpers
// ---------------------------------------------------------------------------
__device__ __forceinline__ uint32_t f2tf(float f) {
    uint32_t r;
    asm("cvt.rna.tf32.f32 %0, %1;" : "=r"(r) : "f"(f));
    return r;
}
__device__ __forceinline__ float tfr(float f) { return __uint_as_float(f2tf(f)); }

__device__ __forceinline__ void mma_tf32(float* d, const uint32_t* a, const uint32_t* b) {
    asm volatile(
        "mma.sync.aligned.m16n8k8.row.col.f32.tf32.tf32.f32 "
        "{%0,%1,%2,%3}, {%4,%5,%6,%7}, {%8,%9}, {%0,%1,%2,%3};"
        : "+f"(d[0]), "+f"(d[1]), "+f"(d[2]), "+f"(d[3])
        : "r"(a[0]), "r"(a[1]), "r"(a[2]), "r"(a[3]),
          "r"(b[0]), "r"(b[1]));
}

__device__ __forceinline__ void cp_async16(uint32_t smem_byte_addr, const void* gptr) {
    asm volatile("cp.async.cg.shared.global [%0], [%1], 16;"
                 :: "r"(smem_byte_addr), "l"(gptr));
}
__device__ __forceinline__ void cp_commit() {
    asm volatile("cp.async.commit_group;");
}

// ---------------------------------------------------------------------------
// TF32 tensor-core GEMM: C[M,N] = A[M,K] @ W[K,N] + bias
// mode 0: C row-major [M,N]
// mode 1: scatter to [B,H,S,hd], values rounded to tf32-RNA (so downstream
//         flash can cp.async them and feed the MMA losslessly)
// ---------------------------------------------------------------------------
#define LDA 20
#define LDB 136

__global__ __launch_bounds__(256) void tf32_gemm_kernel(
    const float* __restrict__ A, const float* __restrict__ W,
    const float* __restrict__ bias, float* __restrict__ C,
    int M, int N, int K, int mode)
{
    __shared__ uint32_t As[2][128 * LDA];   // [row][k] tf32
    __shared__ uint32_t Bs[2][16 * LDB];    // [k][n]   tf32

    const int tid  = threadIdx.x;
    const int lane = tid & 31;
    const int warp = tid >> 5;
    const int bm = blockIdx.y * 128;
    const int bn = blockIdx.x * 128;
    const int wm = (warp & 1) << 6;
    const int wn = (warp >> 1) << 5;

    const int ar0 = tid >> 2;
    const int ar1 = (tid + 256) >> 2;
    const int akc = (tid & 3) << 2;
    const int bk0 = tid >> 5;
    const int bk1 = (tid + 256) >> 5;
    const int bnc = (tid & 31) << 2;

    const float* Ap0 = A + (size_t)(bm + ar0) * K + akc;
    const float* Ap1 = A + (size_t)(bm + ar1) * K + akc;
    const float* Bp0 = W + (size_t)bk0 * N + bn + bnc;
    const float* Bp1 = W + (size_t)bk1 * N + bn + bnc;

    float acc[16][4];
#pragma unroll
    for (int i = 0; i < 16; i++)
#pragma unroll
        for (int j = 0; j < 4; j++) acc[i][j] = 0.0f;

    float4 a0 = *(const float4*)Ap0;
    float4 a1 = *(const float4*)Ap1;
    float4 b0 = *(const float4*)Bp0;
    float4 b1 = *(const float4*)Bp1;
    {
        uint4 v;
        v.x = f2tf(a0.x); v.y = f2tf(a0.y); v.z = f2tf(a0.z); v.w = f2tf(a0.w);
        *(uint4*)&As[0][ar0 * LDA + akc] = v;
        v.x = f2tf(a1.x); v.y = f2tf(a1.y); v.z = f2tf(a1.z); v.w = f2tf(a1.w);
        *(uint4*)&As[0][ar1 * LDA + akc] = v;
        v.x = f2tf(b0.x); v.y = f2tf(b0.y); v.z = f2tf(b0.z); v.w = f2tf(b0.w);
        *(uint4*)&Bs[0][bk0 * LDB + bnc] = v;
        v.x = f2tf(b1.x); v.y = f2tf(b1.y); v.z = f2tf(b1.z); v.w = f2tf(b1.w);
        *(uint4*)&Bs[0][bk1 * LDB + bnc] = v;
    }
    __syncthreads();

    const int NT = K / 16;
#pragma unroll 1
    for (int kt = 0; kt < NT; kt++) {
        const int cur = kt & 1;
        const bool more = (kt + 1) < NT;
        if (more) {
            a0 = *(const float4*)(Ap0 + (kt + 1) * 16);
            a1 = *(const float4*)(Ap1 + (kt + 1) * 16);
            b0 = *(const float4*)(Bp0 + (size_t)(kt + 1) * 16 * N);
            b1 = *(const float4*)(Bp1 + (size_t)(kt + 1) * 16 * N);
        }

#pragma unroll
        for (int ks = 0; ks < 2; ks++) {
            uint32_t af[4][4], bf[4][2];
#pragma unroll
            for (int mi = 0; mi < 4; mi++) {
                const int r = wm + mi * 16 + (lane >> 2);
                const int c = ks * 8 + (lane & 3);
                af[mi][0] = As[cur][r * LDA + c];
                af[mi][1] = As[cur][(r + 8) * LDA + c];
                af[mi][2] = As[cur][r * LDA + c + 4];
                af[mi][3] = As[cur][(r + 8) * LDA + c + 4];
            }
#pragma unroll
            for (int ni = 0; ni < 4; ni++) {
                const int n = wn + ni * 8 + (lane >> 2);
                const int k = ks * 8 + (lane & 3);
                bf[ni][0] = Bs[cur][k * LDB + n];
                bf[ni][1] = Bs[cur][(k + 4) * LDB + n];
            }
#pragma unroll
            for (int mi = 0; mi < 4; mi++)
#pragma unroll
                for (int ni = 0; ni < 4; ni++)
                    mma_tf32(acc[mi * 4 + ni], af[mi], bf[ni]);
        }

        if (more) {
            const int nx = (kt + 1) & 1;
            uint4 v;
            v.x = f2tf(a0.x); v.y = f2tf(a0.y); v.z = f2tf(a0.z); v.w = f2tf(a0.w);
            *(uint4*)&As[nx][ar0 * LDA + akc] = v;
            v.x = f2tf(a1.x); v.y = f2tf(a1.y); v.z = f2tf(a1.z); v.w = f2tf(a1.w);
            *(uint4*)&As[nx][ar1 * LDA + akc] = v;
            v.x = f2tf(b0.x); v.y = f2tf(b0.y); v.z = f2tf(b0.z); v.w = f2tf(b0.w);
            *(uint4*)&Bs[nx][bk0 * LDB + bnc] = v;
            v.x = f2tf(b1.x); v.y = f2tf(b1.y); v.z = f2tf(b1.z); v.w = f2tf(b1.w);
            *(uint4*)&Bs[nx][bk1 * LDB + bnc] = v;
        }
        __syncthreads();
    }

#pragma unroll
    for (int mi = 0; mi < 4; mi++) {
        const int r0 = bm + wm + mi * 16 + (lane >> 2);
        const int r1 = r0 + 8;
#pragma unroll
        for (int ni = 0; ni < 4; ni++) {
            const int c0 = bn + wn + ni * 8 + ((lane & 3) << 1);
            const float* a = acc[mi * 4 + ni];
            const float bi0 = bias[c0], bi1 = bias[c0 + 1];
            if (mode == 0) {
                *(float2*)&C[(size_t)r0 * N + c0] = make_float2(a[0] + bi0, a[1] + bi1);
                *(float2*)&C[(size_t)r1 * N + c0] = make_float2(a[2] + bi0, a[3] + bi1);
            } else {
                const int h = c0 >> 6, d = c0 & 63;
                const int b0r = r0 >> 11, s0 = r0 & (S_ - 1);
                const int b1r = r1 >> 11, s1 = r1 & (S_ - 1);
                *(float2*)&C[(((size_t)(b0r * NH + h)) * S_ + s0) * HD + d] =
                    make_float2(tfr(a[0] + bi0), tfr(a[1] + bi1));
                *(float2*)&C[(((size_t)(b1r * NH + h)) * S_ + s1) * HD + d] =
                    make_float2(tfr(a[2] + bi0), tfr(a[3] + bi1));
            }
        }
    }
}

// ---------------------------------------------------------------------------
// RoPE (in-place on Q and K). Outputs rounded to tf32-RNA so flash can
// consume the raw bits losslessly through the tf32 MMA.
// ---------------------------------------------------------------------------
__global__ void rope_kernel(float* __restrict__ Q, float* __restrict__ K,
                            const float* __restrict__ theta)
{
    const int gid  = blockIdx.x * blockDim.x + threadIdx.x;
    const int warp = gid >> 5;
    const int lane = gid & 31;
    const int s = warp & (S_ - 1);

    const float th = theta[lane];
    float sn, cs;
    sincosf((float)s * th, &sn, &cs);

    float* q = Q + (size_t)warp * HD;
    float x1 = q[2 * lane], x2 = q[2 * lane + 1];
    __syncwarp();
    q[lane]      = tfr(x1 * cs - x2 * sn);
    q[lane + 32] = tfr(x1 * sn + x2 * cs);

    float* k = K + (size_t)warp * HD;
    float y1 = k[2 * lane], y2 = k[2 * lane + 1];
    __syncwarp();
    k[lane]      = tfr(y1 * cs - y2 * sn);
    k[lane + 32] = tfr(y1 * sn + y2 * cs);
}

// ---------------------------------------------------------------------------
// TF32 tensor-core causal flash attention, cp.async double-buffered K/V.
// Grid (S/128, B*H), 256 threads = 8 warps; warp w owns q-rows [16w,16w+16).
// K/V arrive in GMEM already tf32-RNA-rounded, so raw cp.async bytes feed
// the tf32 MMA losslessly (HW truncation is a no-op on pre-rounded values).
// ---------------------------------------------------------------------------
#define QLD 68
#define KLD 68
#define VLD 72
#define PLD 68
#define KBUF (64 * KLD)
#define VBUF (64 * VLD)
#define FLASH_SMEM_WORDS (128*QLD + 2*KBUF + 2*VBUF + 128*PLD)

__global__ __launch_bounds__(256, 1) void flash_tf32_kernel(
    const float* __restrict__ Q, const float* __restrict__ K,
    const float* __restrict__ V, float* __restrict__ ctx)
{
    extern __shared__ uint32_t sm[];
    uint32_t* Qs = sm;                   // [128][QLD] tf32 (pre-scaled by 1/8)
    uint32_t* Ks = Qs + 128 * QLD;       // [2][64][KLD]
    uint32_t* Vs = Ks + 2 * KBUF;        // [2][64][VLD]
    uint32_t* Ps = Vs + 2 * VBUF;        // [128][PLD] tf32

    const int qb   = blockIdx.x;
    const int bh   = blockIdx.y;
    const int tid  = threadIdx.x;
    const int lane = tid & 31;
    const int warp = tid >> 5;
    const int g = lane >> 2;
    const int c = lane & 3;
    const int wrow = warp * 16;

    const float* Qg = Q + ((size_t)bh * S_ + qb * 128) * HD;
    const float* Kg = K + (size_t)bh * S_ * HD;
    const float* Vg = V + (size_t)bh * S_ * HD;

    const uint32_t ks_smem = (uint32_t)__cvta_generic_to_shared(Ks);
    const uint32_t vs_smem = (uint32_t)__cvta_generic_to_shared(Vs);

    // per-thread cp.async assignment: 4 rows of 16B chunks for K and V each
    const int lr = tid >> 4;            // 0..15  (row block)
    const int lc = (tid & 15) << 2;     // 0..60  (float col)

    // issue async copy of tile t into buffer b
    auto issue_tile = [&](int t, int b) {
        const float* kg = Kg + (size_t)t * 64 * HD;
        const float* vg = Vg + (size_t)t * 64 * HD;
#pragma unroll
        for (int rr = 0; rr < 4; rr++) {
            const int r = lr + rr * 16;
            cp_async16(ks_smem + (b * KBUF + r * KLD + lc) * 4, kg + r * HD + lc);
            cp_async16(vs_smem + (b * VBUF + r * VLD + lc) * 4, vg + r * HD + lc);
        }
        cp_commit();
    };

    issue_tile(0, 0);

    // load Q tile: fold softmax scale (x0.125 exact in tf32), convert
    for (int i = tid; i < 2048; i += 256) {
        const int r = i >> 4, c4 = (i & 15) << 2;
        float4 v = ((const float4*)Qg)[i];
        Qs[r * QLD + c4 + 0] = f2tf(v.x * 0.125f);
        Qs[r * QLD + c4 + 1] = f2tf(v.y * 0.125f);
        Qs[r * QLD + c4 + 2] = f2tf(v.z * 0.125f);
        Qs[r * QLD + c4 + 3] = f2tf(v.w * 0.125f);
    }

    float oacc[8][4];
#pragma unroll
    for (int nt = 0; nt < 8; nt++)
#pragma unroll
        for (int k = 0; k < 4; k++) oacc[nt][k] = 0.0f;
    float m0 = -3.0e38f, m1 = -3.0e38f, l0 = 0.0f, l1 = 0.0f;

    const int jmax = 2 * qb + 1;
    int buf = 0;
    for (int j = 0; j <= jmax; j++) {
        if (j < jmax) {
            issue_tile(j + 1, buf ^ 1);
            asm volatile("cp.async.wait_group 1;");
        } else {
            asm volatile("cp.async.wait_group 0;");
        }
        __syncthreads();   // tile j visible to all; also covers Qs init (j=0)

        const uint32_t* Kb = Ks + buf * KBUF;
        const uint32_t* Vb = Vs + buf * VBUF;

        // ---- S = Qs @ K^T
        float sacc[8][4];
#pragma unroll
        for (int nt = 0; nt < 8; nt++)
#pragma unroll
            for (int k = 0; k < 4; k++) sacc[nt][k] = 0.0f;

#pragma unroll
        for (int ks = 0; ks < 8; ks++) {
            uint32_t af[4];
            af[0] = Qs[(wrow + g)     * QLD + ks * 8 + c];
            af[1] = Qs[(wrow + g + 8) * QLD + ks * 8 + c];
            af[2] = Qs[(wrow + g)     * QLD + ks * 8 + c + 4];
            af[3] = Qs[(wrow + g + 8) * QLD + ks * 8 + c + 4];
#pragma unroll
            for (int nt = 0; nt < 8; nt++) {
                uint32_t bf[2];
                bf[0] = Kb[(nt * 8 + g) * KLD + ks * 8 + c];
                bf[1] = Kb[(nt * 8 + g) * KLD + ks * 8 + c + 4];
                mma_tf32(sacc[nt], af, bf);
            }
        }

        // ---- causal mask (diagonal tiles only)
        if (j >= 2 * qb) {
            const int r0 = qb * 128 + wrow + g;
            const int r1 = r0 + 8;
#pragma unroll
            for (int nt = 0; nt < 8; nt++) {
                const int col = j * 64 + nt * 8 + 2 * c;
                if (col     > r0) sacc[nt][0] = -3.0e38f;
                if (col + 1 > r0) sacc[nt][1] = -3.0e38f;
                if (col     > r1) sacc[nt][2] = -3.0e38f;
                if (col + 1 > r1) sacc[nt][3] = -3.0e38f;
            }
        }

        // ---- online softmax on fragments
        float rmax0 = -3.0e38f, rmax1 = -3.0e38f;
#pragma unroll
        for (int nt = 0; nt < 8; nt++) {
            rmax0 = fmaxf(rmax0, fmaxf(sacc[nt][0], sacc[nt][1]));
            rmax1 = fmaxf(rmax1, fmaxf(sacc[nt][2], sacc[nt][3]));
        }
#pragma unroll
        for (int off = 1; off < 4; off <<= 1) {
            rmax0 = fmaxf(rmax0, __shfl_xor_sync(0xffffffffu, rmax0, off));
            rmax1 = fmaxf(rmax1, __shfl_xor_sync(0xffffffffu, rmax1, off));
        }

        const float mn0 = fmaxf(m0, rmax0);
        const float mn1 = fmaxf(m1, rmax1);
        const float al0 = __expf(m0 - mn0);
        const float al1 = __expf(m1 - mn1);

        float rsum0 = 0.0f, rsum1 = 0.0f;
        __syncwarp();   // prior PV reads of Ps complete before overwrite
#pragma unroll
        for (int nt = 0; nt < 8; nt++) {
            const float p0 = __expf(sacc[nt][0] - mn0);
            const float p1 = __expf(sacc[nt][1] - mn0);
            const float p2 = __expf(sacc[nt][2] - mn1);
            const float p3 = __expf(sacc[nt][3] - mn1);
            rsum0 += p0 + p1;
            rsum1 += p2 + p3;
            *(uint2*)&Ps[(wrow + g)     * PLD + nt * 8 + 2 * c] =
                make_uint2(f2tf(p0), f2tf(p1));
            *(uint2*)&Ps[(wrow + g + 8) * PLD + nt * 8 + 2 * c] =
                make_uint2(f2tf(p2), f2tf(p3));
        }
#pragma unroll
        for (int off = 1; off < 4; off <<= 1) {
            rsum0 += __shfl_xor_sync(0xffffffffu, rsum0, off);
            rsum1 += __shfl_xor_sync(0xffffffffu, rsum1, off);
        }
        l0 = l0 * al0 + rsum0;
        l1 = l1 * al1 + rsum1;
        m0 = mn0;
        m1 = mn1;
#pragma unroll
        for (int nt = 0; nt < 8; nt++) {
            oacc[nt][0] *= al0;
            oacc[nt][1] *= al0;
            oacc[nt][2] *= al1;
            oacc[nt][3] *= al1;
        }
        __syncwarp();   // Ps writes visible to whole warp

        // ---- O += P @ V
#pragma unroll
        for (int ks = 0; ks < 8; ks++) {
            uint32_t af[4];
            af[0] = Ps[(wrow + g)     * PLD + ks * 8 + c];
            af[1] = Ps[(wrow + g + 8) * PLD + ks * 8 + c];
            af[2] = Ps[(wrow + g)     * PLD + ks * 8 + c + 4];
            af[3] = Ps[(wrow + g + 8) * PLD + ks * 8 + c + 4];
#pragma unroll
            for (int nt = 0; nt < 8; nt++) {
                uint32_t bf[2];
                bf[0] = Vb[(ks * 8 + c)     * VLD + nt * 8 + g];
                bf[1] = Vb[(ks * 8 + c + 4) * VLD + nt * 8 + g];
                mma_tf32(oacc[nt], af, bf);
            }
        }

        __syncthreads();   // all warps done with buf before it is re-issued
        buf ^= 1;
    }

    // ---- write ctx [B*S, H*hd]
    const int b = bh >> 4, h = bh & 15;
    const int r0 = qb * 128 + wrow + g;
    const int r1 = r0 + 8;
    const float inv0 = 1.0f / l0;
    const float inv1 = 1.0f / l1;
#pragma unroll
    for (int nt = 0; nt < 8; nt++) {
        const int col = h * 64 + nt * 8 + 2 * c;
        *(float2*)&ctx[(size_t)(b * S_ + r0) * DIM + col] =
            make_float2(oacc[nt][0] * inv0, oacc[nt][1] * inv0);
        *(float2*)&ctx[(size_t)(b * S_ + r1) * DIM + col] =
            make_float2(oacc[nt][2] * inv1, oacc[nt][3] * inv1);
    }
}

// ---------------------------------------------------------------------------
extern "C" void kernel_launch(void* const* d_in, const int* in_sizes, int n_in,
                              void* d_out, int out_size)
{
    const float* x     = (const float*)d_in[0];
    const float* theta = (const float*)d_in[2];
    const float* Wq    = (const float*)d_in[3];
    const float* bq    = (const float*)d_in[4];
    const float* Wk    = (const float*)d_in[5];
    const float* bk    = (const float*)d_in[6];
    const float* Wv    = (const float*)d_in[7];
    const float* bv    = (const float*)d_in[8];
    const float* Wo    = (const float*)d_in[9];
    const float* bo    = (const float*)d_in[10];
    float* out = (float*)d_out;

    float *Qb, *Kb, *Vb, *Cb;
    cudaGetSymbolAddress((void**)&Qb, g_Q);
    cudaGetSymbolAddress((void**)&Kb, g_K);
    cudaGetSymbolAddress((void**)&Vb, g_V);
    cudaGetSymbolAddress((void**)&Cb, g_C);

    const dim3 gemmGrid(DIM / 128, MROWS / 128);

    tf32_gemm_kernel<<<gemmGrid, 256>>>(x, Wq, bq, Qb, MROWS, DIM, DIM, 1);
    tf32_gemm_kernel<<<gemmGrid, 256>>>(x, Wk, bk, Kb, MROWS, DIM, DIM, 1);
    tf32_gemm_kernel<<<gemmGrid, 256>>>(x, Wv, bv, Vb, MROWS, DIM, DIM, 1);

    rope_kernel<<<(B_ * NH * S_ * 32) / 256, 256>>>(Qb, Kb, theta);

    const int flashSmem = FLASH_SMEM_WORDS * (int)sizeof(uint32_t);  // ~138 KB
    cudaFuncSetAttribute(flash_tf32_kernel,
                         cudaFuncAttributeMaxDynamicSharedMemorySize, flashSmem);
    flash_tf32_kernel<<<dim3(S_ / 128, B_ * NH), 256, flashSmem>>>(Qb, Kb, Vb, Cb);

    tf32_gemm_kernel<<<gemmGrid, 256>>>(Cb, Wo, bo, out, MROWS, DIM, DIM, 0);
}

// round 9
// speedup vs baseline: 3.5926x; 1.2260x over previous
#include <cuda_runtime.h>
#include <math.h>
#include <stdint.h>

#define DIM   1024
#define NH    16
#define HD    64
#define B_    2
#define S_    2048
#define MROWS (B_ * S_)   // 4096

// Scratch (allocation-free rule: __device__ globals)
__device__ float g_Q[B_ * NH * S_ * HD];   // [B,H,S,hd]
__device__ float g_K[B_ * NH * S_ * HD];
__device__ float g_V[B_ * NH * S_ * HD];
__device__ float g_C[MROWS * DIM];         // attention context, [B*S, H*hd]

// ---------------------------------------------------------------------------
// TF32 / async helpers
// ---------------------------------------------------------------------------
__device__ __forceinline__ uint32_t f2tf(float f) {
    uint32_t r;
    asm("cvt.rna.tf32.f32 %0, %1;" : "=r"(r) : "f"(f));
    return r;
}
__device__ __forceinline__ float tfr(float f) { return __uint_as_float(f2tf(f)); }

__device__ __forceinline__ void mma_tf32(float* d, const uint32_t* a, const uint32_t* b) {
    asm volatile(
        "mma.sync.aligned.m16n8k8.row.col.f32.tf32.tf32.f32 "
        "{%0,%1,%2,%3}, {%4,%5,%6,%7}, {%8,%9}, {%0,%1,%2,%3};"
        : "+f"(d[0]), "+f"(d[1]), "+f"(d[2]), "+f"(d[3])
        : "r"(a[0]), "r"(a[1]), "r"(a[2]), "r"(a[3]),
          "r"(b[0]), "r"(b[1]));
}

__device__ __forceinline__ void cp_async16(uint32_t smem_byte_addr, const void* gptr) {
    asm volatile("cp.async.cg.shared.global [%0], [%1], 16;"
                 :: "r"(smem_byte_addr), "l"(gptr));
}
__device__ __forceinline__ void cp_commit() {
    asm volatile("cp.async.commit_group;");
}

// ---------------------------------------------------------------------------
// TF32 tensor-core GEMM: C[M,N] = A[M,K] @ W[K,N] + bias
// mode 0: C row-major [M,N]
// mode 1: scatter to [B,H,S,hd], tf32-RNA-rounded values
// ---------------------------------------------------------------------------
#define LDA 20
#define LDB 136

__global__ __launch_bounds__(256, 2) void tf32_gemm_kernel(
    const float* __restrict__ A, const float* __restrict__ W,
    const float* __restrict__ bias, float* __restrict__ C,
    int M, int N, int K, int mode)
{
    __shared__ uint32_t As[2][128 * LDA];   // [row][k] tf32
    __shared__ uint32_t Bs[2][16 * LDB];    // [k][n]   tf32

    const int tid  = threadIdx.x;
    const int lane = tid & 31;
    const int warp = tid >> 5;
    const int bm = blockIdx.y * 128;
    const int bn = blockIdx.x * 128;
    const int wm = (warp & 1) << 6;
    const int wn = (warp >> 1) << 5;

    const int ar0 = tid >> 2;
    const int ar1 = (tid + 256) >> 2;
    const int akc = (tid & 3) << 2;
    const int bk0 = tid >> 5;
    const int bk1 = (tid + 256) >> 5;
    const int bnc = (tid & 31) << 2;

    const float* Ap0 = A + (size_t)(bm + ar0) * K + akc;
    const float* Ap1 = A + (size_t)(bm + ar1) * K + akc;
    const float* Bp0 = W + (size_t)bk0 * N + bn + bnc;
    const float* Bp1 = W + (size_t)bk1 * N + bn + bnc;

    float acc[16][4];
#pragma unroll
    for (int i = 0; i < 16; i++)
#pragma unroll
        for (int j = 0; j < 4; j++) acc[i][j] = 0.0f;

    float4 a0 = *(const float4*)Ap0;
    float4 a1 = *(const float4*)Ap1;
    float4 b0 = *(const float4*)Bp0;
    float4 b1 = *(const float4*)Bp1;
    {
        uint4 v;
        v.x = f2tf(a0.x); v.y = f2tf(a0.y); v.z = f2tf(a0.z); v.w = f2tf(a0.w);
        *(uint4*)&As[0][ar0 * LDA + akc] = v;
        v.x = f2tf(a1.x); v.y = f2tf(a1.y); v.z = f2tf(a1.z); v.w = f2tf(a1.w);
        *(uint4*)&As[0][ar1 * LDA + akc] = v;
        v.x = f2tf(b0.x); v.y = f2tf(b0.y); v.z = f2tf(b0.z); v.w = f2tf(b0.w);
        *(uint4*)&Bs[0][bk0 * LDB + bnc] = v;
        v.x = f2tf(b1.x); v.y = f2tf(b1.y); v.z = f2tf(b1.z); v.w = f2tf(b1.w);
        *(uint4*)&Bs[0][bk1 * LDB + bnc] = v;
    }
    __syncthreads();

    const int NT = K / 16;
#pragma unroll 1
    for (int kt = 0; kt < NT; kt++) {
        const int cur = kt & 1;
        const bool more = (kt + 1) < NT;
        if (more) {
            a0 = *(const float4*)(Ap0 + (kt + 1) * 16);
            a1 = *(const float4*)(Ap1 + (kt + 1) * 16);
            b0 = *(const float4*)(Bp0 + (size_t)(kt + 1) * 16 * N);
            b1 = *(const float4*)(Bp1 + (size_t)(kt + 1) * 16 * N);
        }

#pragma unroll
        for (int ks = 0; ks < 2; ks++) {
            uint32_t af[4][4], bf[4][2];
#pragma unroll
            for (int mi = 0; mi < 4; mi++) {
                const int r = wm + mi * 16 + (lane >> 2);
                const int c = ks * 8 + (lane & 3);
                af[mi][0] = As[cur][r * LDA + c];
                af[mi][1] = As[cur][(r + 8) * LDA + c];
                af[mi][2] = As[cur][r * LDA + c + 4];
                af[mi][3] = As[cur][(r + 8) * LDA + c + 4];
            }
#pragma unroll
            for (int ni = 0; ni < 4; ni++) {
                const int n = wn + ni * 8 + (lane >> 2);
                const int k = ks * 8 + (lane & 3);
                bf[ni][0] = Bs[cur][k * LDB + n];
                bf[ni][1] = Bs[cur][(k + 4) * LDB + n];
            }
#pragma unroll
            for (int mi = 0; mi < 4; mi++)
#pragma unroll
                for (int ni = 0; ni < 4; ni++)
                    mma_tf32(acc[mi * 4 + ni], af[mi], bf[ni]);
        }

        if (more) {
            const int nx = (kt + 1) & 1;
            uint4 v;
            v.x = f2tf(a0.x); v.y = f2tf(a0.y); v.z = f2tf(a0.z); v.w = f2tf(a0.w);
            *(uint4*)&As[nx][ar0 * LDA + akc] = v;
            v.x = f2tf(a1.x); v.y = f2tf(a1.y); v.z = f2tf(a1.z); v.w = f2tf(a1.w);
            *(uint4*)&As[nx][ar1 * LDA + akc] = v;
            v.x = f2tf(b0.x); v.y = f2tf(b0.y); v.z = f2tf(b0.z); v.w = f2tf(b0.w);
            *(uint4*)&Bs[nx][bk0 * LDB + bnc] = v;
            v.x = f2tf(b1.x); v.y = f2tf(b1.y); v.z = f2tf(b1.z); v.w = f2tf(b1.w);
            *(uint4*)&Bs[nx][bk1 * LDB + bnc] = v;
        }
        __syncthreads();
    }

#pragma unroll
    for (int mi = 0; mi < 4; mi++) {
        const int r0 = bm + wm + mi * 16 + (lane >> 2);
        const int r1 = r0 + 8;
#pragma unroll
        for (int ni = 0; ni < 4; ni++) {
            const int c0 = bn + wn + ni * 8 + ((lane & 3) << 1);
            const float* a = acc[mi * 4 + ni];
            const float bi0 = bias[c0], bi1 = bias[c0 + 1];
            if (mode == 0) {
                *(float2*)&C[(size_t)r0 * N + c0] = make_float2(a[0] + bi0, a[1] + bi1);
                *(float2*)&C[(size_t)r1 * N + c0] = make_float2(a[2] + bi0, a[3] + bi1);
            } else {
                const int h = c0 >> 6, d = c0 & 63;
                const int b0r = r0 >> 11, s0 = r0 & (S_ - 1);
                const int b1r = r1 >> 11, s1 = r1 & (S_ - 1);
                *(float2*)&C[(((size_t)(b0r * NH + h)) * S_ + s0) * HD + d] =
                    make_float2(tfr(a[0] + bi0), tfr(a[1] + bi1));
                *(float2*)&C[(((size_t)(b1r * NH + h)) * S_ + s1) * HD + d] =
                    make_float2(tfr(a[2] + bi0), tfr(a[3] + bi1));
            }
        }
    }
}

// ---------------------------------------------------------------------------
// RoPE (in-place on Q and K), tf32-RNA-rounded outputs.
// ---------------------------------------------------------------------------
__global__ void rope_kernel(float* __restrict__ Q, float* __restrict__ K,
                            const float* __restrict__ theta)
{
    const int gid  = blockIdx.x * blockDim.x + threadIdx.x;
    const int warp = gid >> 5;
    const int lane = gid & 31;
    const int s = warp & (S_ - 1);

    const float th = theta[lane];
    float sn, cs;
    sincosf((float)s * th, &sn, &cs);

    float* q = Q + (size_t)warp * HD;
    float x1 = q[2 * lane], x2 = q[2 * lane + 1];
    __syncwarp();
    q[lane]      = tfr(x1 * cs - x2 * sn);
    q[lane + 32] = tfr(x1 * sn + x2 * cs);

    float* k = K + (size_t)warp * HD;
    float y1 = k[2 * lane], y2 = k[2 * lane + 1];
    __syncwarp();
    k[lane]      = tfr(y1 * cs - y2 * sn);
    k[lane + 32] = tfr(y1 * sn + y2 * cs);
}

// ---------------------------------------------------------------------------
// TF32 flash attention v3: Q fragments hoisted to registers (Q smem aliased
// with Ps), 2 CTAs/SM, per-warp dead-chunk skipping on diagonal tiles,
// heavy-blocks-first scheduling. cp.async double-buffered K/V.
// ---------------------------------------------------------------------------
#define KLD 68
#define VLD 72
#define PLD 68
#define KBUF (64 * KLD)
#define VBUF (64 * VLD)
#define FLASH_SMEM_WORDS (2*KBUF + 2*VBUF + 128*PLD)   // 26624 w = 106.5 KB

__global__ __launch_bounds__(256, 2) void flash_tf32_kernel(
    const float* __restrict__ Q, const float* __restrict__ K,
    const float* __restrict__ V, float* __restrict__ ctx)
{
    extern __shared__ uint32_t sm[];
    uint32_t* Ks = sm;                   // [2][64][KLD]
    uint32_t* Vs = Ks + 2 * KBUF;        // [2][64][VLD]
    uint32_t* Ps = Vs + 2 * VBUF;        // [128][PLD]; also Q staging at init

    const int bid  = blockIdx.x;
    const int qb   = 15 - (bid >> 5);    // heavy q-tiles first (LPT-ish)
    const int bh   = bid & 31;
    const int tid  = threadIdx.x;
    const int lane = tid & 31;
    const int warp = tid >> 5;
    const int g = lane >> 2;
    const int c = lane & 3;
    const int wrow = warp * 16;

    const float* Qg = Q + ((size_t)bh * S_ + qb * 128) * HD;
    const float* Kg = K + (size_t)bh * S_ * HD;
    const float* Vg = V + (size_t)bh * S_ * HD;

    const uint32_t ks_smem = (uint32_t)__cvta_generic_to_shared(Ks);
    const uint32_t vs_smem = (uint32_t)__cvta_generic_to_shared(Vs);

    const int lr = tid >> 4;            // 0..15
    const int lc = (tid & 15) << 2;     // 0..60

    auto issue_tile = [&](int t, int b) {
        const float* kg = Kg + (size_t)t * 64 * HD;
        const float* vg = Vg + (size_t)t * 64 * HD;
#pragma unroll
        for (int rr = 0; rr < 4; rr++) {
            const int r = lr + rr * 16;
            cp_async16(ks_smem + (b * KBUF + r * KLD + lc) * 4, kg + r * HD + lc);
            cp_async16(vs_smem + (b * VBUF + r * VLD + lc) * 4, vg + r * HD + lc);
        }
        cp_commit();
    };

    issue_tile(0, 0);

    // stage Q (scaled, tf32) into Ps region, then hoist this warp's fragments
    for (int i = tid; i < 2048; i += 256) {
        const int r = i >> 4, c4 = (i & 15) << 2;
        float4 v = ((const float4*)Qg)[i];
        Ps[r * PLD + c4 + 0] = f2tf(v.x * 0.125f);
        Ps[r * PLD + c4 + 1] = f2tf(v.y * 0.125f);
        Ps[r * PLD + c4 + 2] = f2tf(v.z * 0.125f);
        Ps[r * PLD + c4 + 3] = f2tf(v.w * 0.125f);
    }
    __syncthreads();

    uint32_t qf[8][4];
#pragma unroll
    for (int ks = 0; ks < 8; ks++) {
        qf[ks][0] = Ps[(wrow + g)     * PLD + ks * 8 + c];
        qf[ks][1] = Ps[(wrow + g + 8) * PLD + ks * 8 + c];
        qf[ks][2] = Ps[(wrow + g)     * PLD + ks * 8 + c + 4];
        qf[ks][3] = Ps[(wrow + g + 8) * PLD + ks * 8 + c + 4];
    }
    // loop-top __syncthreads() orders these reads before any Ps overwrite

    float oacc[8][4];
#pragma unroll
    for (int nt = 0; nt < 8; nt++)
#pragma unroll
        for (int k = 0; k < 4; k++) oacc[nt][k] = 0.0f;
    float m0 = -3.0e38f, m1 = -3.0e38f, l0 = 0.0f, l1 = 0.0f;

    const int jmax = 2 * qb + 1;
    int buf = 0;
    for (int j = 0; j <= jmax; j++) {
        if (j < jmax) {
            issue_tile(j + 1, buf ^ 1);
            asm volatile("cp.async.wait_group 1;");
        } else {
            asm volatile("cp.async.wait_group 0;");
        }
        __syncthreads();

        const uint32_t* Kb = Ks + buf * KBUF;
        const uint32_t* Vb = Vs + buf * VBUF;

        // per-warp live key-chunk count (uniform across warp, no divergence)
        int ntlim = 8;
        const bool diag = (j >= 2 * qb);
        if (diag) {
            const int t = j - 2 * qb;
            const int lim = ((wrow + 15 - 64 * t) >> 3) + 1;
            ntlim = lim < 0 ? 0 : (lim > 8 ? 8 : lim);
        }

        if (ntlim > 0) {
            // ---- S = Q @ K^T (key chunks < ntlim)
            float sacc[8][4];
#pragma unroll
            for (int nt = 0; nt < 8; nt++)
#pragma unroll
                for (int k = 0; k < 4; k++) sacc[nt][k] = 0.0f;

            for (int nt = 0; nt < ntlim; nt++) {
#pragma unroll
                for (int ks = 0; ks < 8; ks++) {
                    uint32_t bf[2];
                    bf[0] = Kb[(nt * 8 + g) * KLD + ks * 8 + c];
                    bf[1] = Kb[(nt * 8 + g) * KLD + ks * 8 + c + 4];
                    mma_tf32(sacc[nt], qf[ks], bf);
                }
            }

            // ---- boundary masking on diagonal tiles
            if (diag) {
                const int r0 = qb * 128 + wrow + g;
                const int r1 = r0 + 8;
                for (int nt = 0; nt < ntlim; nt++) {
                    const int col = j * 64 + nt * 8 + 2 * c;
                    if (col     > r0) sacc[nt][0] = -3.0e38f;
                    if (col + 1 > r0) sacc[nt][1] = -3.0e38f;
                    if (col     > r1) sacc[nt][2] = -3.0e38f;
                    if (col + 1 > r1) sacc[nt][3] = -3.0e38f;
                }
            }

            // ---- online softmax
            float rmax0 = -3.0e38f, rmax1 = -3.0e38f;
            for (int nt = 0; nt < ntlim; nt++) {
                rmax0 = fmaxf(rmax0, fmaxf(sacc[nt][0], sacc[nt][1]));
                rmax1 = fmaxf(rmax1, fmaxf(sacc[nt][2], sacc[nt][3]));
            }
#pragma unroll
            for (int off = 1; off < 4; off <<= 1) {
                rmax0 = fmaxf(rmax0, __shfl_xor_sync(0xffffffffu, rmax0, off));
                rmax1 = fmaxf(rmax1, __shfl_xor_sync(0xffffffffu, rmax1, off));
            }

            const float mn0 = fmaxf(m0, rmax0);
            const float mn1 = fmaxf(m1, rmax1);
            const float al0 = __expf(m0 - mn0);
            const float al1 = __expf(m1 - mn1);

            float rsum0 = 0.0f, rsum1 = 0.0f;
            __syncwarp();   // prior PV reads of Ps done before overwrite
            for (int nt = 0; nt < ntlim; nt++) {
                const float p0 = __expf(sacc[nt][0] - mn0);
                const float p1 = __expf(sacc[nt][1] - mn0);
                const float p2 = __expf(sacc[nt][2] - mn1);
                const float p3 = __expf(sacc[nt][3] - mn1);
                rsum0 += p0 + p1;
                rsum1 += p2 + p3;
                *(uint2*)&Ps[(wrow + g)     * PLD + nt * 8 + 2 * c] =
                    make_uint2(f2tf(p0), f2tf(p1));
                *(uint2*)&Ps[(wrow + g + 8) * PLD + nt * 8 + 2 * c] =
                    make_uint2(f2tf(p2), f2tf(p3));
            }
#pragma unroll
            for (int off = 1; off < 4; off <<= 1) {
                rsum0 += __shfl_xor_sync(0xffffffffu, rsum0, off);
                rsum1 += __shfl_xor_sync(0xffffffffu, rsum1, off);
            }
            l0 = l0 * al0 + rsum0;
            l1 = l1 * al1 + rsum1;
            m0 = mn0;
            m1 = mn1;
#pragma unroll
            for (int nt = 0; nt < 8; nt++) {
                oacc[nt][0] *= al0;
                oacc[nt][1] *= al0;
                oacc[nt][2] *= al1;
                oacc[nt][3] *= al1;
            }
            __syncwarp();   // Ps writes visible warp-wide

            // ---- O += P @ V (key chunks < ntlim; all 8 hd chunks)
            for (int ks = 0; ks < ntlim; ks++) {
                uint32_t af[4];
                af[0] = Ps[(wrow + g)     * PLD + ks * 8 + c];
                af[1] = Ps[(wrow + g + 8) * PLD + ks * 8 + c];
                af[2] = Ps[(wrow + g)     * PLD + ks * 8 + c + 4];
                af[3] = Ps[(wrow + g + 8) * PLD + ks * 8 + c + 4];
#pragma unroll
                for (int nt = 0; nt < 8; nt++) {
                    uint32_t bf[2];
                    bf[0] = Vb[(ks * 8 + c)     * VLD + nt * 8 + g];
                    bf[1] = Vb[(ks * 8 + c + 4) * VLD + nt * 8 + g];
                    mma_tf32(oacc[nt], af, bf);
                }
            }
        }

        __syncthreads();   // all warps done with buf before re-issue
        buf ^= 1;
    }

    // ---- write ctx [B*S, H*hd]
    const int b = bh >> 4, h = bh & 15;
    const int r0 = qb * 128 + wrow + g;
    const int r1 = r0 + 8;
    const float inv0 = 1.0f / l0;
    const float inv1 = 1.0f / l1;
#pragma unroll
    for (int nt = 0; nt < 8; nt++) {
        const int col = h * 64 + nt * 8 + 2 * c;
        *(float2*)&ctx[(size_t)(b * S_ + r0) * DIM + col] =
            make_float2(oacc[nt][0] * inv0, oacc[nt][1] * inv0);
        *(float2*)&ctx[(size_t)(b * S_ + r1) * DIM + col] =
            make_float2(oacc[nt][2] * inv1, oacc[nt][3] * inv1);
    }
}

// ---------------------------------------------------------------------------
extern "C" void kernel_launch(void* const* d_in, const int* in_sizes, int n_in,
                              void* d_out, int out_size)
{
    const float* x     = (const float*)d_in[0];
    const float* theta = (const float*)d_in[2];
    const float* Wq    = (const float*)d_in[3];
    const float* bq    = (const float*)d_in[4];
    const float* Wk    = (const float*)d_in[5];
    const float* bk    = (const float*)d_in[6];
    const float* Wv    = (const float*)d_in[7];
    const float* bv    = (const float*)d_in[8];
    const float* Wo    = (const float*)d_in[9];
    const float* bo    = (const float*)d_in[10];
    float* out = (float*)d_out;

    float *Qb, *Kb, *Vb, *Cb;
    cudaGetSymbolAddress((void**)&Qb, g_Q);
    cudaGetSymbolAddress((void**)&Kb, g_K);
    cudaGetSymbolAddress((void**)&Vb, g_V);
    cudaGetSymbolAddress((void**)&Cb, g_C);

    const dim3 gemmGrid(DIM / 128, MROWS / 128);

    tf32_gemm_kernel<<<gemmGrid, 256>>>(x, Wq, bq, Qb, MROWS, DIM, DIM, 1);
    tf32_gemm_kernel<<<gemmGrid, 256>>>(x, Wk, bk, Kb, MROWS, DIM, DIM, 1);
    tf32_gemm_kernel<<<gemmGrid, 256>>>(x, Wv, bv, Vb, MROWS, DIM, DIM, 1);

    rope_kernel<<<(B_ * NH * S_ * 32) / 256, 256>>>(Qb, Kb, theta);

    const int flashSmem = FLASH_SMEM_WORDS * (int)sizeof(uint32_t);  // 106.5 KB
    cudaFuncSetAttribute(flash_tf32_kernel,
                         cudaFuncAttributeMaxDynamicSharedMemorySize, flashSmem);
    flash_tf32_kernel<<<16 * 32, 256, flashSmem>>>(Qb, Kb, Vb, Cb);

    tf32_gemm_kernel<<<gemmGrid, 256>>>(Cb, Wo, bo, out, MROWS, DIM, DIM, 0);
}

// round 10
// speedup vs baseline: 3.8054x; 1.0592x over previous
#include <cuda_runtime.h>
#include <math.h>
#include <stdint.h>

#define DIM   1024
#define NH    16
#define HD    64
#define B_    2
#define S_    2048
#define MROWS (B_ * S_)   // 4096

// Scratch (allocation-free rule: __device__ globals)
__device__ float g_Q[B_ * NH * S_ * HD];   // [B,H,S,hd]
__device__ float g_K[B_ * NH * S_ * HD];
__device__ float g_V[B_ * NH * S_ * HD];
__device__ float g_C[MROWS * DIM];         // attention context, [B*S, H*hd] (tf32-rounded)
__device__ float g_Xr[MROWS * DIM];        // x, tf32-RNA-rounded
__device__ float g_Wr[4 * DIM * DIM];      // Wq|Wk|Wv|Wo, tf32-RNA-rounded

// ---------------------------------------------------------------------------
// TF32 / async helpers
// ---------------------------------------------------------------------------
__device__ __forceinline__ uint32_t f2tf(float f) {
    uint32_t r;
    asm("cvt.rna.tf32.f32 %0, %1;" : "=r"(r) : "f"(f));
    return r;
}
__device__ __forceinline__ float tfr(float f) { return __uint_as_float(f2tf(f)); }

__device__ __forceinline__ void mma_tf32(float* d, const uint32_t* a, const uint32_t* b) {
    asm volatile(
        "mma.sync.aligned.m16n8k8.row.col.f32.tf32.tf32.f32 "
        "{%0,%1,%2,%3}, {%4,%5,%6,%7}, {%8,%9}, {%0,%1,%2,%3};"
        : "+f"(d[0]), "+f"(d[1]), "+f"(d[2]), "+f"(d[3])
        : "r"(a[0]), "r"(a[1]), "r"(a[2]), "r"(a[3]),
          "r"(b[0]), "r"(b[1]));
}

__device__ __forceinline__ void cp_async16(uint32_t smem_byte_addr, const void* gptr) {
    asm volatile("cp.async.cg.shared.global [%0], [%1], 16;"
                 :: "r"(smem_byte_addr), "l"(gptr));
}
__device__ __forceinline__ void cp_commit() {
    asm volatile("cp.async.commit_group;");
}
__device__ __forceinline__ void cp_wait0() {
    asm volatile("cp.async.wait_group 0;");
}

// ---------------------------------------------------------------------------
// Pre-round x and the four weight matrices to tf32-RNA (one float4/thread).
// After this, every GEMM input in GMEM is exact tf32: cp.async raw bytes feed
// the MMA losslessly (HW RZ truncation is a no-op on pre-rounded values).
// ---------------------------------------------------------------------------
#define X4 (MROWS * DIM / 4)   // 1048576
#define W4 (DIM * DIM / 4)     // 262144

__global__ void round_tf32_kernel(
    const float* __restrict__ x,
    const float* __restrict__ wq, const float* __restrict__ wk,
    const float* __restrict__ wv, const float* __restrict__ wo,
    float* __restrict__ xr, float* __restrict__ wr)
{
    const int gid = blockIdx.x * blockDim.x + threadIdx.x;
    const float4* src;
    float4* dst;
    int idx;
    if (gid < X4) {
        src = (const float4*)x;  dst = (float4*)xr;  idx = gid;
    } else {
        const int t = gid - X4;
        const int w = t >> 18;          // / W4
        idx = t & (W4 - 1);
        src = (const float4*)(w == 0 ? wq : w == 1 ? wk : w == 2 ? wv : wo);
        dst = (float4*)(wr + (size_t)w * DIM * DIM);
    }
    float4 v = src[idx];
    v.x = tfr(v.x); v.y = tfr(v.y); v.z = tfr(v.z); v.w = tfr(v.w);
    dst[idx] = v;
}

// ---------------------------------------------------------------------------
// TF32 GEMM over pre-rounded inputs, cp.async double-buffered, 1 barrier/tile.
// QKV=1: fused N=3072 (per-CTA weight select), scatter to [B,H,S,hd], tfr out.
// QKV=0: N=1024, row-major out + bias (harness output, fp32).
// A stride = W row stride = DIM. Block 128x128x16, 8 warps, m16n8k8.
// ---------------------------------------------------------------------------
#define LDA 20
#define LDB 136

template<int QKV>
__global__ __launch_bounds__(256, 2) void gemm_tf32_kernel(
    const float* __restrict__ A, const float* __restrict__ Wall,
    const float* __restrict__ b0, const float* __restrict__ b1,
    const float* __restrict__ b2,
    float* __restrict__ O0, float* __restrict__ O1, float* __restrict__ O2)
{
    __shared__ uint32_t As[2][128 * LDA];
    __shared__ uint32_t Bs[2][16 * LDB];

    const int tid  = threadIdx.x;
    const int lane = tid & 31;
    const int warp = tid >> 5;
    const int bm  = blockIdx.y * 128;
    const int bnG = blockIdx.x * 128;
    const int wsel = bnG >> 10;          // which weight (0 for QKV=0)
    const int bn   = bnG & 1023;         // column within that weight
    const int wm = (warp & 1) << 6;
    const int wn = (warp >> 1) << 5;

    const float* W    = Wall + (size_t)wsel * DIM * DIM;
    const float* bias = QKV ? (wsel == 0 ? b0 : (wsel == 1 ? b1 : b2)) : b0;
    float* Osel = QKV ? (wsel == 0 ? O0 : (wsel == 1 ? O1 : O2)) : O0;

    const int ar0 = tid >> 2;            // A rows 0..63 (+64 for second)
    const int akc = (tid & 3) << 2;      // k offset
    const int bk0 = tid >> 5;            // B k-rows 0..7 (+8 for second)
    const int bnc = (tid & 31) << 2;     // n offset

    const float* Ap = A + (size_t)(bm + ar0) * DIM + akc;
    const float* Bp = W + (size_t)bk0 * DIM + bn + bnc;

    const uint32_t as_b = (uint32_t)__cvta_generic_to_shared(As);
    const uint32_t bs_b = (uint32_t)__cvta_generic_to_shared(Bs);

    auto issue = [&](int kt, int bf) {
        const float* a = Ap + kt * 16;
        cp_async16(as_b + (bf * 128 * LDA + ar0 * LDA + akc) * 4, a);
        cp_async16(as_b + (bf * 128 * LDA + (ar0 + 64) * LDA + akc) * 4, a + (size_t)64 * DIM);
        const float* b = Bp + (size_t)kt * 16 * DIM;
        cp_async16(bs_b + (bf * 16 * LDB + bk0 * LDB + bnc) * 4, b);
        cp_async16(bs_b + (bf * 16 * LDB + (bk0 + 8) * LDB + bnc) * 4, b + (size_t)8 * DIM);
        cp_commit();
    };

    float acc[16][4];
#pragma unroll
    for (int i = 0; i < 16; i++)
#pragma unroll
        for (int j = 0; j < 4; j++) acc[i][j] = 0.0f;

    issue(0, 0);

    const int NT = DIM / 16;
#pragma unroll 1
    for (int kt = 0; kt < NT; kt++) {
        cp_wait0();
        __syncthreads();            // tile kt visible; prior buffer drained
        if (kt + 1 < NT) issue(kt + 1, (kt + 1) & 1);
        const int cur = kt & 1;

#pragma unroll
        for (int ks = 0; ks < 2; ks++) {
            uint32_t af[4][4], bf[4][2];
#pragma unroll
            for (int mi = 0; mi < 4; mi++) {
                const int r = wm + mi * 16 + (lane >> 2);
                const int c = ks * 8 + (lane & 3);
                af[mi][0] = As[cur][r * LDA + c];
                af[mi][1] = As[cur][(r + 8) * LDA + c];
                af[mi][2] = As[cur][r * LDA + c + 4];
                af[mi][3] = As[cur][(r + 8) * LDA + c + 4];
            }
#pragma unroll
            for (int ni = 0; ni < 4; ni++) {
                const int n = wn + ni * 8 + (lane >> 2);
                const int k = ks * 8 + (lane & 3);
                bf[ni][0] = Bs[cur][k * LDB + n];
                bf[ni][1] = Bs[cur][(k + 4) * LDB + n];
            }
#pragma unroll
            for (int mi = 0; mi < 4; mi++)
#pragma unroll
                for (int ni = 0; ni < 4; ni++)
                    mma_tf32(acc[mi * 4 + ni], af[mi], bf[ni]);
        }
    }

#pragma unroll
    for (int mi = 0; mi < 4; mi++) {
        const int r0 = bm + wm + mi * 16 + (lane >> 2);
        const int r1 = r0 + 8;
#pragma unroll
        for (int ni = 0; ni < 4; ni++) {
            const int c0 = bn + wn + ni * 8 + ((lane & 3) << 1);
            const float* a = acc[mi * 4 + ni];
            const float bi0 = bias[c0], bi1 = bias[c0 + 1];
            if (QKV == 0) {
                *(float2*)&Osel[(size_t)r0 * DIM + c0] = make_float2(a[0] + bi0, a[1] + bi1);
                *(float2*)&Osel[(size_t)r1 * DIM + c0] = make_float2(a[2] + bi0, a[3] + bi1);
            } else {
                const int h = c0 >> 6, d = c0 & 63;
                const int b0r = r0 >> 11, s0 = r0 & (S_ - 1);
                const int b1r = r1 >> 11, s1 = r1 & (S_ - 1);
                *(float2*)&Osel[(((size_t)(b0r * NH + h)) * S_ + s0) * HD + d] =
                    make_float2(tfr(a[0] + bi0), tfr(a[1] + bi1));
                *(float2*)&Osel[(((size_t)(b1r * NH + h)) * S_ + s1) * HD + d] =
                    make_float2(tfr(a[2] + bi0), tfr(a[3] + bi1));
            }
        }
    }
}

// ---------------------------------------------------------------------------
// RoPE (in-place on Q and K), tf32-RNA-rounded outputs.
// ---------------------------------------------------------------------------
__global__ void rope_kernel(float* __restrict__ Q, float* __restrict__ K,
                            const float* __restrict__ theta)
{
    const int gid  = blockIdx.x * blockDim.x + threadIdx.x;
    const int warp = gid >> 5;
    const int lane = gid & 31;
    const int s = warp & (S_ - 1);

    const float th = theta[lane];
    float sn, cs;
    sincosf((float)s * th, &sn, &cs);

    float* q = Q + (size_t)warp * HD;
    float x1 = q[2 * lane], x2 = q[2 * lane + 1];
    __syncwarp();
    q[lane]      = tfr(x1 * cs - x2 * sn);
    q[lane + 32] = tfr(x1 * sn + x2 * cs);

    float* k = K + (size_t)warp * HD;
    float y1 = k[2 * lane], y2 = k[2 * lane + 1];
    __syncwarp();
    k[lane]      = tfr(y1 * cs - y2 * sn);
    k[lane + 32] = tfr(y1 * sn + y2 * cs);
}

// ---------------------------------------------------------------------------
// TF32 flash attention v4: register-resident Q, cp.async double-buffered K/V
// with ONE barrier per tile, 2 CTAs/SM, diagonal dead-chunk skip, heavy-first
// scheduling. ctx written tf32-rounded for the downstream cp.async GEMM.
// ---------------------------------------------------------------------------
#define KLD 68
#define VLD 72
#define PLD 68
#define KBUF (64 * KLD)
#define VBUF (64 * VLD)
#define FLASH_SMEM_WORDS (2*KBUF + 2*VBUF + 128*PLD)   // 106.5 KB

__global__ __launch_bounds__(256, 2) void flash_tf32_kernel(
    const float* __restrict__ Q, const float* __restrict__ K,
    const float* __restrict__ V, float* __restrict__ ctx)
{
    extern __shared__ uint32_t sm[];
    uint32_t* Ks = sm;                   // [2][64][KLD]
    uint32_t* Vs = Ks + 2 * KBUF;        // [2][64][VLD]
    uint32_t* Ps = Vs + 2 * VBUF;        // [128][PLD]; Q staging at init

    const int bid  = blockIdx.x;
    const int qb   = 15 - (bid >> 5);    // heavy q-tiles first
    const int bh   = bid & 31;
    const int tid  = threadIdx.x;
    const int lane = tid & 31;
    const int warp = tid >> 5;
    const int g = lane >> 2;
    const int c = lane & 3;
    const int wrow = warp * 16;

    const float* Qg = Q + ((size_t)bh * S_ + qb * 128) * HD;
    const float* Kg = K + (size_t)bh * S_ * HD;
    const float* Vg = V + (size_t)bh * S_ * HD;

    const uint32_t ks_smem = (uint32_t)__cvta_generic_to_shared(Ks);
    const uint32_t vs_smem = (uint32_t)__cvta_generic_to_shared(Vs);

    const int lr = tid >> 4;
    const int lc = (tid & 15) << 2;

    auto issue_tile = [&](int t, int b) {
        const float* kg = Kg + (size_t)t * 64 * HD;
        const float* vg = Vg + (size_t)t * 64 * HD;
#pragma unroll
        for (int rr = 0; rr < 4; rr++) {
            const int r = lr + rr * 16;
            cp_async16(ks_smem + (b * KBUF + r * KLD + lc) * 4, kg + r * HD + lc);
            cp_async16(vs_smem + (b * VBUF + r * VLD + lc) * 4, vg + r * HD + lc);
        }
        cp_commit();
    };

    issue_tile(0, 0);

    // stage Q (scaled, tf32) into Ps, hoist this warp's fragments to regs
    for (int i = tid; i < 2048; i += 256) {
        const int r = i >> 4, c4 = (i & 15) << 2;
        float4 v = ((const float4*)Qg)[i];
        Ps[r * PLD + c4 + 0] = f2tf(v.x * 0.125f);
        Ps[r * PLD + c4 + 1] = f2tf(v.y * 0.125f);
        Ps[r * PLD + c4 + 2] = f2tf(v.z * 0.125f);
        Ps[r * PLD + c4 + 3] = f2tf(v.w * 0.125f);
    }
    __syncthreads();

    uint32_t qf[8][4];
#pragma unroll
    for (int ks = 0; ks < 8; ks++) {
        qf[ks][0] = Ps[(wrow + g)     * PLD + ks * 8 + c];
        qf[ks][1] = Ps[(wrow + g + 8) * PLD + ks * 8 + c];
        qf[ks][2] = Ps[(wrow + g)     * PLD + ks * 8 + c + 4];
        qf[ks][3] = Ps[(wrow + g + 8) * PLD + ks * 8 + c + 4];
    }

    float oacc[8][4];
#pragma unroll
    for (int nt = 0; nt < 8; nt++)
#pragma unroll
        for (int k = 0; k < 4; k++) oacc[nt][k] = 0.0f;
    float m0 = -3.0e38f, m1 = -3.0e38f, l0 = 0.0f, l1 = 0.0f;

    const int jmax = 2 * qb + 1;
    int buf = 0;
    for (int j = 0; j <= jmax; j++) {
        cp_wait0();
        __syncthreads();   // tile j visible; other buffer drained; Ps(qf) read
        if (j < jmax) issue_tile(j + 1, buf ^ 1);

        const uint32_t* Kb = Ks + buf * KBUF;
        const uint32_t* Vb = Vs + buf * VBUF;

        int ntlim = 8;
        const bool diag = (j >= 2 * qb);
        if (diag) {
            const int t = j - 2 * qb;
            const int lim = ((wrow + 15 - 64 * t) >> 3) + 1;
            ntlim = lim < 0 ? 0 : (lim > 8 ? 8 : lim);
        }

        if (ntlim > 0) {
            float sacc[8][4];
#pragma unroll
            for (int nt = 0; nt < 8; nt++)
#pragma unroll
                for (int k = 0; k < 4; k++) sacc[nt][k] = 0.0f;

            for (int nt = 0; nt < ntlim; nt++) {
#pragma unroll
                for (int ks = 0; ks < 8; ks++) {
                    uint32_t bf[2];
                    bf[0] = Kb[(nt * 8 + g) * KLD + ks * 8 + c];
                    bf[1] = Kb[(nt * 8 + g) * KLD + ks * 8 + c + 4];
                    mma_tf32(sacc[nt], qf[ks], bf);
                }
            }

            if (diag) {
                const int r0 = qb * 128 + wrow + g;
                const int r1 = r0 + 8;
                for (int nt = 0; nt < ntlim; nt++) {
                    const int col = j * 64 + nt * 8 + 2 * c;
                    if (col     > r0) sacc[nt][0] = -3.0e38f;
                    if (col + 1 > r0) sacc[nt][1] = -3.0e38f;
                    if (col     > r1) sacc[nt][2] = -3.0e38f;
                    if (col + 1 > r1) sacc[nt][3] = -3.0e38f;
                }
            }

            float rmax0 = -3.0e38f, rmax1 = -3.0e38f;
            for (int nt = 0; nt < ntlim; nt++) {
                rmax0 = fmaxf(rmax0, fmaxf(sacc[nt][0], sacc[nt][1]));
                rmax1 = fmaxf(rmax1, fmaxf(sacc[nt][2], sacc[nt][3]));
            }
#pragma unroll
            for (int off = 1; off < 4; off <<= 1) {
                rmax0 = fmaxf(rmax0, __shfl_xor_sync(0xffffffffu, rmax0, off));
                rmax1 = fmaxf(rmax1, __shfl_xor_sync(0xffffffffu, rmax1, off));
            }

            const float mn0 = fmaxf(m0, rmax0);
            const float mn1 = fmaxf(m1, rmax1);
            const float al0 = __expf(m0 - mn0);
            const float al1 = __expf(m1 - mn1);

            float rsum0 = 0.0f, rsum1 = 0.0f;
            __syncwarp();   // prior PV reads of Ps done before overwrite
            for (int nt = 0; nt < ntlim; nt++) {
                const float p0 = __expf(sacc[nt][0] - mn0);
                const float p1 = __expf(sacc[nt][1] - mn0);
                const float p2 = __expf(sacc[nt][2] - mn1);
                const float p3 = __expf(sacc[nt][3] - mn1);
                rsum0 += p0 + p1;
                rsum1 += p2 + p3;
                *(uint2*)&Ps[(wrow + g)     * PLD + nt * 8 + 2 * c] =
                    make_uint2(f2tf(p0), f2tf(p1));
                *(uint2*)&Ps[(wrow + g + 8) * PLD + nt * 8 + 2 * c] =
                    make_uint2(f2tf(p2), f2tf(p3));
            }
#pragma unroll
            for (int off = 1; off < 4; off <<= 1) {
                rsum0 += __shfl_xor_sync(0xffffffffu, rsum0, off);
                rsum1 += __shfl_xor_sync(0xffffffffu, rsum1, off);
            }
            l0 = l0 * al0 + rsum0;
            l1 = l1 * al1 + rsum1;
            m0 = mn0;
            m1 = mn1;
#pragma unroll
            for (int nt = 0; nt < 8; nt++) {
                oacc[nt][0] *= al0;
                oacc[nt][1] *= al0;
                oacc[nt][2] *= al1;
                oacc[nt][3] *= al1;
            }
            __syncwarp();   // Ps writes visible warp-wide

            for (int ks = 0; ks < ntlim; ks++) {
                uint32_t af[4];
                af[0] = Ps[(wrow + g)     * PLD + ks * 8 + c];
                af[1] = Ps[(wrow + g + 8) * PLD + ks * 8 + c];
                af[2] = Ps[(wrow + g)     * PLD + ks * 8 + c + 4];
                af[3] = Ps[(wrow + g + 8) * PLD + ks * 8 + c + 4];
#pragma unroll
                for (int nt = 0; nt < 8; nt++) {
                    uint32_t bf[2];
                    bf[0] = Vb[(ks * 8 + c)     * VLD + nt * 8 + g];
                    bf[1] = Vb[(ks * 8 + c + 4) * VLD + nt * 8 + g];
                    mma_tf32(oacc[nt], af, bf);
                }
            }
        }
        buf ^= 1;
    }

    // write ctx [B*S, H*hd], tf32-rounded for downstream cp.async GEMM
    const int b = bh >> 4, h = bh & 15;
    const int r0 = qb * 128 + wrow + g;
    const int r1 = r0 + 8;
    const float inv0 = 1.0f / l0;
    const float inv1 = 1.0f / l1;
#pragma unroll
    for (int nt = 0; nt < 8; nt++) {
        const int col = h * 64 + nt * 8 + 2 * c;
        *(float2*)&ctx[(size_t)(b * S_ + r0) * DIM + col] =
            make_float2(tfr(oacc[nt][0] * inv0), tfr(oacc[nt][1] * inv0));
        *(float2*)&ctx[(size_t)(b * S_ + r1) * DIM + col] =
            make_float2(tfr(oacc[nt][2] * inv1), tfr(oacc[nt][3] * inv1));
    }
}

// ---------------------------------------------------------------------------
extern "C" void kernel_launch(void* const* d_in, const int* in_sizes, int n_in,
                              void* d_out, int out_size)
{
    const float* x     = (const float*)d_in[0];
    const float* theta = (const float*)d_in[2];
    const float* Wq    = (const float*)d_in[3];
    const float* bq    = (const float*)d_in[4];
    const float* Wk    = (const float*)d_in[5];
    const float* bk    = (const float*)d_in[6];
    const float* Wv    = (const float*)d_in[7];
    const float* bv    = (const float*)d_in[8];
    const float* Wo    = (const float*)d_in[9];
    const float* bo    = (const float*)d_in[10];
    float* out = (float*)d_out;

    float *Qb, *Kb, *Vb, *Cb, *Xr, *Wr;
    cudaGetSymbolAddress((void**)&Qb, g_Q);
    cudaGetSymbolAddress((void**)&Kb, g_K);
    cudaGetSymbolAddress((void**)&Vb, g_V);
    cudaGetSymbolAddress((void**)&Cb, g_C);
    cudaGetSymbolAddress((void**)&Xr, g_Xr);
    cudaGetSymbolAddress((void**)&Wr, g_Wr);

    round_tf32_kernel<<<(X4 + 4 * W4) / 256, 256>>>(x, Wq, Wk, Wv, Wo, Xr, Wr);

    gemm_tf32_kernel<1><<<dim3(3 * DIM / 128, MROWS / 128), 256>>>(
        Xr, Wr, bq, bk, bv, Qb, Kb, Vb);

    rope_kernel<<<(B_ * NH * S_ * 32) / 256, 256>>>(Qb, Kb, theta);

    const int flashSmem = FLASH_SMEM_WORDS * (int)sizeof(uint32_t);  // 106.5 KB
    cudaFuncSetAttribute(flash_tf32_kernel,
                         cudaFuncAttributeMaxDynamicSharedMemorySize, flashSmem);
    flash_tf32_kernel<<<16 * 32, 256, flashSmem>>>(Qb, Kb, Vb, Cb);

    gemm_tf32_kernel<0><<<dim3(DIM / 128, MROWS / 128), 256>>>(
        Cb, Wr + (size_t)3 * DIM * DIM, bo, bo, bo, out, out, out);
}

// round 11
// speedup vs baseline: 3.9661x; 1.0422x over previous
#include <cuda_runtime.h>
#include <math.h>
#include <stdint.h>

#define DIM   1024
#define NH    16
#define HD    64
#define B_    2
#define S_    2048
#define MROWS (B_ * S_)   // 4096

// Scratch (allocation-free rule: __device__ globals)
__device__ float g_Q[B_ * NH * S_ * HD];   // [B,H,S,hd]
__device__ float g_K[B_ * NH * S_ * HD];
__device__ float g_V[B_ * NH * S_ * HD];
__device__ float g_C[MROWS * DIM];         // attention context (tf32-rounded)
__device__ float g_Xr[MROWS * DIM];        // x, tf32-RNA-rounded
__device__ float g_Wr[4 * DIM * DIM];      // Wq|Wk|Wv|Wo, tf32-RNA-rounded

// ---------------------------------------------------------------------------
// TF32 / async helpers
// ---------------------------------------------------------------------------
__device__ __forceinline__ uint32_t f2tf(float f) {
    uint32_t r;
    asm("cvt.rna.tf32.f32 %0, %1;" : "=r"(r) : "f"(f));
    return r;
}
__device__ __forceinline__ float tfr(float f) { return __uint_as_float(f2tf(f)); }

__device__ __forceinline__ void mma_tf32(float* d, const uint32_t* a, const uint32_t* b) {
    asm volatile(
        "mma.sync.aligned.m16n8k8.row.col.f32.tf32.tf32.f32 "
        "{%0,%1,%2,%3}, {%4,%5,%6,%7}, {%8,%9}, {%0,%1,%2,%3};"
        : "+f"(d[0]), "+f"(d[1]), "+f"(d[2]), "+f"(d[3])
        : "r"(a[0]), "r"(a[1]), "r"(a[2]), "r"(a[3]),
          "r"(b[0]), "r"(b[1]));
}

__device__ __forceinline__ void cp_async16(uint32_t smem_byte_addr, const void* gptr) {
    asm volatile("cp.async.cg.shared.global [%0], [%1], 16;"
                 :: "r"(smem_byte_addr), "l"(gptr));
}
__device__ __forceinline__ void cp_commit() {
    asm volatile("cp.async.commit_group;");
}
__device__ __forceinline__ void cp_wait0() {
    asm volatile("cp.async.wait_group 0;");
}

// ---------------------------------------------------------------------------
// Pre-round x and the four weight matrices to tf32-RNA.
// ---------------------------------------------------------------------------
#define X4 (MROWS * DIM / 4)   // 1048576
#define W4 (DIM * DIM / 4)     // 262144

__global__ void round_tf32_kernel(
    const float* __restrict__ x,
    const float* __restrict__ wq, const float* __restrict__ wk,
    const float* __restrict__ wv, const float* __restrict__ wo,
    float* __restrict__ xr, float* __restrict__ wr)
{
    const int gid = blockIdx.x * blockDim.x + threadIdx.x;
    const float4* src;
    float4* dst;
    int idx;
    if (gid < X4) {
        src = (const float4*)x;  dst = (float4*)xr;  idx = gid;
    } else {
        const int t = gid - X4;
        const int w = t >> 18;          // / W4
        idx = t & (W4 - 1);
        src = (const float4*)(w == 0 ? wq : w == 1 ? wk : w == 2 ? wv : wo);
        dst = (float4*)(wr + (size_t)w * DIM * DIM);
    }
    float4 v = src[idx];
    v.x = tfr(v.x); v.y = tfr(v.y); v.z = tfr(v.z); v.w = tfr(v.w);
    dst[idx] = v;
}

// ---------------------------------------------------------------------------
// TF32 GEMM v2: 128 threads, 4 warps, warp tile 64x64 (2x2 warp grid).
// Block 128x128x16, cp.async double-buffered, 1 barrier/tile.
// QKV=1: fused N=3072 (per-CTA weight select), scatter to [B,H,S,hd], tfr out.
// QKV=0: N=1024, row-major out + bias.
// ---------------------------------------------------------------------------
#define LDA 20
#define LDB 136

template<int QKV>
__global__ __launch_bounds__(128, 2) void gemm_tf32_kernel(
    const float* __restrict__ A, const float* __restrict__ Wall,
    const float* __restrict__ b0, const float* __restrict__ b1,
    const float* __restrict__ b2,
    float* __restrict__ O0, float* __restrict__ O1, float* __restrict__ O2)
{
    __shared__ uint32_t As[2][128 * LDA];
    __shared__ uint32_t Bs[2][16 * LDB];

    const int tid  = threadIdx.x;
    const int lane = tid & 31;
    const int warp = tid >> 5;
    const int bm  = blockIdx.y * 128;
    const int bnG = blockIdx.x * 128;
    const int wsel = bnG >> 10;
    const int bn   = bnG & 1023;
    const int wm = (warp & 1) << 6;      // 0 / 64
    const int wn = (warp >> 1) << 6;     // 0 / 64

    const float* W    = Wall + (size_t)wsel * DIM * DIM;
    const float* bias = QKV ? (wsel == 0 ? b0 : (wsel == 1 ? b1 : b2)) : b0;
    float* Osel = QKV ? (wsel == 0 ? O0 : (wsel == 1 ? O1 : O2)) : O0;

    // cp.async assignments (128 threads): A 512 float4, B 512 float4 per tile
    const int ar  = tid >> 2;            // 0..31 (+32,+64,+96)
    const int akc = (tid & 3) << 2;
    const int bk  = tid >> 5;            // 0..3 (+4,+8,+12)
    const int bnc = (tid & 31) << 2;

    const float* Ap = A + (size_t)(bm + ar) * DIM + akc;
    const float* Bp = W + (size_t)bk * DIM + bn + bnc;

    const uint32_t as_b = (uint32_t)__cvta_generic_to_shared(As);
    const uint32_t bs_b = (uint32_t)__cvta_generic_to_shared(Bs);

    auto issue = [&](int kt, int bf) {
        const float* a = Ap + kt * 16;
#pragma unroll
        for (int rr = 0; rr < 4; rr++)
            cp_async16(as_b + (bf * 128 * LDA + (ar + rr * 32) * LDA + akc) * 4,
                       a + (size_t)(rr * 32) * DIM);
        const float* b = Bp + (size_t)kt * 16 * DIM;
#pragma unroll
        for (int rr = 0; rr < 4; rr++)
            cp_async16(bs_b + (bf * 16 * LDB + (bk + rr * 4) * LDB + bnc) * 4,
                       b + (size_t)(rr * 4) * DIM);
        cp_commit();
    };

    float acc[32][4];
#pragma unroll
    for (int i = 0; i < 32; i++)
#pragma unroll
        for (int j = 0; j < 4; j++) acc[i][j] = 0.0f;

    issue(0, 0);

    const int NT = DIM / 16;
#pragma unroll 1
    for (int kt = 0; kt < NT; kt++) {
        cp_wait0();
        __syncthreads();
        if (kt + 1 < NT) issue(kt + 1, (kt + 1) & 1);
        const int cur = kt & 1;

#pragma unroll
        for (int ks = 0; ks < 2; ks++) {
            uint32_t af[4][4], bf[8][2];
#pragma unroll
            for (int mi = 0; mi < 4; mi++) {
                const int r = wm + mi * 16 + (lane >> 2);
                const int c = ks * 8 + (lane & 3);
                af[mi][0] = As[cur][r * LDA + c];
                af[mi][1] = As[cur][(r + 8) * LDA + c];
                af[mi][2] = As[cur][r * LDA + c + 4];
                af[mi][3] = As[cur][(r + 8) * LDA + c + 4];
            }
#pragma unroll
            for (int ni = 0; ni < 8; ni++) {
                const int n = wn + ni * 8 + (lane >> 2);
                const int k = ks * 8 + (lane & 3);
                bf[ni][0] = Bs[cur][k * LDB + n];
                bf[ni][1] = Bs[cur][(k + 4) * LDB + n];
            }
#pragma unroll
            for (int mi = 0; mi < 4; mi++)
#pragma unroll
                for (int ni = 0; ni < 8; ni++)
                    mma_tf32(acc[mi * 8 + ni], af[mi], bf[ni]);
        }
    }

#pragma unroll
    for (int mi = 0; mi < 4; mi++) {
        const int r0 = bm + wm + mi * 16 + (lane >> 2);
        const int r1 = r0 + 8;
#pragma unroll
        for (int ni = 0; ni < 8; ni++) {
            const int c0 = bn + wn + ni * 8 + ((lane & 3) << 1);
            const float* a = acc[mi * 8 + ni];
            const float bi0 = bias[c0], bi1 = bias[c0 + 1];
            if (QKV == 0) {
                *(float2*)&Osel[(size_t)r0 * DIM + c0] = make_float2(a[0] + bi0, a[1] + bi1);
                *(float2*)&Osel[(size_t)r1 * DIM + c0] = make_float2(a[2] + bi0, a[3] + bi1);
            } else {
                const int h = c0 >> 6, d = c0 & 63;
                const int b0r = r0 >> 11, s0 = r0 & (S_ - 1);
                const int b1r = r1 >> 11, s1 = r1 & (S_ - 1);
                *(float2*)&Osel[(((size_t)(b0r * NH + h)) * S_ + s0) * HD + d] =
                    make_float2(tfr(a[0] + bi0), tfr(a[1] + bi1));
                *(float2*)&Osel[(((size_t)(b1r * NH + h)) * S_ + s1) * HD + d] =
                    make_float2(tfr(a[2] + bi0), tfr(a[3] + bi1));
            }
        }
    }
}

// ---------------------------------------------------------------------------
// RoPE (in-place on Q and K), tf32-RNA-rounded outputs.
// ---------------------------------------------------------------------------
__global__ void rope_kernel(float* __restrict__ Q, float* __restrict__ K,
                            const float* __restrict__ theta)
{
    const int gid  = blockIdx.x * blockDim.x + threadIdx.x;
    const int warp = gid >> 5;
    const int lane = gid & 31;
    const int s = warp & (S_ - 1);

    const float th = theta[lane];
    float sn, cs;
    sincosf((float)s * th, &sn, &cs);

    float* q = Q + (size_t)warp * HD;
    float x1 = q[2 * lane], x2 = q[2 * lane + 1];
    __syncwarp();
    q[lane]      = tfr(x1 * cs - x2 * sn);
    q[lane + 32] = tfr(x1 * sn + x2 * cs);

    float* k = K + (size_t)warp * HD;
    float y1 = k[2 * lane], y2 = k[2 * lane + 1];
    __syncwarp();
    k[lane]      = tfr(y1 * cs - y2 * sn);
    k[lane + 32] = tfr(y1 * sn + y2 * cs);
}

// ---------------------------------------------------------------------------
// TF32 flash attention v5: 128 threads, 4 warps, 32 q-rows per warp
// (2 mi-groups) -> K/V fragments reused across mi in registers, cutting smem
// crossbar traffic ~37% per MMA. Register-resident Q, cp.async double
// buffering (1 barrier/tile), diagonal dead-chunk skip, heavy-first order.
// ---------------------------------------------------------------------------
#define KLD 68
#define VLD 72
#define PLD 68
#define KBUF (64 * KLD)
#define VBUF (64 * VLD)
#define FLASH_SMEM_WORDS (2*KBUF + 2*VBUF + 128*PLD)   // 106.5 KB

__global__ __launch_bounds__(128, 2) void flash_tf32_kernel(
    const float* __restrict__ Q, const float* __restrict__ K,
    const float* __restrict__ V, float* __restrict__ ctx)
{
    extern __shared__ uint32_t sm[];
    uint32_t* Ks = sm;                   // [2][64][KLD]
    uint32_t* Vs = Ks + 2 * KBUF;        // [2][64][VLD]
    uint32_t* Ps = Vs + 2 * VBUF;        // [128][PLD]; Q staging at init

    const int bid  = blockIdx.x;
    const int qb   = 15 - (bid >> 5);    // heavy q-tiles first
    const int bh   = bid & 31;
    const int tid  = threadIdx.x;
    const int lane = tid & 31;
    const int warp = tid >> 5;           // 0..3
    const int g = lane >> 2;
    const int c = lane & 3;
    const int wrow = warp * 32;          // warp owns q-rows [wrow, wrow+32)

    const float* Qg = Q + ((size_t)bh * S_ + qb * 128) * HD;
    const float* Kg = K + (size_t)bh * S_ * HD;
    const float* Vg = V + (size_t)bh * S_ * HD;

    const uint32_t ks_smem = (uint32_t)__cvta_generic_to_shared(Ks);
    const uint32_t vs_smem = (uint32_t)__cvta_generic_to_shared(Vs);

    const int lr = tid >> 4;            // 0..7
    const int lc = (tid & 15) << 2;

    auto issue_tile = [&](int t, int b) {
        const float* kg = Kg + (size_t)t * 64 * HD;
        const float* vg = Vg + (size_t)t * 64 * HD;
#pragma unroll
        for (int rr = 0; rr < 8; rr++) {
            const int r = lr + rr * 8;
            cp_async16(ks_smem + (b * KBUF + r * KLD + lc) * 4, kg + r * HD + lc);
            cp_async16(vs_smem + (b * VBUF + r * VLD + lc) * 4, vg + r * HD + lc);
        }
        cp_commit();
    };

    issue_tile(0, 0);

    // stage Q (scaled, tf32) into Ps, hoist this warp's fragments to regs
    for (int i = tid; i < 2048; i += 128) {
        const int r = i >> 4, c4 = (i & 15) << 2;
        float4 v = ((const float4*)Qg)[i];
        Ps[r * PLD + c4 + 0] = f2tf(v.x * 0.125f);
        Ps[r * PLD + c4 + 1] = f2tf(v.y * 0.125f);
        Ps[r * PLD + c4 + 2] = f2tf(v.z * 0.125f);
        Ps[r * PLD + c4 + 3] = f2tf(v.w * 0.125f);
    }
    __syncthreads();

    uint32_t qf[2][8][4];
#pragma unroll
    for (int mi = 0; mi < 2; mi++) {
        const int r0 = wrow + mi * 16 + g;
#pragma unroll
        for (int ks = 0; ks < 8; ks++) {
            qf[mi][ks][0] = Ps[r0 * PLD + ks * 8 + c];
            qf[mi][ks][1] = Ps[(r0 + 8) * PLD + ks * 8 + c];
            qf[mi][ks][2] = Ps[r0 * PLD + ks * 8 + c + 4];
            qf[mi][ks][3] = Ps[(r0 + 8) * PLD + ks * 8 + c + 4];
        }
    }

    float oacc[2][8][4];
#pragma unroll
    for (int mi = 0; mi < 2; mi++)
#pragma unroll
        for (int nt = 0; nt < 8; nt++)
#pragma unroll
            for (int k = 0; k < 4; k++) oacc[mi][nt][k] = 0.0f;
    float mI[2][2] = {{-3.0e38f, -3.0e38f}, {-3.0e38f, -3.0e38f}};
    float lI[2][2] = {{0.0f, 0.0f}, {0.0f, 0.0f}};

    const int jmax = 2 * qb + 1;
    int buf = 0;
    for (int j = 0; j <= jmax; j++) {
        cp_wait0();
        __syncthreads();   // tile j visible; other buffer drained; qf read done
        if (j < jmax) issue_tile(j + 1, buf ^ 1);

        const uint32_t* Kb = Ks + buf * KBUF;
        const uint32_t* Vb = Vs + buf * VBUF;

        int ntlim = 8;
        const bool diag = (j >= 2 * qb);
        if (diag) {
            const int t = j - 2 * qb;
            const int lim = ((wrow + 31 - 64 * t) >> 3) + 1;
            ntlim = lim < 0 ? 0 : (lim > 8 ? 8 : lim);
        }

        if (ntlim > 0) {
            // ---- S = Q @ K^T : K fragments reused across both mi groups
            float sacc[2][8][4];
#pragma unroll
            for (int mi = 0; mi < 2; mi++)
#pragma unroll
                for (int nt = 0; nt < 8; nt++)
#pragma unroll
                    for (int k = 0; k < 4; k++) sacc[mi][nt][k] = 0.0f;

            for (int nt = 0; nt < ntlim; nt++) {
#pragma unroll
                for (int ks = 0; ks < 8; ks++) {
                    uint32_t bf[2];
                    bf[0] = Kb[(nt * 8 + g) * KLD + ks * 8 + c];
                    bf[1] = Kb[(nt * 8 + g) * KLD + ks * 8 + c + 4];
                    mma_tf32(sacc[0][nt], qf[0][ks], bf);
                    mma_tf32(sacc[1][nt], qf[1][ks], bf);
                }
            }

            if (diag) {
#pragma unroll
                for (int mi = 0; mi < 2; mi++) {
                    const int r0 = qb * 128 + wrow + mi * 16 + g;
                    const int r1 = r0 + 8;
                    for (int nt = 0; nt < ntlim; nt++) {
                        const int col = j * 64 + nt * 8 + 2 * c;
                        if (col     > r0) sacc[mi][nt][0] = -3.0e38f;
                        if (col + 1 > r0) sacc[mi][nt][1] = -3.0e38f;
                        if (col     > r1) sacc[mi][nt][2] = -3.0e38f;
                        if (col + 1 > r1) sacc[mi][nt][3] = -3.0e38f;
                    }
                }
            }

            // ---- online softmax (per mi group), P -> smem
            __syncwarp();   // prior PV reads of Ps done before overwrite
#pragma unroll
            for (int mi = 0; mi < 2; mi++) {
                float rmax0 = -3.0e38f, rmax1 = -3.0e38f;
                for (int nt = 0; nt < ntlim; nt++) {
                    rmax0 = fmaxf(rmax0, fmaxf(sacc[mi][nt][0], sacc[mi][nt][1]));
                    rmax1 = fmaxf(rmax1, fmaxf(sacc[mi][nt][2], sacc[mi][nt][3]));
                }
#pragma unroll
                for (int off = 1; off < 4; off <<= 1) {
                    rmax0 = fmaxf(rmax0, __shfl_xor_sync(0xffffffffu, rmax0, off));
                    rmax1 = fmaxf(rmax1, __shfl_xor_sync(0xffffffffu, rmax1, off));
                }

                const float mn0 = fmaxf(mI[mi][0], rmax0);
                const float mn1 = fmaxf(mI[mi][1], rmax1);
                const float al0 = __expf(mI[mi][0] - mn0);
                const float al1 = __expf(mI[mi][1] - mn1);

                const int r0 = wrow + mi * 16 + g;
                float rsum0 = 0.0f, rsum1 = 0.0f;
                for (int nt = 0; nt < ntlim; nt++) {
                    const float p0 = __expf(sacc[mi][nt][0] - mn0);
                    const float p1 = __expf(sacc[mi][nt][1] - mn0);
                    const float p2 = __expf(sacc[mi][nt][2] - mn1);
                    const float p3 = __expf(sacc[mi][nt][3] - mn1);
                    rsum0 += p0 + p1;
                    rsum1 += p2 + p3;
                    *(uint2*)&Ps[r0 * PLD + nt * 8 + 2 * c] =
                        make_uint2(f2tf(p0), f2tf(p1));
                    *(uint2*)&Ps[(r0 + 8) * PLD + nt * 8 + 2 * c] =
                        make_uint2(f2tf(p2), f2tf(p3));
                }
#pragma unroll
                for (int off = 1; off < 4; off <<= 1) {
                    rsum0 += __shfl_xor_sync(0xffffffffu, rsum0, off);
                    rsum1 += __shfl_xor_sync(0xffffffffu, rsum1, off);
                }
                lI[mi][0] = lI[mi][0] * al0 + rsum0;
                lI[mi][1] = lI[mi][1] * al1 + rsum1;
                mI[mi][0] = mn0;
                mI[mi][1] = mn1;
#pragma unroll
                for (int nt = 0; nt < 8; nt++) {
                    oacc[mi][nt][0] *= al0;
                    oacc[mi][nt][1] *= al0;
                    oacc[mi][nt][2] *= al1;
                    oacc[mi][nt][3] *= al1;
                }
            }
            __syncwarp();   // Ps writes visible warp-wide

            // ---- O += P @ V : V fragments reused across both mi groups
            for (int ks = 0; ks < ntlim; ks++) {
                uint32_t af0[4], af1[4];
                const int pr0 = wrow + g;
                af0[0] = Ps[pr0 * PLD + ks * 8 + c];
                af0[1] = Ps[(pr0 + 8) * PLD + ks * 8 + c];
                af0[2] = Ps[pr0 * PLD + ks * 8 + c + 4];
                af0[3] = Ps[(pr0 + 8) * PLD + ks * 8 + c + 4];
                af1[0] = Ps[(pr0 + 16) * PLD + ks * 8 + c];
                af1[1] = Ps[(pr0 + 24) * PLD + ks * 8 + c];
                af1[2] = Ps[(pr0 + 16) * PLD + ks * 8 + c + 4];
                af1[3] = Ps[(pr0 + 24) * PLD + ks * 8 + c + 4];
#pragma unroll
                for (int nt = 0; nt < 8; nt++) {
                    uint32_t bf[2];
                    bf[0] = Vb[(ks * 8 + c)     * VLD + nt * 8 + g];
                    bf[1] = Vb[(ks * 8 + c + 4) * VLD + nt * 8 + g];
                    mma_tf32(oacc[0][nt], af0, bf);
                    mma_tf32(oacc[1][nt], af1, bf);
                }
            }
        }
        buf ^= 1;
    }

    // ---- write ctx [B*S, H*hd], tf32-rounded for downstream cp.async GEMM
    const int b = bh >> 4, h = bh & 15;
#pragma unroll
    for (int mi = 0; mi < 2; mi++) {
        const int r0 = qb * 128 + wrow + mi * 16 + g;
        const int r1 = r0 + 8;
        const float inv0 = 1.0f / lI[mi][0];
        const float inv1 = 1.0f / lI[mi][1];
#pragma unroll
        for (int nt = 0; nt < 8; nt++) {
            const int col = h * 64 + nt * 8 + 2 * c;
            *(float2*)&ctx[(size_t)(b * S_ + r0) * DIM + col] =
                make_float2(tfr(oacc[mi][nt][0] * inv0), tfr(oacc[mi][nt][1] * inv0));
            *(float2*)&ctx[(size_t)(b * S_ + r1) * DIM + col] =
                make_float2(tfr(oacc[mi][nt][2] * inv1), tfr(oacc[mi][nt][3] * inv1));
        }
    }
}

// ---------------------------------------------------------------------------
extern "C" void kernel_launch(void* const* d_in, const int* in_sizes, int n_in,
                              void* d_out, int out_size)
{
    const float* x     = (const float*)d_in[0];
    const float* theta = (const float*)d_in[2];
    const float* Wq    = (const float*)d_in[3];
    const float* bq    = (const float*)d_in[4];
    const float* Wk    = (const float*)d_in[5];
    const float* bk    = (const float*)d_in[6];
    const float* Wv    = (const float*)d_in[7];
    const float* bv    = (const float*)d_in[8];
    const float* Wo    = (const float*)d_in[9];
    const float* bo    = (const float*)d_in[10];
    float* out = (float*)d_out;

    float *Qb, *Kb, *Vb, *Cb, *Xr, *Wr;
    cudaGetSymbolAddress((void**)&Qb, g_Q);
    cudaGetSymbolAddress((void**)&Kb, g_K);
    cudaGetSymbolAddress((void**)&Vb, g_V);
    cudaGetSymbolAddress((void**)&Cb, g_C);
    cudaGetSymbolAddress((void**)&Xr, g_Xr);
    cudaGetSymbolAddress((void**)&Wr, g_Wr);

    round_tf32_kernel<<<(X4 + 4 * W4) / 256, 256>>>(x, Wq, Wk, Wv, Wo, Xr, Wr);

    gemm_tf32_kernel<1><<<dim3(3 * DIM / 128, MROWS / 128), 128>>>(
        Xr, Wr, bq, bk, bv, Qb, Kb, Vb);

    rope_kernel<<<(B_ * NH * S_ * 32) / 256, 256>>>(Qb, Kb, theta);

    const int flashSmem = FLASH_SMEM_WORDS * (int)sizeof(uint32_t);  // 106.5 KB
    cudaFuncSetAttribute(flash_tf32_kernel,
                         cudaFuncAttributeMaxDynamicSharedMemorySize, flashSmem);
    flash_tf32_kernel<<<16 * 32, 128, flashSmem>>>(Qb, Kb, Vb, Cb);

    gemm_tf32_kernel<0><<<dim3(DIM / 128, MROWS / 128), 128>>>(
        Cb, Wr + (size_t)3 * DIM * DIM, bo, bo, bo, out, out, out);
}

// round 13
// speedup vs baseline: 4.0239x; 1.0146x over previous
#include <cuda_runtime.h>
#include <math.h>
#include <stdint.h>

#define DIM   1024
#define NH    16
#define HD    64
#define B_    2
#define S_    2048
#define MROWS (B_ * S_)   // 4096

// Scratch (allocation-free rule: __device__ globals)
__device__ float g_Q[B_ * NH * S_ * HD];   // [B,H,S,hd]
__device__ float g_K[B_ * NH * S_ * HD];
__device__ float g_V[B_ * NH * S_ * HD];
__device__ float g_C[MROWS * DIM];         // attention context (tf32-rounded)
__device__ float g_Xr[MROWS * DIM];        // x, tf32-RNA-rounded
__device__ float g_Wr[4 * DIM * DIM];      // Wq|Wk|Wv|Wo, tf32-RNA-rounded

// ---------------------------------------------------------------------------
// TF32 / async helpers
// ---------------------------------------------------------------------------
__device__ __forceinline__ uint32_t f2tf(float f) {
    uint32_t r;
    asm("cvt.rna.tf32.f32 %0, %1;" : "=r"(r) : "f"(f));
    return r;
}
__device__ __forceinline__ float tfr(float f) { return __uint_as_float(f2tf(f)); }

__device__ __forceinline__ void mma_tf32(float* d, const uint32_t* a, const uint32_t* b) {
    asm volatile(
        "mma.sync.aligned.m16n8k8.row.col.f32.tf32.tf32.f32 "
        "{%0,%1,%2,%3}, {%4,%5,%6,%7}, {%8,%9}, {%0,%1,%2,%3};"
        : "+f"(d[0]), "+f"(d[1]), "+f"(d[2]), "+f"(d[3])
        : "r"(a[0]), "r"(a[1]), "r"(a[2]), "r"(a[3]),
          "r"(b[0]), "r"(b[1]));
}

__device__ __forceinline__ void cp_async16(uint32_t smem_byte_addr, const void* gptr) {
    asm volatile("cp.async.cg.shared.global [%0], [%1], 16;"
                 :: "r"(smem_byte_addr), "l"(gptr));
}
__device__ __forceinline__ void cp_commit() { asm volatile("cp.async.commit_group;"); }
__device__ __forceinline__ void cp_wait0()  { asm volatile("cp.async.wait_group 0;"); }

// ---------------------------------------------------------------------------
// Pre-round x and the four weight matrices to tf32-RNA.
// ---------------------------------------------------------------------------
#define X4 (MROWS * DIM / 4)   // 1048576
#define W4 (DIM * DIM / 4)     // 262144

__global__ void round_tf32_kernel(
    const float* __restrict__ x,
    const float* __restrict__ wq, const float* __restrict__ wk,
    const float* __restrict__ wv, const float* __restrict__ wo,
    float* __restrict__ xr, float* __restrict__ wr)
{
    const int gid = blockIdx.x * blockDim.x + threadIdx.x;
    const float4* src;
    float4* dst;
    int idx;
    if (gid < X4) {
        src = (const float4*)x;  dst = (float4*)xr;  idx = gid;
    } else {
        const int t = gid - X4;
        const int w = t >> 18;          // / W4
        idx = t & (W4 - 1);
        src = (const float4*)(w == 0 ? wq : w == 1 ? wk : w == 2 ? wv : wo);
        dst = (float4*)(wr + (size_t)w * DIM * DIM);
    }
    float4 v = src[idx];
    v.x = tfr(v.x); v.y = tfr(v.y); v.z = tfr(v.z); v.w = tfr(v.w);
    dst[idx] = v;
}

// ---------------------------------------------------------------------------
// TF32 GEMM v2: 128 threads, 4 warps, warp tile 64x64 (2x2 warp grid).
// Block 128x128x16, cp.async double-buffered, 1 barrier/tile.
// QKV=1: fused N=3072 (per-CTA weight select), scatter to [B,H,S,hd], tfr out.
// QKV=0: N=1024, row-major out + bias.
// ---------------------------------------------------------------------------
#define LDA 20
#define LDB 136

template<int QKV>
__global__ __launch_bounds__(128, 2) void gemm_tf32_kernel(
    const float* __restrict__ A, const float* __restrict__ Wall,
    const float* __restrict__ b0, const float* __restrict__ b1,
    const float* __restrict__ b2,
    float* __restrict__ O0, float* __restrict__ O1, float* __restrict__ O2)
{
    __shared__ uint32_t As[2][128 * LDA];
    __shared__ uint32_t Bs[2][16 * LDB];

    const int tid  = threadIdx.x;
    const int lane = tid & 31;
    const int warp = tid >> 5;
    const int bm  = blockIdx.y * 128;
    const int bnG = blockIdx.x * 128;
    const int wsel = bnG >> 10;
    const int bn   = bnG & 1023;
    const int wm = (warp & 1) << 6;      // 0 / 64
    const int wn = (warp >> 1) << 6;     // 0 / 64

    const float* W    = Wall + (size_t)wsel * DIM * DIM;
    const float* bias = QKV ? (wsel == 0 ? b0 : (wsel == 1 ? b1 : b2)) : b0;
    float* Osel = QKV ? (wsel == 0 ? O0 : (wsel == 1 ? O1 : O2)) : O0;

    const int ar  = tid >> 2;            // 0..31 (+32,+64,+96)
    const int akc = (tid & 3) << 2;
    const int bk  = tid >> 5;            // 0..3 (+4,+8,+12)
    const int bnc = (tid & 31) << 2;

    const float* Ap = A + (size_t)(bm + ar) * DIM + akc;
    const float* Bp = W + (size_t)bk * DIM + bn + bnc;

    const uint32_t as_b = (uint32_t)__cvta_generic_to_shared(As);
    const uint32_t bs_b = (uint32_t)__cvta_generic_to_shared(Bs);

    auto issue = [&](int kt, int bf) {
        const float* a = Ap + kt * 16;
#pragma unroll
        for (int rr = 0; rr < 4; rr++)
            cp_async16(as_b + (bf * 128 * LDA + (ar + rr * 32) * LDA + akc) * 4,
                       a + (size_t)(rr * 32) * DIM);
        const float* b = Bp + (size_t)kt * 16 * DIM;
#pragma unroll
        for (int rr = 0; rr < 4; rr++)
            cp_async16(bs_b + (bf * 16 * LDB + (bk + rr * 4) * LDB + bnc) * 4,
                       b + (size_t)(rr * 4) * DIM);
        cp_commit();
    };

    float acc[32][4];
#pragma unroll
    for (int i = 0; i < 32; i++)
#pragma unroll
        for (int j = 0; j < 4; j++) acc[i][j] = 0.0f;

    issue(0, 0);

    const int NT = DIM / 16;
#pragma unroll 1
    for (int kt = 0; kt < NT; kt++) {
        cp_wait0();
        __syncthreads();
        if (kt + 1 < NT) issue(kt + 1, (kt + 1) & 1);
        const int cur = kt & 1;

#pragma unroll
        for (int ks = 0; ks < 2; ks++) {
            uint32_t af[4][4], bf[8][2];
#pragma unroll
            for (int mi = 0; mi < 4; mi++) {
                const int r = wm + mi * 16 + (lane >> 2);
                const int c = ks * 8 + (lane & 3);
                af[mi][0] = As[cur][r * LDA + c];
                af[mi][1] = As[cur][(r + 8) * LDA + c];
                af[mi][2] = As[cur][r * LDA + c + 4];
                af[mi][3] = As[cur][(r + 8) * LDA + c + 4];
            }
#pragma unroll
            for (int ni = 0; ni < 8; ni++) {
                const int n = wn + ni * 8 + (lane >> 2);
                const int k = ks * 8 + (lane & 3);
                bf[ni][0] = Bs[cur][k * LDB + n];
                bf[ni][1] = Bs[cur][(k + 4) * LDB + n];
            }
#pragma unroll
            for (int mi = 0; mi < 4; mi++)
#pragma unroll
                for (int ni = 0; ni < 8; ni++)
                    mma_tf32(acc[mi * 8 + ni], af[mi], bf[ni]);
        }
    }

#pragma unroll
    for (int mi = 0; mi < 4; mi++) {
        const int r0 = bm + wm + mi * 16 + (lane >> 2);
        const int r1 = r0 + 8;
#pragma unroll
        for (int ni = 0; ni < 8; ni++) {
            const int c0 = bn + wn + ni * 8 + ((lane & 3) << 1);
            const float* a = acc[mi * 8 + ni];
            const float bi0 = bias[c0], bi1 = bias[c0 + 1];
            if (QKV == 0) {
                *(float2*)&Osel[(size_t)r0 * DIM + c0] = make_float2(a[0] + bi0, a[1] + bi1);
                *(float2*)&Osel[(size_t)r1 * DIM + c0] = make_float2(a[2] + bi0, a[3] + bi1);
            } else {
                const int h = c0 >> 6, d = c0 & 63;
                const int b0r = r0 >> 11, s0 = r0 & (S_ - 1);
                const int b1r = r1 >> 11, s1 = r1 & (S_ - 1);
                *(float2*)&Osel[(((size_t)(b0r * NH + h)) * S_ + s0) * HD + d] =
                    make_float2(tfr(a[0] + bi0), tfr(a[1] + bi1));
                *(float2*)&Osel[(((size_t)(b1r * NH + h)) * S_ + s1) * HD + d] =
                    make_float2(tfr(a[2] + bi0), tfr(a[3] + bi1));
            }
        }
    }
}

// ---------------------------------------------------------------------------
// RoPE (in-place on Q and K), tf32-RNA-rounded outputs.
// ---------------------------------------------------------------------------
__global__ void rope_kernel(float* __restrict__ Q, float* __restrict__ K,
                            const float* __restrict__ theta)
{
    const int gid  = blockIdx.x * blockDim.x + threadIdx.x;
    const int warp = gid >> 5;
    const int lane = gid & 31;
    const int s = warp & (S_ - 1);

    const float th = theta[lane];
    float sn, cs;
    sincosf((float)s * th, &sn, &cs);

    float* q = Q + (size_t)warp * HD;
    float x1 = q[2 * lane], x2 = q[2 * lane + 1];
    __syncwarp();
    q[lane]      = tfr(x1 * cs - x2 * sn);
    q[lane + 32] = tfr(x1 * sn + x2 * cs);

    float* k = K + (size_t)warp * HD;
    float y1 = k[2 * lane], y2 = k[2 * lane + 1];
    __syncwarp();
    k[lane]      = tfr(y1 * cs - y2 * sn);
    k[lane + 32] = tfr(y1 * sn + y2 * cs);
}

// ---------------------------------------------------------------------------
// TF32 flash attention v6: as v5 (4 warps, 32 q-rows/warp, register Q,
// cp.async double buffer, diag skip) + QK^T loop interchange on full tiles:
// ks-outer / nt-inner fully unrolled -> 16 independent MMA chains (was 2),
// removing the dependent-MMA stall that capped tensor pipe at ~38%.
// Per-accumulator k-order unchanged (ks ascending) -> bit-identical output.
// ---------------------------------------------------------------------------
#define KLD 68
#define VLD 72
#define PLD 68
#define KBUF (64 * KLD)
#define VBUF (64 * VLD)
#define FLASH_SMEM_WORDS (2*KBUF + 2*VBUF + 128*PLD)   // 106.5 KB

__global__ __launch_bounds__(128, 2) void flash_tf32_kernel(
    const float* __restrict__ Q, const float* __restrict__ K,
    const float* __restrict__ V, float* __restrict__ ctx)
{
    extern __shared__ uint32_t sm[];
    uint32_t* Ks = sm;
    uint32_t* Vs = Ks + 2 * KBUF;
    uint32_t* Ps = Vs + 2 * VBUF;

    const int bid  = blockIdx.x;
    const int qb   = 15 - (bid >> 5);
    const int bh   = bid & 31;
    const int tid  = threadIdx.x;
    const int lane = tid & 31;
    const int warp = tid >> 5;
    const int g = lane >> 2;
    const int c = lane & 3;
    const int wrow = warp * 32;

    const float* Qg = Q + ((size_t)bh * S_ + qb * 128) * HD;
    const float* Kg = K + (size_t)bh * S_ * HD;
    const float* Vg = V + (size_t)bh * S_ * HD;

    const uint32_t ks_smem = (uint32_t)__cvta_generic_to_shared(Ks);
    const uint32_t vs_smem = (uint32_t)__cvta_generic_to_shared(Vs);

    const int lr = tid >> 4;
    const int lc = (tid & 15) << 2;

    auto issue_tile = [&](int t, int b) {
        const float* kg = Kg + (size_t)t * 64 * HD;
        const float* vg = Vg + (size_t)t * 64 * HD;
#pragma unroll
        for (int rr = 0; rr < 8; rr++) {
            const int r = lr + rr * 8;
            cp_async16(ks_smem + (b * KBUF + r * KLD + lc) * 4, kg + r * HD + lc);
            cp_async16(vs_smem + (b * VBUF + r * VLD + lc) * 4, vg + r * HD + lc);
        }
        cp_commit();
    };

    issue_tile(0, 0);

    for (int i = tid; i < 2048; i += 128) {
        const int r = i >> 4, c4 = (i & 15) << 2;
        float4 v = ((const float4*)Qg)[i];
        Ps[r * PLD + c4 + 0] = f2tf(v.x * 0.125f);
        Ps[r * PLD + c4 + 1] = f2tf(v.y * 0.125f);
        Ps[r * PLD + c4 + 2] = f2tf(v.z * 0.125f);
        Ps[r * PLD + c4 + 3] = f2tf(v.w * 0.125f);
    }
    __syncthreads();

    uint32_t qf[2][8][4];
#pragma unroll
    for (int mi = 0; mi < 2; mi++) {
        const int r0 = wrow + mi * 16 + g;
#pragma unroll
        for (int ks = 0; ks < 8; ks++) {
            qf[mi][ks][0] = Ps[r0 * PLD + ks * 8 + c];
            qf[mi][ks][1] = Ps[(r0 + 8) * PLD + ks * 8 + c];
            qf[mi][ks][2] = Ps[r0 * PLD + ks * 8 + c + 4];
            qf[mi][ks][3] = Ps[(r0 + 8) * PLD + ks * 8 + c + 4];
        }
    }

    float oacc[2][8][4];
#pragma unroll
    for (int mi = 0; mi < 2; mi++)
#pragma unroll
        for (int nt = 0; nt < 8; nt++)
#pragma unroll
            for (int k = 0; k < 4; k++) oacc[mi][nt][k] = 0.0f;
    float mI[2][2] = {{-3.0e38f, -3.0e38f}, {-3.0e38f, -3.0e38f}};
    float lI[2][2] = {{0.0f, 0.0f}, {0.0f, 0.0f}};

    const int jmax = 2 * qb + 1;
    int buf = 0;
    for (int j = 0; j <= jmax; j++) {
        cp_wait0();
        __syncthreads();
        if (j < jmax) issue_tile(j + 1, buf ^ 1);

        const uint32_t* Kb = Ks + buf * KBUF;
        const uint32_t* Vb = Vs + buf * VBUF;

        int ntlim = 8;
        const bool diag = (j >= 2 * qb);
        if (diag) {
            const int t = j - 2 * qb;
            const int lim = ((wrow + 31 - 64 * t) >> 3) + 1;
            ntlim = lim < 0 ? 0 : (lim > 8 ? 8 : lim);
        }

        if (ntlim > 0) {
            float sacc[2][8][4];
#pragma unroll
            for (int mi = 0; mi < 2; mi++)
#pragma unroll
                for (int nt = 0; nt < 8; nt++)
#pragma unroll
                    for (int k = 0; k < 4; k++) sacc[mi][nt][k] = 0.0f;

            if (ntlim == 8) {
                // full tile: ks-outer / nt-inner, fully unrolled ->
                // 16 independent accumulator chains between dependent MMAs
#pragma unroll
                for (int ks = 0; ks < 8; ks++) {
#pragma unroll
                    for (int nt = 0; nt < 8; nt++) {
                        uint32_t bf[2];
                        bf[0] = Kb[(nt * 8 + g) * KLD + ks * 8 + c];
                        bf[1] = Kb[(nt * 8 + g) * KLD + ks * 8 + c + 4];
                        mma_tf32(sacc[0][nt], qf[0][ks], bf);
                        mma_tf32(sacc[1][nt], qf[1][ks], bf);
                    }
                }
            } else {
                // diagonal tile: runtime nt bound (same ks-ascending order)
                for (int nt = 0; nt < ntlim; nt++) {
#pragma unroll
                    for (int ks = 0; ks < 8; ks++) {
                        uint32_t bf[2];
                        bf[0] = Kb[(nt * 8 + g) * KLD + ks * 8 + c];
                        bf[1] = Kb[(nt * 8 + g) * KLD + ks * 8 + c + 4];
                        mma_tf32(sacc[0][nt], qf[0][ks], bf);
                        mma_tf32(sacc[1][nt], qf[1][ks], bf);
                    }
                }
            }

            if (diag) {
#pragma unroll
                for (int mi = 0; mi < 2; mi++) {
                    const int r0 = qb * 128 + wrow + mi * 16 + g;
                    const int r1 = r0 + 8;
                    for (int nt = 0; nt < ntlim; nt++) {
                        const int col = j * 64 + nt * 8 + 2 * c;
                        if (col     > r0) sacc[mi][nt][0] = -3.0e38f;
                        if (col + 1 > r0) sacc[mi][nt][1] = -3.0e38f;
                        if (col     > r1) sacc[mi][nt][2] = -3.0e38f;
                        if (col + 1 > r1) sacc[mi][nt][3] = -3.0e38f;
                    }
                }
            }

            __syncwarp();
#pragma unroll
            for (int mi = 0; mi < 2; mi++) {
                float rmax0 = -3.0e38f, rmax1 = -3.0e38f;
                for (int nt = 0; nt < ntlim; nt++) {
                    rmax0 = fmaxf(rmax0, fmaxf(sacc[mi][nt][0], sacc[mi][nt][1]));
                    rmax1 = fmaxf(rmax1, fmaxf(sacc[mi][nt][2], sacc[mi][nt][3]));
                }
#pragma unroll
                for (int off = 1; off < 4; off <<= 1) {
                    rmax0 = fmaxf(rmax0, __shfl_xor_sync(0xffffffffu, rmax0, off));
                    rmax1 = fmaxf(rmax1, __shfl_xor_sync(0xffffffffu, rmax1, off));
                }

                const float mn0 = fmaxf(mI[mi][0], rmax0);
                const float mn1 = fmaxf(mI[mi][1], rmax1);
                const float al0 = __expf(mI[mi][0] - mn0);
                const float al1 = __expf(mI[mi][1] - mn1);

                const int r0 = wrow + mi * 16 + g;
                float rsum0 = 0.0f, rsum1 = 0.0f;
                for (int nt = 0; nt < ntlim; nt++) {
                    const float p0 = __expf(sacc[mi][nt][0] - mn0);
                    const float p1 = __expf(sacc[mi][nt][1] - mn0);
                    const float p2 = __expf(sacc[mi][nt][2] - mn1);
                    const float p3 = __expf(sacc[mi][nt][3] - mn1);
                    rsum0 += p0 + p1;
                    rsum1 += p2 + p3;
                    *(uint2*)&Ps[r0 * PLD + nt * 8 + 2 * c] =
                        make_uint2(f2tf(p0), f2tf(p1));
                    *(uint2*)&Ps[(r0 + 8) * PLD + nt * 8 + 2 * c] =
                        make_uint2(f2tf(p2), f2tf(p3));
                }
#pragma unroll
                for (int off = 1; off < 4; off <<= 1) {
                    rsum0 += __shfl_xor_sync(0xffffffffu, rsum0, off);
                    rsum1 += __shfl_xor_sync(0xffffffffu, rsum1, off);
                }
                lI[mi][0] = lI[mi][0] * al0 + rsum0;
                lI[mi][1] = lI[mi][1] * al1 + rsum1;
                mI[mi][0] = mn0;
                mI[mi][1] = mn1;
#pragma unroll
                for (int nt = 0; nt < 8; nt++) {
                    oacc[mi][nt][0] *= al0;
                    oacc[mi][nt][1] *= al0;
                    oacc[mi][nt][2] *= al1;
                    oacc[mi][nt][3] *= al1;
                }
            }
            __syncwarp();

            for (int ks = 0; ks < ntlim; ks++) {
                uint32_t af0[4], af1[4];
                const int pr0 = wrow + g;
                af0[0] = Ps[pr0 * PLD + ks * 8 + c];
                af0[1] = Ps[(pr0 + 8) * PLD + ks * 8 + c];
                af0[2] = Ps[pr0 * PLD + ks * 8 + c + 4];
                af0[3] = Ps[(pr0 + 8) * PLD + ks * 8 + c + 4];
                af1[0] = Ps[(pr0 + 16) * PLD + ks * 8 + c];
                af1[1] = Ps[(pr0 + 24) * PLD + ks * 8 + c];
                af1[2] = Ps[(pr0 + 16) * PLD + ks * 8 + c + 4];
                af1[3] = Ps[(pr0 + 24) * PLD + ks * 8 + c + 4];
#pragma unroll
                for (int nt = 0; nt < 8; nt++) {
                    uint32_t bf[2];
                    bf[0] = Vb[(ks * 8 + c)     * VLD + nt * 8 + g];
                    bf[1] = Vb[(ks * 8 + c + 4) * VLD + nt * 8 + g];
                    mma_tf32(oacc[0][nt], af0, bf);
                    mma_tf32(oacc[1][nt], af1, bf);
                }
            }
        }
        buf ^= 1;
    }

    const int b = bh >> 4, h = bh & 15;
#pragma unroll
    for (int mi = 0; mi < 2; mi++) {
        const int r0 = qb * 128 + wrow + mi * 16 + g;
        const int r1 = r0 + 8;
        const float inv0 = 1.0f / lI[mi][0];
        const float inv1 = 1.0f / lI[mi][1];
#pragma unroll
        for (int nt = 0; nt < 8; nt++) {
            const int col = h * 64 + nt * 8 + 2 * c;
            *(float2*)&ctx[(size_t)(b * S_ + r0) * DIM + col] =
                make_float2(tfr(oacc[mi][nt][0] * inv0), tfr(oacc[mi][nt][1] * inv0));
            *(float2*)&ctx[(size_t)(b * S_ + r1) * DIM + col] =
                make_float2(tfr(oacc[mi][nt][2] * inv1), tfr(oacc[mi][nt][3] * inv1));
        }
    }
}

// ---------------------------------------------------------------------------
extern "C" void kernel_launch(void* const* d_in, const int* in_sizes, int n_in,
                              void* d_out, int out_size)
{
    const float* x     = (const float*)d_in[0];
    const float* theta = (const float*)d_in[2];
    const float* Wq    = (const float*)d_in[3];
    const float* bq    = (const float*)d_in[4];
    const float* Wk    = (const float*)d_in[5];
    const float* bk    = (const float*)d_in[6];
    const float* Wv    = (const float*)d_in[7];
    const float* bv    = (const float*)d_in[8];
    const float* Wo    = (const float*)d_in[9];
    const float* bo    = (const float*)d_in[10];
    float* out = (float*)d_out;

    float *Qb, *Kb, *Vb, *Cb, *Xr, *Wr;
    cudaGetSymbolAddress((void**)&Qb, g_Q);
    cudaGetSymbolAddress((void**)&Kb, g_K);
    cudaGetSymbolAddress((void**)&Vb, g_V);
    cudaGetSymbolAddress((void**)&Cb, g_C);
    cudaGetSymbolAddress((void**)&Xr, g_Xr);
    cudaGetSymbolAddress((void**)&Wr, g_Wr);

    round_tf32_kernel<<<(X4 + 4 * W4) / 256, 256>>>(x, Wq, Wk, Wv, Wo, Xr, Wr);

    gemm_tf32_kernel<1><<<dim3(3 * DIM / 128, MROWS / 128), 128>>>(
        Xr, Wr, bq, bk, bv, Qb, Kb, Vb);

    rope_kernel<<<(B_ * NH * S_ * 32) / 256, 256>>>(Qb, Kb, theta);

    const int flashSmem = FLASH_SMEM_WORDS * (int)sizeof(uint32_t);  // 106.5 KB
    cudaFuncSetAttribute(flash_tf32_kernel,
                         cudaFuncAttributeMaxDynamicSharedMemorySize, flashSmem);
    flash_tf32_kernel<<<16 * 32, 128, flashSmem>>>(Qb, Kb, Vb, Cb);

    gemm_tf32_kernel<0><<<dim3(DIM / 128, MROWS / 128), 128>>>(
        Cb, Wr + (size_t)3 * DIM * DIM, bo, bo, bo, out, out, out);
}